// round 3
// baseline (speedup 1.0000x reference)
#include <cuda_runtime.h>
#include <math.h>

#define BATCH   2
#define SEQ     1024
#define DMODEL  1024
#define DINNER  2048
#define DTRANK  64
#define DSTATE  16
#define DCONV   4
#define ROWS    (BATCH*SEQ)            // 2048
#define XPROJ_OUT (DTRANK + 2*DSTATE)  // 96

typedef unsigned long long ull;

__device__ __forceinline__ void ffma2(ull &d, ull a, ull b) {
    asm("fma.rn.f32x2 %0, %1, %2, %0;" : "+l"(d) : "l"(a), "l"(b));
}
__device__ __forceinline__ ull pack_dup(float x) {
    ull r; asm("mov.b64 %0, {%1, %1};" : "=l"(r) : "f"(x)); return r;
}
__device__ __forceinline__ float2 unpack2(ull v) {
    float2 f; asm("mov.b64 {%0, %1}, %2;" : "=f"(f.x), "=f"(f.y) : "l"(v)); return f;
}

// ---------------- scratch (static device globals; no allocation) ------------
#define XP_KSPLIT 4
__device__ float g_xn   [ROWS*DMODEL];
__device__ float g_xz   [ROWS*2*DINNER];
__device__ float g_u    [ROWS*DINNER];
__device__ float g_xdbl [ROWS*XPROJ_OUT];
__device__ float g_xpart[XP_KSPLIT*ROWS*XPROJ_OUT];
__device__ float g_delta[ROWS*DINNER];
__device__ float g_yg   [ROWS*DINNER];

// ---------------- LayerNorm: one block per row ------------------------------
__global__ void ln_kernel(const float* __restrict__ x, const float* __restrict__ g,
                          const float* __restrict__ b, float* __restrict__ out)
{
    int row = blockIdx.x;
    int tid = threadIdx.x;
    const float* xr = x + (size_t)row*DMODEL;
    float v[4];
    float s1 = 0.f, s2 = 0.f;
    #pragma unroll
    for (int i = 0; i < 4; i++) {
        v[i] = xr[tid + 256*i];
        s1 += v[i];
        s2 += v[i]*v[i];
    }
    __shared__ float sh1[8], sh2[8];
    #pragma unroll
    for (int o = 16; o; o >>= 1) {
        s1 += __shfl_xor_sync(0xffffffffu, s1, o);
        s2 += __shfl_xor_sync(0xffffffffu, s2, o);
    }
    if ((tid & 31) == 0) { sh1[tid>>5] = s1; sh2[tid>>5] = s2; }
    __syncthreads();
    if (tid < 32) {
        float a = (tid < 8) ? sh1[tid] : 0.f;
        float c = (tid < 8) ? sh2[tid] : 0.f;
        #pragma unroll
        for (int o = 4; o; o >>= 1) {
            a += __shfl_xor_sync(0xffffffffu, a, o);
            c += __shfl_xor_sync(0xffffffffu, c, o);
        }
        if (tid == 0) { sh1[0] = a; sh2[0] = c; }
    }
    __syncthreads();
    float mu  = sh1[0] * (1.f/DMODEL);
    float var = sh2[0] * (1.f/DMODEL) - mu*mu;
    float r   = rsqrtf(var + 1e-5f);
    float* o = out + (size_t)row*DMODEL;
    #pragma unroll
    for (int i = 0; i < 4; i++) {
        int c = tid + 256*i;
        o[c] = (v[i]-mu)*r*g[c] + b[c];
    }
}

// ---------------- SGEMM NT with f32x2 packed FMA ----------------------------
// C[M,N] = A[M,K] * B[N,K]^T, epilogue modes:
//   0: plain store, 1: += R (residual), 2: softplus(v + bias[n])
#define BM 128
#define BN 128
#define BKT 8

__global__ __launch_bounds__(256) void sgemm_nt(
    const float* __restrict__ A, int lda,
    const float* __restrict__ B, int ldb,
    float* __restrict__ C, int ldc,
    const float* __restrict__ R, int ldr,
    const float* __restrict__ bias,
    int M, int N, int K, int mode)
{
    __shared__ float As[BKT][BM+4];
    __shared__ float Bs[BKT][BN+4];

    int tid = threadIdx.x;
    int tx  = tid & 15;   // 0..15
    int ty  = tid >> 4;   // 0..15
    int m0  = blockIdx.y * BM;
    int n0  = blockIdx.x * BN;

    int lrow = tid >> 1;         // 0..127
    int lk4  = (tid & 1) * 4;    // 0 / 4

    ull acc2[8][4];
    #pragma unroll
    for (int i = 0; i < 8; i++)
        #pragma unroll
        for (int j = 0; j < 4; j++) acc2[i][j] = 0ull;

    for (int k0 = 0; k0 < K; k0 += BKT) {
        float4 a = make_float4(0.f,0.f,0.f,0.f);
        int am = m0 + lrow;
        if (am < M) a = *reinterpret_cast<const float4*>(A + (size_t)am*lda + k0 + lk4);
        As[lk4+0][lrow] = a.x; As[lk4+1][lrow] = a.y;
        As[lk4+2][lrow] = a.z; As[lk4+3][lrow] = a.w;

        float4 bv = make_float4(0.f,0.f,0.f,0.f);
        int bn = n0 + lrow;
        if (bn < N) bv = *reinterpret_cast<const float4*>(B + (size_t)bn*ldb + k0 + lk4);
        Bs[lk4+0][lrow] = bv.x; Bs[lk4+1][lrow] = bv.y;
        Bs[lk4+2][lrow] = bv.z; Bs[lk4+3][lrow] = bv.w;

        __syncthreads();

        #pragma unroll
        for (int kk = 0; kk < BKT; kk++) {
            float4 a0 = *reinterpret_cast<const float4*>(&As[kk][ty*4]);
            float4 a1 = *reinterpret_cast<const float4*>(&As[kk][64 + ty*4]);
            ulonglong2 b0 = *reinterpret_cast<const ulonglong2*>(&Bs[kk][tx*4]);
            ulonglong2 b1 = *reinterpret_cast<const ulonglong2*>(&Bs[kk][64 + tx*4]);
            ull ra2[8];
            ra2[0] = pack_dup(a0.x); ra2[1] = pack_dup(a0.y);
            ra2[2] = pack_dup(a0.z); ra2[3] = pack_dup(a0.w);
            ra2[4] = pack_dup(a1.x); ra2[5] = pack_dup(a1.y);
            ra2[6] = pack_dup(a1.z); ra2[7] = pack_dup(a1.w);
            ull rb2[4] = {b0.x, b0.y, b1.x, b1.y};
            #pragma unroll
            for (int i = 0; i < 8; i++)
                #pragma unroll
                for (int j = 0; j < 4; j++)
                    ffma2(acc2[i][j], ra2[i], rb2[j]);
        }
        __syncthreads();
    }

    #pragma unroll
    for (int i = 0; i < 8; i++) {
        int m = m0 + ((i < 4) ? (ty*4 + i) : (64 + ty*4 + i - 4));
        if (m >= M) continue;
        #pragma unroll
        for (int j = 0; j < 4; j++) {
            int n = n0 + ((j < 2) ? (tx*4 + j*2) : (64 + tx*4 + (j-2)*2));
            if (n + 1 < N) {
                float2 v = unpack2(acc2[i][j]);
                if (mode == 1) {
                    v.x += R[(size_t)m*ldr + n];
                    v.y += R[(size_t)m*ldr + n + 1];
                } else if (mode == 2) {
                    float vx = v.x + bias[n];
                    float vy = v.y + bias[n+1];
                    v.x = (vx > 20.f) ? vx : log1pf(expf(vx));
                    v.y = (vy > 20.f) ? vy : log1pf(expf(vy));
                }
                *reinterpret_cast<float2*>(C + (size_t)m*ldc + n) = v;
            }
        }
    }
}

// ---------------- x_proj tall-skinny GEMM, split-K --------------------------
// part[kc][2048,96] = u[:, kc*512:(kc+1)*512] @ w[:, kc*512:(kc+1)*512]^T
#define XP_BM 16
#define XP_BK 32
#define XP_BSROW 98   // padded Bs row: 8B-aligned, 2-way max conflict

__global__ __launch_bounds__(256) void xproj_kernel(
    const float* __restrict__ u, const float* __restrict__ w, float* __restrict__ part)
{
    __shared__ float As[XP_BK][XP_BM+1];
    __shared__ float Bs[XP_BK][XP_BSROW];

    int tid  = threadIdx.x;
    int m0   = blockIdx.x * XP_BM;
    int kc   = blockIdx.y;
    int kbeg = kc * (DINNER/XP_KSPLIT);
    int kend = kbeg + (DINNER/XP_KSPLIT);
    int r    = tid >> 4;   // 0..15 row
    int cg   = tid & 15;   // col group: cols cg*6 .. cg*6+5

    ull acc[2][3];
    #pragma unroll
    for (int p = 0; p < 2; p++)
        #pragma unroll
        for (int j = 0; j < 3; j++) acc[p][j] = 0ull;

    for (int k0 = kbeg; k0 < kend; k0 += XP_BK) {
        #pragma unroll
        for (int e = tid; e < XP_BM*XP_BK; e += 256) {
            int k = e & 31, m = e >> 5;
            As[k][m] = u[(size_t)(m0+m)*DINNER + k0 + k];
        }
        #pragma unroll
        for (int e = tid; e < XPROJ_OUT*XP_BK; e += 256) {
            int k = e & 31, n = e >> 5;
            Bs[k][n] = w[(size_t)n*DINNER + k0 + k];
        }
        __syncthreads();
        #pragma unroll
        for (int kk = 0; kk < XP_BK; kk += 2) {
            ull a0 = pack_dup(As[kk  ][r]);
            ull a1 = pack_dup(As[kk+1][r]);
            const ull* b0 = reinterpret_cast<const ull*>(&Bs[kk  ][cg*6]);
            const ull* b1 = reinterpret_cast<const ull*>(&Bs[kk+1][cg*6]);
            ffma2(acc[0][0], a0, b0[0]);
            ffma2(acc[0][1], a0, b0[1]);
            ffma2(acc[0][2], a0, b0[2]);
            ffma2(acc[1][0], a1, b1[0]);
            ffma2(acc[1][1], a1, b1[1]);
            ffma2(acc[1][2], a1, b1[2]);
        }
        __syncthreads();
    }

    float* o = part + (size_t)kc*ROWS*XPROJ_OUT + (size_t)(m0 + r)*XPROJ_OUT + cg*6;
    #pragma unroll
    for (int j = 0; j < 3; j++) {
        float2 v0 = unpack2(acc[0][j]);
        float2 v1 = unpack2(acc[1][j]);
        v0.x += v1.x; v0.y += v1.y;
        *reinterpret_cast<float2*>(o + 2*j) = v0;
    }
}

__global__ void xpart_reduce(const float* __restrict__ part, float* __restrict__ xdbl)
{
    int i = blockIdx.x*blockDim.x + threadIdx.x;
    if (i >= ROWS*XPROJ_OUT) return;
    const int S = ROWS*XPROJ_OUT;
    xdbl[i] = (part[i] + part[i+S]) + (part[i+2*S] + part[i+3*S]);
}

// ---------------- causal depthwise conv1d + SiLU ----------------------------
__global__ void conv_silu_kernel(const float* __restrict__ xz, const float* __restrict__ w,
                                 const float* __restrict__ bias, float* __restrict__ u)
{
    int i = blockIdx.x*blockDim.x + threadIdx.x;
    if (i >= ROWS*DINNER) return;
    int d    = i % DINNER;
    int row  = i / DINNER;       // b*SEQ + l
    int l    = row % SEQ;
    float acc = bias[d];
    #pragma unroll
    for (int t = 0; t < DCONV; t++) {
        int li = l + t - (DCONV-1);
        if (li >= 0)
            acc += xz[((size_t)(row + li - l))*(2*DINNER) + d] * w[d*DCONV + t];
    }
    float sig = 1.f / (1.f + expf(-acc));
    u[i] = acc * sig;
}

// ---------------- selective scan: 1 lane per (channel,state), gate fused ----
__global__ __launch_bounds__(256) void scan_kernel(
    const float* __restrict__ delta, const float* __restrict__ u,
    const float* __restrict__ xdbl, const float* __restrict__ xz,
    const float* __restrict__ A_log, const float* __restrict__ Dskip,
    float* __restrict__ yg)
{
    int warp = threadIdx.x >> 5;
    int lane = threadIdx.x & 31;
    int half = lane >> 4;
    int n    = lane & 15;
    int c    = blockIdx.x*16 + warp*2 + half;   // 0..4095
    int b    = c / DINNER;
    int d    = c % DINNER;

    float A  = -expf(A_log[d*DSTATE + n]);
    float Dd = Dskip[d];
    float h  = 0.f;

    const float* drow = delta + (size_t)b*SEQ*DINNER + d;
    const float* urow = u     + (size_t)b*SEQ*DINNER + d;
    const float* xrow = xdbl  + (size_t)b*SEQ*XPROJ_OUT;
    const float* zrow = xz    + (size_t)b*SEQ*(2*DINNER) + DINNER + d;
    float*       yrow = yg    + (size_t)b*SEQ*DINNER + d;

    for (int t = 0; t < SEQ; t++) {
        float dt = drow[(size_t)t*DINNER];
        float ut = urow[(size_t)t*DINNER];
        float Bn = xrow[t*XPROJ_OUT + DTRANK + n];
        float Cn = xrow[t*XPROJ_OUT + DTRANK + DSTATE + n];
        float dA = expf(dt * A);
        h = fmaf(dA, h, dt*ut*Bn);
        float p = h * Cn;
        p += __shfl_xor_sync(0xffffffffu, p, 8);
        p += __shfl_xor_sync(0xffffffffu, p, 4);
        p += __shfl_xor_sync(0xffffffffu, p, 2);
        p += __shfl_xor_sync(0xffffffffu, p, 1);
        if (n == 0) {
            float z = zrow[(size_t)t*(2*DINNER)];
            float s = z / (1.f + expf(-z));
            yrow[(size_t)t*DINNER] = fmaf(ut, Dd, p) * s;
        }
    }
}

// ---------------- launch ----------------------------------------------------
extern "C" void kernel_launch(void* const* d_in, const int* in_sizes, int n_in,
                              void* d_out, int out_size)
{
    const float* x      = (const float*)d_in[0];
    const float* ln_g   = (const float*)d_in[1];
    const float* ln_b   = (const float*)d_in[2];
    const float* w_in   = (const float*)d_in[3];
    const float* conv_w = (const float*)d_in[4];
    const float* conv_b = (const float*)d_in[5];
    const float* w_x    = (const float*)d_in[6];
    const float* w_dt   = (const float*)d_in[7];
    const float* b_dt   = (const float*)d_in[8];
    const float* A_log  = (const float*)d_in[9];
    const float* Dsk    = (const float*)d_in[10];
    const float* w_out  = (const float*)d_in[11];
    float* out = (float*)d_out;

    float *xn, *xz, *u, *xdbl, *xpart, *delta, *yg;
    cudaGetSymbolAddress((void**)&xn,    g_xn);
    cudaGetSymbolAddress((void**)&xz,    g_xz);
    cudaGetSymbolAddress((void**)&u,     g_u);
    cudaGetSymbolAddress((void**)&xdbl,  g_xdbl);
    cudaGetSymbolAddress((void**)&xpart, g_xpart);
    cudaGetSymbolAddress((void**)&delta, g_delta);
    cudaGetSymbolAddress((void**)&yg,    g_yg);

    int nelem = ROWS*DINNER;

    // 1. layernorm
    ln_kernel<<<ROWS, 256>>>(x, ln_g, ln_b, xn);

    // 2. in_proj: xz[2048,4096] = xn[2048,1024] @ w_in[4096,1024]^T
    {
        dim3 g(2*DINNER/BN, ROWS/BM);
        sgemm_nt<<<g, 256>>>(xn, DMODEL, w_in, DMODEL, xz, 2*DINNER,
                             nullptr, 0, nullptr, ROWS, 2*DINNER, DMODEL, 0);
    }

    // 3. causal depthwise conv + SiLU -> u
    conv_silu_kernel<<<(nelem+255)/256, 256>>>(xz, conv_w, conv_b, u);

    // 4. x_proj (split-K): xdbl[2048,96] = u @ w_x[96,2048]^T
    {
        dim3 g(ROWS/XP_BM, XP_KSPLIT);
        xproj_kernel<<<g, 256>>>(u, w_x, xpart);
        xpart_reduce<<<(ROWS*XPROJ_OUT+255)/256, 256>>>(xpart, xdbl);
    }

    // 5. dt_proj + fused softplus: delta = softplus(xdbl[:, :64] @ w_dt^T + b_dt)
    {
        dim3 g(DINNER/BN, ROWS/BM);
        sgemm_nt<<<g, 256>>>(xdbl, XPROJ_OUT, w_dt, DTRANK, delta, DINNER,
                             nullptr, 0, b_dt, ROWS, DINNER, DTRANK, 2);
    }

    // 6. selective scan (+ u*D_skip, fused gate with silu(z))
    scan_kernel<<<(BATCH*DINNER)/16, 256>>>(delta, u, xdbl, xz, A_log, Dsk, yg);

    // 7. out_proj + residual
    {
        dim3 g(DMODEL/BN, ROWS/BM);
        sgemm_nt<<<g, 256>>>(yg, DINNER, w_out, DINNER, out, DMODEL,
                             x, DMODEL, nullptr, ROWS, DMODEL, DINNER, 1);
    }
}

// round 4
// speedup vs baseline: 1.3739x; 1.3739x over previous
#include <cuda_runtime.h>
#include <math.h>

#define BATCH   2
#define SEQ     1024
#define DMODEL  1024
#define DINNER  2048
#define DTRANK  64
#define DSTATE  16
#define DCONV   4
#define ROWS    (BATCH*SEQ)            // 2048
#define XPROJ_OUT (DTRANK + 2*DSTATE)  // 96

typedef unsigned long long ull;

__device__ __forceinline__ void ffma2(ull &d, ull a, ull b) {
    asm("fma.rn.f32x2 %0, %1, %2, %0;" : "+l"(d) : "l"(a), "l"(b));
}
__device__ __forceinline__ ull pack_dup(float x) {
    ull r; asm("mov.b64 %0, {%1, %1};" : "=l"(r) : "f"(x)); return r;
}
__device__ __forceinline__ float2 unpack2(ull v) {
    float2 f; asm("mov.b64 {%0, %1}, %2;" : "=f"(f.x), "=f"(f.y) : "l"(v)); return f;
}

// ---------------- scratch (static device globals; no allocation) ------------
#define XP_KSPLIT 4
__device__ float g_xn   [ROWS*DMODEL];
__device__ float g_xz   [ROWS*2*DINNER];
__device__ float g_u    [ROWS*DINNER];
__device__ float g_xdbl [ROWS*XPROJ_OUT];
__device__ float g_xpart[XP_KSPLIT*ROWS*XPROJ_OUT];
__device__ float g_delta[ROWS*DINNER];
__device__ float g_yg   [ROWS*DINNER];

// ---------------- LayerNorm: one block per row ------------------------------
__global__ void ln_kernel(const float* __restrict__ x, const float* __restrict__ g,
                          const float* __restrict__ b, float* __restrict__ out)
{
    int row = blockIdx.x;
    int tid = threadIdx.x;
    const float* xr = x + (size_t)row*DMODEL;
    float v[4];
    float s1 = 0.f, s2 = 0.f;
    #pragma unroll
    for (int i = 0; i < 4; i++) {
        v[i] = xr[tid + 256*i];
        s1 += v[i];
        s2 += v[i]*v[i];
    }
    __shared__ float sh1[8], sh2[8];
    #pragma unroll
    for (int o = 16; o; o >>= 1) {
        s1 += __shfl_xor_sync(0xffffffffu, s1, o);
        s2 += __shfl_xor_sync(0xffffffffu, s2, o);
    }
    if ((tid & 31) == 0) { sh1[tid>>5] = s1; sh2[tid>>5] = s2; }
    __syncthreads();
    if (tid < 32) {
        float a = (tid < 8) ? sh1[tid] : 0.f;
        float c = (tid < 8) ? sh2[tid] : 0.f;
        #pragma unroll
        for (int o = 4; o; o >>= 1) {
            a += __shfl_xor_sync(0xffffffffu, a, o);
            c += __shfl_xor_sync(0xffffffffu, c, o);
        }
        if (tid == 0) { sh1[0] = a; sh2[0] = c; }
    }
    __syncthreads();
    float mu  = sh1[0] * (1.f/DMODEL);
    float var = sh2[0] * (1.f/DMODEL) - mu*mu;
    float r   = rsqrtf(var + 1e-5f);
    float* o = out + (size_t)row*DMODEL;
    #pragma unroll
    for (int i = 0; i < 4; i++) {
        int c = tid + 256*i;
        o[c] = (v[i]-mu)*r*g[c] + b[c];
    }
}

// ---------------- SGEMM NT (scalar FFMA, proven) ----------------------------
// C[M,N] = A[M,K] * B[N,K]^T, epilogue modes:
//   0: plain store, 1: += R (residual), 2: softplus(v + bias[n])
#define BM 128
#define BN 128
#define BKT 8

__global__ __launch_bounds__(256) void sgemm_nt(
    const float* __restrict__ A, int lda,
    const float* __restrict__ B, int ldb,
    float* __restrict__ C, int ldc,
    const float* __restrict__ R, int ldr,
    const float* __restrict__ bias,
    int M, int N, int K, int mode)
{
    __shared__ float As[BKT][BM+4];
    __shared__ float Bs[BKT][BN+4];

    int tid = threadIdx.x;
    int tx  = tid & 15;   // 0..15
    int ty  = tid >> 4;   // 0..15
    int m0  = blockIdx.y * BM;
    int n0  = blockIdx.x * BN;

    int lrow = tid >> 1;         // 0..127
    int lk4  = (tid & 1) * 4;    // 0 / 4

    float acc[8][8];
    #pragma unroll
    for (int i = 0; i < 8; i++)
        #pragma unroll
        for (int j = 0; j < 8; j++) acc[i][j] = 0.f;

    for (int k0 = 0; k0 < K; k0 += BKT) {
        float4 a = make_float4(0.f,0.f,0.f,0.f);
        int am = m0 + lrow;
        if (am < M) a = *reinterpret_cast<const float4*>(A + (size_t)am*lda + k0 + lk4);
        As[lk4+0][lrow] = a.x; As[lk4+1][lrow] = a.y;
        As[lk4+2][lrow] = a.z; As[lk4+3][lrow] = a.w;

        float4 bv = make_float4(0.f,0.f,0.f,0.f);
        int bn = n0 + lrow;
        if (bn < N) bv = *reinterpret_cast<const float4*>(B + (size_t)bn*ldb + k0 + lk4);
        Bs[lk4+0][lrow] = bv.x; Bs[lk4+1][lrow] = bv.y;
        Bs[lk4+2][lrow] = bv.z; Bs[lk4+3][lrow] = bv.w;

        __syncthreads();

        #pragma unroll
        for (int kk = 0; kk < BKT; kk++) {
            float ra[8], rb[8];
            #pragma unroll
            for (int i = 0; i < 4; i++) {
                ra[i]   = As[kk][ty*4 + i];
                ra[i+4] = As[kk][64 + ty*4 + i];
                rb[i]   = Bs[kk][tx*4 + i];
                rb[i+4] = Bs[kk][64 + tx*4 + i];
            }
            #pragma unroll
            for (int i = 0; i < 8; i++)
                #pragma unroll
                for (int j = 0; j < 8; j++)
                    acc[i][j] = fmaf(ra[i], rb[j], acc[i][j]);
        }
        __syncthreads();
    }

    #pragma unroll
    for (int i = 0; i < 8; i++) {
        int m = m0 + ((i < 4) ? (ty*4 + i) : (64 + ty*4 + i - 4));
        if (m >= M) continue;
        #pragma unroll
        for (int j = 0; j < 8; j++) {
            int n = n0 + ((j < 4) ? (tx*4 + j) : (64 + tx*4 + j - 4));
            if (n < N) {
                float val = acc[i][j];
                if (mode == 1) {
                    val += R[(size_t)m*ldr + n];
                } else if (mode == 2) {
                    float v = val + bias[n];
                    val = (v > 20.f) ? v : log1pf(expf(v));
                }
                C[(size_t)m*ldc + n] = val;
            }
        }
    }
}

// ---------------- x_proj tall-skinny GEMM, split-K (measured good) ----------
#define XP_BM 16
#define XP_BK 32
#define XP_BSROW 98

__global__ __launch_bounds__(256) void xproj_kernel(
    const float* __restrict__ u, const float* __restrict__ w, float* __restrict__ part)
{
    __shared__ float As[XP_BK][XP_BM+1];
    __shared__ float Bs[XP_BK][XP_BSROW];

    int tid  = threadIdx.x;
    int m0   = blockIdx.x * XP_BM;
    int kc   = blockIdx.y;
    int kbeg = kc * (DINNER/XP_KSPLIT);
    int kend = kbeg + (DINNER/XP_KSPLIT);
    int r    = tid >> 4;   // 0..15 row
    int cg   = tid & 15;   // col group: cols cg*6 .. cg*6+5

    ull acc[2][3];
    #pragma unroll
    for (int p = 0; p < 2; p++)
        #pragma unroll
        for (int j = 0; j < 3; j++) acc[p][j] = 0ull;

    for (int k0 = kbeg; k0 < kend; k0 += XP_BK) {
        #pragma unroll
        for (int e = tid; e < XP_BM*XP_BK; e += 256) {
            int k = e & 31, m = e >> 5;
            As[k][m] = u[(size_t)(m0+m)*DINNER + k0 + k];
        }
        #pragma unroll
        for (int e = tid; e < XPROJ_OUT*XP_BK; e += 256) {
            int k = e & 31, n = e >> 5;
            Bs[k][n] = w[(size_t)n*DINNER + k0 + k];
        }
        __syncthreads();
        #pragma unroll
        for (int kk = 0; kk < XP_BK; kk += 2) {
            ull a0 = pack_dup(As[kk  ][r]);
            ull a1 = pack_dup(As[kk+1][r]);
            const ull* b0 = reinterpret_cast<const ull*>(&Bs[kk  ][cg*6]);
            const ull* b1 = reinterpret_cast<const ull*>(&Bs[kk+1][cg*6]);
            ffma2(acc[0][0], a0, b0[0]);
            ffma2(acc[0][1], a0, b0[1]);
            ffma2(acc[0][2], a0, b0[2]);
            ffma2(acc[1][0], a1, b1[0]);
            ffma2(acc[1][1], a1, b1[1]);
            ffma2(acc[1][2], a1, b1[2]);
        }
        __syncthreads();
    }

    float* o = part + (size_t)kc*ROWS*XPROJ_OUT + (size_t)(m0 + r)*XPROJ_OUT + cg*6;
    #pragma unroll
    for (int j = 0; j < 3; j++) {
        float2 v0 = unpack2(acc[0][j]);
        float2 v1 = unpack2(acc[1][j]);
        v0.x += v1.x; v0.y += v1.y;
        *reinterpret_cast<float2*>(o + 2*j) = v0;
    }
}

__global__ void xpart_reduce(const float* __restrict__ part, float* __restrict__ xdbl)
{
    int i = blockIdx.x*blockDim.x + threadIdx.x;
    if (i >= ROWS*XPROJ_OUT) return;
    const int S = ROWS*XPROJ_OUT;
    xdbl[i] = (part[i] + part[i+S]) + (part[i+2*S] + part[i+3*S]);
}

// ---------------- causal depthwise conv1d + SiLU ----------------------------
__global__ void conv_silu_kernel(const float* __restrict__ xz, const float* __restrict__ w,
                                 const float* __restrict__ bias, float* __restrict__ u)
{
    int i = blockIdx.x*blockDim.x + threadIdx.x;
    if (i >= ROWS*DINNER) return;
    int d    = i % DINNER;
    int row  = i / DINNER;       // b*SEQ + l
    int l    = row % SEQ;
    float acc = bias[d];
    #pragma unroll
    for (int t = 0; t < DCONV; t++) {
        int li = l + t - (DCONV-1);
        if (li >= 0)
            acc += xz[((size_t)(row + li - l))*(2*DINNER) + d] * w[d*DCONV + t];
    }
    float sig = 1.f / (1.f + expf(-acc));
    u[i] = acc * sig;
}

// ---------------- selective scan: 1 lane per (channel,state), gate fused ----
__global__ __launch_bounds__(256) void scan_kernel(
    const float* __restrict__ delta, const float* __restrict__ u,
    const float* __restrict__ xdbl, const float* __restrict__ xz,
    const float* __restrict__ A_log, const float* __restrict__ Dskip,
    float* __restrict__ yg)
{
    int warp = threadIdx.x >> 5;
    int lane = threadIdx.x & 31;
    int half = lane >> 4;
    int n    = lane & 15;
    int c    = blockIdx.x*16 + warp*2 + half;   // 0..4095
    int b    = c / DINNER;
    int d    = c % DINNER;

    float A  = -expf(A_log[d*DSTATE + n]);
    float Dd = Dskip[d];
    float h  = 0.f;

    const float* drow = delta + (size_t)b*SEQ*DINNER + d;
    const float* urow = u     + (size_t)b*SEQ*DINNER + d;
    const float* xrow = xdbl  + (size_t)b*SEQ*XPROJ_OUT;
    const float* zrow = xz    + (size_t)b*SEQ*(2*DINNER) + DINNER + d;
    float*       yrow = yg    + (size_t)b*SEQ*DINNER + d;

    for (int t = 0; t < SEQ; t++) {
        float dt = drow[(size_t)t*DINNER];
        float ut = urow[(size_t)t*DINNER];
        float Bn = xrow[t*XPROJ_OUT + DTRANK + n];
        float Cn = xrow[t*XPROJ_OUT + DTRANK + DSTATE + n];
        float dA = expf(dt * A);
        h = fmaf(dA, h, dt*ut*Bn);
        float p = h * Cn;
        p += __shfl_xor_sync(0xffffffffu, p, 8);
        p += __shfl_xor_sync(0xffffffffu, p, 4);
        p += __shfl_xor_sync(0xffffffffu, p, 2);
        p += __shfl_xor_sync(0xffffffffu, p, 1);
        if (n == 0) {
            float z = zrow[(size_t)t*(2*DINNER)];
            float s = z / (1.f + expf(-z));
            yrow[(size_t)t*DINNER] = fmaf(ut, Dd, p) * s;
        }
    }
}

// ---------------- launch ----------------------------------------------------
extern "C" void kernel_launch(void* const* d_in, const int* in_sizes, int n_in,
                              void* d_out, int out_size)
{
    const float* x      = (const float*)d_in[0];
    const float* ln_g   = (const float*)d_in[1];
    const float* ln_b   = (const float*)d_in[2];
    const float* w_in   = (const float*)d_in[3];
    const float* conv_w = (const float*)d_in[4];
    const float* conv_b = (const float*)d_in[5];
    const float* w_x    = (const float*)d_in[6];
    const float* w_dt   = (const float*)d_in[7];
    const float* b_dt   = (const float*)d_in[8];
    const float* A_log  = (const float*)d_in[9];
    const float* Dsk    = (const float*)d_in[10];
    const float* w_out  = (const float*)d_in[11];
    float* out = (float*)d_out;

    float *xn, *xz, *u, *xdbl, *xpart, *delta, *yg;
    cudaGetSymbolAddress((void**)&xn,    g_xn);
    cudaGetSymbolAddress((void**)&xz,    g_xz);
    cudaGetSymbolAddress((void**)&u,     g_u);
    cudaGetSymbolAddress((void**)&xdbl,  g_xdbl);
    cudaGetSymbolAddress((void**)&xpart, g_xpart);
    cudaGetSymbolAddress((void**)&delta, g_delta);
    cudaGetSymbolAddress((void**)&yg,    g_yg);

    int nelem = ROWS*DINNER;

    // 1. layernorm
    ln_kernel<<<ROWS, 256>>>(x, ln_g, ln_b, xn);

    // 2. in_proj: xz[2048,4096] = xn[2048,1024] @ w_in[4096,1024]^T
    {
        dim3 g(2*DINNER/BN, ROWS/BM);
        sgemm_nt<<<g, 256>>>(xn, DMODEL, w_in, DMODEL, xz, 2*DINNER,
                             nullptr, 0, nullptr, ROWS, 2*DINNER, DMODEL, 0);
    }

    // 3. causal depthwise conv + SiLU -> u
    conv_silu_kernel<<<(nelem+255)/256, 256>>>(xz, conv_w, conv_b, u);

    // 4. x_proj (split-K): xdbl[2048,96] = u @ w_x[96,2048]^T
    {
        dim3 g(ROWS/XP_BM, XP_KSPLIT);
        xproj_kernel<<<g, 256>>>(u, w_x, xpart);
        xpart_reduce<<<(ROWS*XPROJ_OUT+255)/256, 256>>>(xpart, xdbl);
    }

    // 5. dt_proj + fused softplus: delta = softplus(xdbl[:, :64] @ w_dt^T + b_dt)
    {
        dim3 g(DINNER/BN, ROWS/BM);
        sgemm_nt<<<g, 256>>>(xdbl, XPROJ_OUT, w_dt, DTRANK, delta, DINNER,
                             nullptr, 0, b_dt, ROWS, DINNER, DTRANK, 2);
    }

    // 6. selective scan (+ u*D_skip, fused gate with silu(z))
    scan_kernel<<<(BATCH*DINNER)/16, 256>>>(delta, u, xdbl, xz, A_log, Dsk, yg);

    // 7. out_proj + residual
    {
        dim3 g(DMODEL/BN, ROWS/BM);
        sgemm_nt<<<g, 256>>>(yg, DINNER, w_out, DINNER, out, DMODEL,
                             x, DMODEL, nullptr, ROWS, DMODEL, DINNER, 1);
    }
}

// round 5
// speedup vs baseline: 1.7834x; 1.2980x over previous
#include <cuda_runtime.h>
#include <math.h>

#define BATCH   2
#define SEQ     1024
#define DMODEL  1024
#define DINNER  2048
#define DTRANK  64
#define DSTATE  16
#define DCONV   4
#define ROWS    (BATCH*SEQ)            // 2048
#define XPROJ_OUT (DTRANK + 2*DSTATE)  // 96

typedef unsigned long long ull;

__device__ __forceinline__ void ffma2(ull &d, ull a, ull b) {
    asm("fma.rn.f32x2 %0, %1, %2, %0;" : "+l"(d) : "l"(a), "l"(b));
}
__device__ __forceinline__ ull pack_dup(float x) {
    ull r; asm("mov.b64 %0, {%1, %1};" : "=l"(r) : "f"(x)); return r;
}
__device__ __forceinline__ float2 unpack2(ull v) {
    float2 f; asm("mov.b64 {%0, %1}, %2;" : "=f"(f.x), "=f"(f.y) : "l"(v)); return f;
}

// ---------------- scratch (static device globals; no allocation) ------------
#define XP_KSPLIT 4
__device__ float g_xn    [ROWS*DMODEL];
__device__ float g_xz    [ROWS*2*DINNER];
__device__ float g_u     [ROWS*DINNER];
__device__ float g_uT    [DINNER*ROWS];
__device__ float g_xdbl  [ROWS*XPROJ_OUT];
__device__ float g_xpart [XP_KSPLIT*ROWS*XPROJ_OUT];
__device__ float g_deltaT[DINNER*ROWS];
__device__ float g_yg    [ROWS*DINNER];

// ---------------- LayerNorm: one block per row ------------------------------
__global__ void ln_kernel(const float* __restrict__ x, const float* __restrict__ g,
                          const float* __restrict__ b, float* __restrict__ out)
{
    int row = blockIdx.x;
    int tid = threadIdx.x;
    const float* xr = x + (size_t)row*DMODEL;
    float v[4];
    float s1 = 0.f, s2 = 0.f;
    #pragma unroll
    for (int i = 0; i < 4; i++) {
        v[i] = xr[tid + 256*i];
        s1 += v[i];
        s2 += v[i]*v[i];
    }
    __shared__ float sh1[8], sh2[8];
    #pragma unroll
    for (int o = 16; o; o >>= 1) {
        s1 += __shfl_xor_sync(0xffffffffu, s1, o);
        s2 += __shfl_xor_sync(0xffffffffu, s2, o);
    }
    if ((tid & 31) == 0) { sh1[tid>>5] = s1; sh2[tid>>5] = s2; }
    __syncthreads();
    if (tid < 32) {
        float a = (tid < 8) ? sh1[tid] : 0.f;
        float c = (tid < 8) ? sh2[tid] : 0.f;
        #pragma unroll
        for (int o = 4; o; o >>= 1) {
            a += __shfl_xor_sync(0xffffffffu, a, o);
            c += __shfl_xor_sync(0xffffffffu, c, o);
        }
        if (tid == 0) { sh1[0] = a; sh2[0] = c; }
    }
    __syncthreads();
    float mu  = sh1[0] * (1.f/DMODEL);
    float var = sh2[0] * (1.f/DMODEL) - mu*mu;
    float r   = rsqrtf(var + 1e-5f);
    float* o = out + (size_t)row*DMODEL;
    #pragma unroll
    for (int i = 0; i < 4; i++) {
        int c = tid + 256*i;
        o[c] = (v[i]-mu)*r*g[c] + b[c];
    }
}

// ---------------- SGEMM NT (scalar FFMA) ------------------------------------
// C[M,N] = A[M,K] * B[N,K]^T, epilogue modes:
//   0: plain store, 1: += R (residual), 3: softplus(v + bias[m])
#define BM 128
#define BN 128
#define BKT 8

__global__ __launch_bounds__(256) void sgemm_nt(
    const float* __restrict__ A, int lda,
    const float* __restrict__ B, int ldb,
    float* __restrict__ C, int ldc,
    const float* __restrict__ R, int ldr,
    const float* __restrict__ bias,
    int M, int N, int K, int mode)
{
    __shared__ float As[BKT][BM+4];
    __shared__ float Bs[BKT][BN+4];

    int tid = threadIdx.x;
    int tx  = tid & 15;   // 0..15
    int ty  = tid >> 4;   // 0..15
    int m0  = blockIdx.y * BM;
    int n0  = blockIdx.x * BN;

    int lrow = tid >> 1;         // 0..127
    int lk4  = (tid & 1) * 4;    // 0 / 4

    float acc[8][8];
    #pragma unroll
    for (int i = 0; i < 8; i++)
        #pragma unroll
        for (int j = 0; j < 8; j++) acc[i][j] = 0.f;

    for (int k0 = 0; k0 < K; k0 += BKT) {
        float4 a = make_float4(0.f,0.f,0.f,0.f);
        int am = m0 + lrow;
        if (am < M) a = *reinterpret_cast<const float4*>(A + (size_t)am*lda + k0 + lk4);
        As[lk4+0][lrow] = a.x; As[lk4+1][lrow] = a.y;
        As[lk4+2][lrow] = a.z; As[lk4+3][lrow] = a.w;

        float4 bv = make_float4(0.f,0.f,0.f,0.f);
        int bn = n0 + lrow;
        if (bn < N) bv = *reinterpret_cast<const float4*>(B + (size_t)bn*ldb + k0 + lk4);
        Bs[lk4+0][lrow] = bv.x; Bs[lk4+1][lrow] = bv.y;
        Bs[lk4+2][lrow] = bv.z; Bs[lk4+3][lrow] = bv.w;

        __syncthreads();

        #pragma unroll
        for (int kk = 0; kk < BKT; kk++) {
            float ra[8], rb[8];
            #pragma unroll
            for (int i = 0; i < 4; i++) {
                ra[i]   = As[kk][ty*4 + i];
                ra[i+4] = As[kk][64 + ty*4 + i];
                rb[i]   = Bs[kk][tx*4 + i];
                rb[i+4] = Bs[kk][64 + tx*4 + i];
            }
            #pragma unroll
            for (int i = 0; i < 8; i++)
                #pragma unroll
                for (int j = 0; j < 8; j++)
                    acc[i][j] = fmaf(ra[i], rb[j], acc[i][j]);
        }
        __syncthreads();
    }

    #pragma unroll
    for (int i = 0; i < 8; i++) {
        int m = m0 + ((i < 4) ? (ty*4 + i) : (64 + ty*4 + i - 4));
        if (m >= M) continue;
        float bm = (mode == 3) ? bias[m] : 0.f;
        #pragma unroll
        for (int j = 0; j < 8; j++) {
            int n = n0 + ((j < 4) ? (tx*4 + j) : (64 + tx*4 + j - 4));
            if (n < N) {
                float val = acc[i][j];
                if (mode == 1) {
                    val += R[(size_t)m*ldr + n];
                } else if (mode == 3) {
                    float v = val + bm;
                    val = (v > 20.f) ? v : log1pf(expf(v));
                }
                C[(size_t)m*ldc + n] = val;
            }
        }
    }
}

// ---------------- x_proj tall-skinny GEMM, split-K (measured good) ----------
#define XP_BM 16
#define XP_BK 32
#define XP_BSROW 98

__global__ __launch_bounds__(256) void xproj_kernel(
    const float* __restrict__ u, const float* __restrict__ w, float* __restrict__ part)
{
    __shared__ float As[XP_BK][XP_BM+1];
    __shared__ float Bs[XP_BK][XP_BSROW];

    int tid  = threadIdx.x;
    int m0   = blockIdx.x * XP_BM;
    int kc   = blockIdx.y;
    int kbeg = kc * (DINNER/XP_KSPLIT);
    int kend = kbeg + (DINNER/XP_KSPLIT);
    int r    = tid >> 4;   // 0..15 row
    int cg   = tid & 15;   // col group: cols cg*6 .. cg*6+5

    ull acc[2][3];
    #pragma unroll
    for (int p = 0; p < 2; p++)
        #pragma unroll
        for (int j = 0; j < 3; j++) acc[p][j] = 0ull;

    for (int k0 = kbeg; k0 < kend; k0 += XP_BK) {
        #pragma unroll
        for (int e = tid; e < XP_BM*XP_BK; e += 256) {
            int k = e & 31, m = e >> 5;
            As[k][m] = u[(size_t)(m0+m)*DINNER + k0 + k];
        }
        #pragma unroll
        for (int e = tid; e < XPROJ_OUT*XP_BK; e += 256) {
            int k = e & 31, n = e >> 5;
            Bs[k][n] = w[(size_t)n*DINNER + k0 + k];
        }
        __syncthreads();
        #pragma unroll
        for (int kk = 0; kk < XP_BK; kk += 2) {
            ull a0 = pack_dup(As[kk  ][r]);
            ull a1 = pack_dup(As[kk+1][r]);
            const ull* b0 = reinterpret_cast<const ull*>(&Bs[kk  ][cg*6]);
            const ull* b1 = reinterpret_cast<const ull*>(&Bs[kk+1][cg*6]);
            ffma2(acc[0][0], a0, b0[0]);
            ffma2(acc[0][1], a0, b0[1]);
            ffma2(acc[0][2], a0, b0[2]);
            ffma2(acc[1][0], a1, b1[0]);
            ffma2(acc[1][1], a1, b1[1]);
            ffma2(acc[1][2], a1, b1[2]);
        }
        __syncthreads();
    }

    float* o = part + (size_t)kc*ROWS*XPROJ_OUT + (size_t)(m0 + r)*XPROJ_OUT + cg*6;
    #pragma unroll
    for (int j = 0; j < 3; j++) {
        float2 v0 = unpack2(acc[0][j]);
        float2 v1 = unpack2(acc[1][j]);
        v0.x += v1.x; v0.y += v1.y;
        *reinterpret_cast<float2*>(o + 2*j) = v0;
    }
}

__global__ void xpart_reduce(const float* __restrict__ part, float* __restrict__ xdbl)
{
    int i = blockIdx.x*blockDim.x + threadIdx.x;
    if (i >= ROWS*XPROJ_OUT) return;
    const int S = ROWS*XPROJ_OUT;
    xdbl[i] = (part[i] + part[i+S]) + (part[i+2*S] + part[i+3*S]);
}

// ---------------- causal depthwise conv1d + SiLU (emits u and u^T) ----------
__global__ void conv_silu_kernel(const float* __restrict__ xz, const float* __restrict__ w,
                                 const float* __restrict__ bias, float* __restrict__ u,
                                 float* __restrict__ uT)
{
    int i = blockIdx.x*blockDim.x + threadIdx.x;
    if (i >= ROWS*DINNER) return;
    int d    = i % DINNER;
    int row  = i / DINNER;       // b*SEQ + l
    int l    = row % SEQ;
    float acc = bias[d];
    #pragma unroll
    for (int t = 0; t < DCONV; t++) {
        int li = l + t - (DCONV-1);
        if (li >= 0)
            acc += xz[((size_t)(row + li - l))*(2*DINNER) + d] * w[d*DCONV + t];
    }
    float sig = 1.f / (1.f + expf(-acc));
    float val = acc * sig;
    u[i] = val;
    uT[(size_t)d*ROWS + row] = val;
}

// ---------------- selective scan: transposed operands, pipelined gate -------
__global__ __launch_bounds__(256) void scan_kernel(
    const float* __restrict__ deltaT, const float* __restrict__ uT,
    const float* __restrict__ xdbl, const float* __restrict__ xz,
    const float* __restrict__ A_log, const float* __restrict__ Dskip,
    float* __restrict__ yg)
{
    int warp = threadIdx.x >> 5;
    int lane = threadIdx.x & 31;
    int half = lane >> 4;
    int n    = lane & 15;
    int c    = blockIdx.x*16 + warp*2 + half;   // 0..4095
    int b    = c / DINNER;
    int d    = c % DINNER;

    float A  = -expf(A_log[d*DSTATE + n]);
    float Dd = Dskip[d];
    float h  = 0.f;

    const float* drow = deltaT + (size_t)d*ROWS + b*SEQ;   // contiguous in t
    const float* urow = uT     + (size_t)d*ROWS + b*SEQ;   // contiguous in t
    const float* xrow = xdbl   + (size_t)b*SEQ*XPROJ_OUT;
    const float* zp   = xz     + (size_t)b*SEQ*(2*DINNER) + DINNER + d;
    float*       yrow = yg     + (size_t)b*SEQ*DINNER + d;

    const size_t ZS = 2*DINNER;
    float z0 = zp[0];
    float z1 = zp[ZS];

    for (int t = 0; t < SEQ; t++) {
        float z2 = (t+2 < SEQ) ? zp[(size_t)(t+2)*ZS] : 0.f;  // prefetch, dist 2
        float dt = drow[t];
        float ut = urow[t];
        float Bn = xrow[t*XPROJ_OUT + DTRANK + n];
        float Cn = xrow[t*XPROJ_OUT + DTRANK + DSTATE + n];
        float dA = expf(dt * A);
        h = fmaf(dA, h, dt*ut*Bn);
        float p = h * Cn;
        p += __shfl_xor_sync(0xffffffffu, p, 8);
        p += __shfl_xor_sync(0xffffffffu, p, 4);
        p += __shfl_xor_sync(0xffffffffu, p, 2);
        p += __shfl_xor_sync(0xffffffffu, p, 1);
        if (n == 0) {
            float s = z0 / (1.f + expf(-z0));
            yrow[(size_t)t*DINNER] = fmaf(ut, Dd, p) * s;
        }
        z0 = z1; z1 = z2;
    }
}

// ---------------- launch ----------------------------------------------------
extern "C" void kernel_launch(void* const* d_in, const int* in_sizes, int n_in,
                              void* d_out, int out_size)
{
    const float* x      = (const float*)d_in[0];
    const float* ln_g   = (const float*)d_in[1];
    const float* ln_b   = (const float*)d_in[2];
    const float* w_in   = (const float*)d_in[3];
    const float* conv_w = (const float*)d_in[4];
    const float* conv_b = (const float*)d_in[5];
    const float* w_x    = (const float*)d_in[6];
    const float* w_dt   = (const float*)d_in[7];
    const float* b_dt   = (const float*)d_in[8];
    const float* A_log  = (const float*)d_in[9];
    const float* Dsk    = (const float*)d_in[10];
    const float* w_out  = (const float*)d_in[11];
    float* out = (float*)d_out;

    float *xn, *xz, *u, *uT, *xdbl, *xpart, *deltaT, *yg;
    cudaGetSymbolAddress((void**)&xn,     g_xn);
    cudaGetSymbolAddress((void**)&xz,     g_xz);
    cudaGetSymbolAddress((void**)&u,      g_u);
    cudaGetSymbolAddress((void**)&uT,     g_uT);
    cudaGetSymbolAddress((void**)&xdbl,   g_xdbl);
    cudaGetSymbolAddress((void**)&xpart,  g_xpart);
    cudaGetSymbolAddress((void**)&deltaT, g_deltaT);
    cudaGetSymbolAddress((void**)&yg,     g_yg);

    int nelem = ROWS*DINNER;

    // 1. layernorm
    ln_kernel<<<ROWS, 256>>>(x, ln_g, ln_b, xn);

    // 2. in_proj: xz[2048,4096] = xn[2048,1024] @ w_in[4096,1024]^T
    {
        dim3 g(2*DINNER/BN, ROWS/BM);
        sgemm_nt<<<g, 256>>>(xn, DMODEL, w_in, DMODEL, xz, 2*DINNER,
                             nullptr, 0, nullptr, ROWS, 2*DINNER, DMODEL, 0);
    }

    // 3. causal depthwise conv + SiLU -> u, u^T
    conv_silu_kernel<<<(nelem+255)/256, 256>>>(xz, conv_w, conv_b, u, uT);

    // 4. x_proj (split-K): xdbl[2048,96] = u @ w_x[96,2048]^T
    {
        dim3 g(ROWS/XP_BM, XP_KSPLIT);
        xproj_kernel<<<g, 256>>>(u, w_x, xpart);
        xpart_reduce<<<(ROWS*XPROJ_OUT+255)/256, 256>>>(xpart, xdbl);
    }

    // 5. dt_proj TRANSPOSED + fused softplus:
    //    deltaT[d][row] = softplus( sum_r w_dt[d][r]*xdbl[row][r] + b_dt[d] )
    {
        dim3 g(ROWS/BN, DINNER/BM);
        sgemm_nt<<<g, 256>>>(w_dt, DTRANK, xdbl, XPROJ_OUT, deltaT, ROWS,
                             nullptr, 0, b_dt, DINNER, ROWS, DTRANK, 3);
    }

    // 6. selective scan (+ u*D_skip, fused pipelined gate with silu(z))
    scan_kernel<<<(BATCH*DINNER)/16, 256>>>(deltaT, uT, xdbl, xz, A_log, Dsk, yg);

    // 7. out_proj + residual
    {
        dim3 g(DMODEL/BN, ROWS/BM);
        sgemm_nt<<<g, 256>>>(yg, DINNER, w_out, DINNER, out, DMODEL,
                             x, DMODEL, nullptr, ROWS, DMODEL, DINNER, 1);
    }
}

// round 6
// speedup vs baseline: 2.2678x; 1.2716x over previous
#include <cuda_runtime.h>
#include <cuda_bf16.h>
#include <mma.h>
#include <math.h>

using namespace nvcuda;

#define BATCH   2
#define SEQ     1024
#define DMODEL  1024
#define DINNER  2048
#define DTRANK  64
#define DSTATE  16
#define DCONV   4
#define ROWS    (BATCH*SEQ)            // 2048
#define XPROJ_OUT (DTRANK + 2*DSTATE)  // 96

typedef unsigned long long ull;

__device__ __forceinline__ void ffma2(ull &d, ull a, ull b) {
    asm("fma.rn.f32x2 %0, %1, %2, %0;" : "+l"(d) : "l"(a), "l"(b));
}
__device__ __forceinline__ ull pack_dup(float x) {
    ull r; asm("mov.b64 %0, {%1, %1};" : "=l"(r) : "f"(x)); return r;
}
__device__ __forceinline__ float2 unpack2(ull v) {
    float2 f; asm("mov.b64 {%0, %1}, %2;" : "=f"(f.x), "=f"(f.y) : "l"(v)); return f;
}

// ---------------- scratch (static device globals; no allocation) ------------
#define XP_KSPLIT 4
__device__ float g_xn    [ROWS*DMODEL];
__device__ float g_xz    [ROWS*2*DINNER];
__device__ float g_u     [ROWS*DINNER];
__device__ float g_uT    [DINNER*ROWS];
__device__ float g_xdbl  [ROWS*XPROJ_OUT];
__device__ float g_xpart [XP_KSPLIT*ROWS*XPROJ_OUT];
__device__ float g_deltaT[DINNER*ROWS];
__device__ float g_yg    [ROWS*DINNER];
// bf16 split-precision operands (K-concatenated: [hi | lo | hi] / [hi | hi | lo])
__device__ __nv_bfloat16 g_xn2  [ROWS*3*DMODEL];
__device__ __nv_bfloat16 g_win2 [2*DINNER*3*DMODEL];
__device__ __nv_bfloat16 g_yg2  [ROWS*3*DINNER];
__device__ __nv_bfloat16 g_wout2[DMODEL*3*DINNER];

// ---------------- split fp32 -> bf16 hi/lo, K-concatenated ------------------
// modeA: [k]=hi, [K+k]=lo, [2K+k]=hi      modeB: [k]=hi, [K+k]=hi, [2K+k]=lo
__global__ void split_kernel(const float* __restrict__ X, __nv_bfloat16* __restrict__ Y,
                             int K, int total, int modeB)
{
    int i = blockIdx.x*blockDim.x + threadIdx.x;
    if (i >= total) return;
    int m = i / K, k = i % K;
    float x = X[i];
    __nv_bfloat16 hi = __float2bfloat16(x);
    __nv_bfloat16 lo = __float2bfloat16(x - __bfloat162float(hi));
    __nv_bfloat16* row = Y + (size_t)m*3*K;
    row[k] = hi;
    if (modeB) { row[K+k] = hi; row[2*K+k] = lo; }
    else       { row[K+k] = lo; row[2*K+k] = hi; }
}

// ---------------- wmma bf16 GEMM NT: C[M,N] = A2[M,K3] @ B2[N,K3]^T ---------
// 128x128 tile, BKW=32, 8 warps (2x4), warp tile 64x32. mode: 0 plain, 1 +=R.
#define WBM 128
#define WBN 128
#define WBK 32
#define WPITCH 40   // bf16 pitch: 80 bytes, 16B-aligned rows

__global__ __launch_bounds__(256) void wmma_nt(
    const __nv_bfloat16* __restrict__ A2, const __nv_bfloat16* __restrict__ B2,
    float* __restrict__ C, int ldc, const float* __restrict__ R, int ldr,
    int M, int N, int K3, int mode)
{
    __shared__ __nv_bfloat16 Asm[WBM*WPITCH];
    __shared__ __nv_bfloat16 Bsm[WBN*WPITCH];

    int tid = threadIdx.x;
    int w   = tid >> 5;
    int wm  = w >> 2;          // 0..1
    int wn  = w & 3;           // 0..3
    int m0  = blockIdx.y * WBM;
    int n0  = blockIdx.x * WBN;

    wmma::fragment<wmma::accumulator, 16,16,16, float> acc[4][2];
    #pragma unroll
    for (int i = 0; i < 4; i++)
        #pragma unroll
        for (int j = 0; j < 2; j++) wmma::fill_fragment(acc[i][j], 0.f);

    for (int k0 = 0; k0 < K3; k0 += WBK) {
        // stage A tile: 128 rows x 32 bf16; 512 int4 chunks, 2 per thread
        #pragma unroll
        for (int e = tid; e < WBM*4; e += 256) {
            int row = e >> 2, q = e & 3;
            *reinterpret_cast<int4*>(&Asm[row*WPITCH + q*8]) =
                *reinterpret_cast<const int4*>(A2 + (size_t)(m0+row)*K3 + k0 + q*8);
        }
        #pragma unroll
        for (int e = tid; e < WBN*4; e += 256) {
            int row = e >> 2, q = e & 3;
            *reinterpret_cast<int4*>(&Bsm[row*WPITCH + q*8]) =
                *reinterpret_cast<const int4*>(B2 + (size_t)(n0+row)*K3 + k0 + q*8);
        }
        __syncthreads();

        #pragma unroll
        for (int ks = 0; ks < WBK; ks += 16) {
            wmma::fragment<wmma::matrix_a, 16,16,16, __nv_bfloat16, wmma::row_major> af[4];
            wmma::fragment<wmma::matrix_b, 16,16,16, __nv_bfloat16, wmma::col_major> bf[2];
            #pragma unroll
            for (int i = 0; i < 4; i++)
                wmma::load_matrix_sync(af[i], &Asm[(wm*64 + i*16)*WPITCH + ks], WPITCH);
            #pragma unroll
            for (int j = 0; j < 2; j++)
                wmma::load_matrix_sync(bf[j], &Bsm[(wn*32 + j*16)*WPITCH + ks], WPITCH);
            #pragma unroll
            for (int i = 0; i < 4; i++)
                #pragma unroll
                for (int j = 0; j < 2; j++)
                    wmma::mma_sync(acc[i][j], af[i], bf[j], acc[i][j]);
        }
        __syncthreads();
    }

    #pragma unroll
    for (int i = 0; i < 4; i++) {
        int m = m0 + wm*64 + i*16;
        #pragma unroll
        for (int j = 0; j < 2; j++) {
            int n = n0 + wn*32 + j*16;
            if (mode == 1) {
                wmma::fragment<wmma::accumulator, 16,16,16, float> rf;
                wmma::load_matrix_sync(rf, R + (size_t)m*ldr + n, ldr, wmma::mem_row_major);
                #pragma unroll
                for (int t = 0; t < acc[i][j].num_elements; t++)
                    acc[i][j].x[t] += rf.x[t];
            }
            wmma::store_matrix_sync(C + (size_t)m*ldc + n, acc[i][j], ldc, wmma::mem_row_major);
        }
    }
}

// ---------------- LayerNorm: one block per row ------------------------------
__global__ void ln_kernel(const float* __restrict__ x, const float* __restrict__ g,
                          const float* __restrict__ b, float* __restrict__ out)
{
    int row = blockIdx.x;
    int tid = threadIdx.x;
    const float* xr = x + (size_t)row*DMODEL;
    float v[4];
    float s1 = 0.f, s2 = 0.f;
    #pragma unroll
    for (int i = 0; i < 4; i++) {
        v[i] = xr[tid + 256*i];
        s1 += v[i];
        s2 += v[i]*v[i];
    }
    __shared__ float sh1[8], sh2[8];
    #pragma unroll
    for (int o = 16; o; o >>= 1) {
        s1 += __shfl_xor_sync(0xffffffffu, s1, o);
        s2 += __shfl_xor_sync(0xffffffffu, s2, o);
    }
    if ((tid & 31) == 0) { sh1[tid>>5] = s1; sh2[tid>>5] = s2; }
    __syncthreads();
    if (tid < 32) {
        float a = (tid < 8) ? sh1[tid] : 0.f;
        float c = (tid < 8) ? sh2[tid] : 0.f;
        #pragma unroll
        for (int o = 4; o; o >>= 1) {
            a += __shfl_xor_sync(0xffffffffu, a, o);
            c += __shfl_xor_sync(0xffffffffu, c, o);
        }
        if (tid == 0) { sh1[0] = a; sh2[0] = c; }
    }
    __syncthreads();
    float mu  = sh1[0] * (1.f/DMODEL);
    float var = sh2[0] * (1.f/DMODEL) - mu*mu;
    float r   = rsqrtf(var + 1e-5f);
    float* o = out + (size_t)row*DMODEL;
    #pragma unroll
    for (int i = 0; i < 4; i++) {
        int c = tid + 256*i;
        o[c] = (v[i]-mu)*r*g[c] + b[c];
    }
}

// ---------------- SGEMM NT (scalar FFMA) — small GEMMs ----------------------
//   0: plain store, 1: += R (residual), 3: softplus(v + bias[m])
#define BM 128
#define BN 128
#define BKT 8

__global__ __launch_bounds__(256) void sgemm_nt(
    const float* __restrict__ A, int lda,
    const float* __restrict__ B, int ldb,
    float* __restrict__ C, int ldc,
    const float* __restrict__ R, int ldr,
    const float* __restrict__ bias,
    int M, int N, int K, int mode)
{
    __shared__ float As[BKT][BM+4];
    __shared__ float Bs[BKT][BN+4];

    int tid = threadIdx.x;
    int tx  = tid & 15;
    int ty  = tid >> 4;
    int m0  = blockIdx.y * BM;
    int n0  = blockIdx.x * BN;

    int lrow = tid >> 1;
    int lk4  = (tid & 1) * 4;

    float acc[8][8];
    #pragma unroll
    for (int i = 0; i < 8; i++)
        #pragma unroll
        for (int j = 0; j < 8; j++) acc[i][j] = 0.f;

    for (int k0 = 0; k0 < K; k0 += BKT) {
        float4 a = make_float4(0.f,0.f,0.f,0.f);
        int am = m0 + lrow;
        if (am < M) a = *reinterpret_cast<const float4*>(A + (size_t)am*lda + k0 + lk4);
        As[lk4+0][lrow] = a.x; As[lk4+1][lrow] = a.y;
        As[lk4+2][lrow] = a.z; As[lk4+3][lrow] = a.w;

        float4 bv = make_float4(0.f,0.f,0.f,0.f);
        int bn = n0 + lrow;
        if (bn < N) bv = *reinterpret_cast<const float4*>(B + (size_t)bn*ldb + k0 + lk4);
        Bs[lk4+0][lrow] = bv.x; Bs[lk4+1][lrow] = bv.y;
        Bs[lk4+2][lrow] = bv.z; Bs[lk4+3][lrow] = bv.w;

        __syncthreads();

        #pragma unroll
        for (int kk = 0; kk < BKT; kk++) {
            float ra[8], rb[8];
            #pragma unroll
            for (int i = 0; i < 4; i++) {
                ra[i]   = As[kk][ty*4 + i];
                ra[i+4] = As[kk][64 + ty*4 + i];
                rb[i]   = Bs[kk][tx*4 + i];
                rb[i+4] = Bs[kk][64 + tx*4 + i];
            }
            #pragma unroll
            for (int i = 0; i < 8; i++)
                #pragma unroll
                for (int j = 0; j < 8; j++)
                    acc[i][j] = fmaf(ra[i], rb[j], acc[i][j]);
        }
        __syncthreads();
    }

    #pragma unroll
    for (int i = 0; i < 8; i++) {
        int m = m0 + ((i < 4) ? (ty*4 + i) : (64 + ty*4 + i - 4));
        if (m >= M) continue;
        float bm = (mode == 3) ? bias[m] : 0.f;
        #pragma unroll
        for (int j = 0; j < 8; j++) {
            int n = n0 + ((j < 4) ? (tx*4 + j) : (64 + tx*4 + j - 4));
            if (n < N) {
                float val = acc[i][j];
                if (mode == 1) {
                    val += R[(size_t)m*ldr + n];
                } else if (mode == 3) {
                    float v = val + bm;
                    val = (v > 20.f) ? v : log1pf(expf(v));
                }
                C[(size_t)m*ldc + n] = val;
            }
        }
    }
}

// ---------------- x_proj tall-skinny GEMM, split-K --------------------------
#define XP_BM 16
#define XP_BK 32
#define XP_BSROW 98

__global__ __launch_bounds__(256) void xproj_kernel(
    const float* __restrict__ u, const float* __restrict__ w, float* __restrict__ part)
{
    __shared__ float As[XP_BK][XP_BM+1];
    __shared__ float Bs[XP_BK][XP_BSROW];

    int tid  = threadIdx.x;
    int m0   = blockIdx.x * XP_BM;
    int kc   = blockIdx.y;
    int kbeg = kc * (DINNER/XP_KSPLIT);
    int kend = kbeg + (DINNER/XP_KSPLIT);
    int r    = tid >> 4;
    int cg   = tid & 15;

    ull acc[2][3];
    #pragma unroll
    for (int p = 0; p < 2; p++)
        #pragma unroll
        for (int j = 0; j < 3; j++) acc[p][j] = 0ull;

    for (int k0 = kbeg; k0 < kend; k0 += XP_BK) {
        #pragma unroll
        for (int e = tid; e < XP_BM*XP_BK; e += 256) {
            int k = e & 31, m = e >> 5;
            As[k][m] = u[(size_t)(m0+m)*DINNER + k0 + k];
        }
        #pragma unroll
        for (int e = tid; e < XPROJ_OUT*XP_BK; e += 256) {
            int k = e & 31, n = e >> 5;
            Bs[k][n] = w[(size_t)n*DINNER + k0 + k];
        }
        __syncthreads();
        #pragma unroll
        for (int kk = 0; kk < XP_BK; kk += 2) {
            ull a0 = pack_dup(As[kk  ][r]);
            ull a1 = pack_dup(As[kk+1][r]);
            const ull* b0 = reinterpret_cast<const ull*>(&Bs[kk  ][cg*6]);
            const ull* b1 = reinterpret_cast<const ull*>(&Bs[kk+1][cg*6]);
            ffma2(acc[0][0], a0, b0[0]);
            ffma2(acc[0][1], a0, b0[1]);
            ffma2(acc[0][2], a0, b0[2]);
            ffma2(acc[1][0], a1, b1[0]);
            ffma2(acc[1][1], a1, b1[1]);
            ffma2(acc[1][2], a1, b1[2]);
        }
        __syncthreads();
    }

    float* o = part + (size_t)kc*ROWS*XPROJ_OUT + (size_t)(m0 + r)*XPROJ_OUT + cg*6;
    #pragma unroll
    for (int j = 0; j < 3; j++) {
        float2 v0 = unpack2(acc[0][j]);
        float2 v1 = unpack2(acc[1][j]);
        v0.x += v1.x; v0.y += v1.y;
        *reinterpret_cast<float2*>(o + 2*j) = v0;
    }
}

__global__ void xpart_reduce(const float* __restrict__ part, float* __restrict__ xdbl)
{
    int i = blockIdx.x*blockDim.x + threadIdx.x;
    if (i >= ROWS*XPROJ_OUT) return;
    const int S = ROWS*XPROJ_OUT;
    xdbl[i] = (part[i] + part[i+S]) + (part[i+2*S] + part[i+3*S]);
}

// ---------------- causal depthwise conv1d + SiLU (emits u and u^T) ----------
__global__ void conv_silu_kernel(const float* __restrict__ xz, const float* __restrict__ w,
                                 const float* __restrict__ bias, float* __restrict__ u,
                                 float* __restrict__ uT)
{
    int i = blockIdx.x*blockDim.x + threadIdx.x;
    if (i >= ROWS*DINNER) return;
    int d    = i % DINNER;
    int row  = i / DINNER;
    int l    = row % SEQ;
    float acc = bias[d];
    #pragma unroll
    for (int t = 0; t < DCONV; t++) {
        int li = l + t - (DCONV-1);
        if (li >= 0)
            acc += xz[((size_t)(row + li - l))*(2*DINNER) + d] * w[d*DCONV + t];
    }
    float sig = 1.f / (1.f + expf(-acc));
    float val = acc * sig;
    u[i] = val;
    uT[(size_t)d*ROWS + row] = val;
}

// ---------------- selective scan: transposed operands, pipelined gate -------
__global__ __launch_bounds__(256) void scan_kernel(
    const float* __restrict__ deltaT, const float* __restrict__ uT,
    const float* __restrict__ xdbl, const float* __restrict__ xz,
    const float* __restrict__ A_log, const float* __restrict__ Dskip,
    float* __restrict__ yg)
{
    int warp = threadIdx.x >> 5;
    int lane = threadIdx.x & 31;
    int half = lane >> 4;
    int n    = lane & 15;
    int c    = blockIdx.x*16 + warp*2 + half;
    int b    = c / DINNER;
    int d    = c % DINNER;

    float A  = -expf(A_log[d*DSTATE + n]);
    float Dd = Dskip[d];
    float h  = 0.f;

    const float* drow = deltaT + (size_t)d*ROWS + b*SEQ;
    const float* urow = uT     + (size_t)d*ROWS + b*SEQ;
    const float* xrow = xdbl   + (size_t)b*SEQ*XPROJ_OUT;
    const float* zp   = xz     + (size_t)b*SEQ*(2*DINNER) + DINNER + d;
    float*       yrow = yg     + (size_t)b*SEQ*DINNER + d;

    const size_t ZS = 2*DINNER;
    float z0 = zp[0];
    float z1 = zp[ZS];

    for (int t = 0; t < SEQ; t++) {
        float z2 = (t+2 < SEQ) ? zp[(size_t)(t+2)*ZS] : 0.f;
        float dt = drow[t];
        float ut = urow[t];
        float Bn = xrow[t*XPROJ_OUT + DTRANK + n];
        float Cn = xrow[t*XPROJ_OUT + DTRANK + DSTATE + n];
        float dA = expf(dt * A);
        h = fmaf(dA, h, dt*ut*Bn);
        float p = h * Cn;
        p += __shfl_xor_sync(0xffffffffu, p, 8);
        p += __shfl_xor_sync(0xffffffffu, p, 4);
        p += __shfl_xor_sync(0xffffffffu, p, 2);
        p += __shfl_xor_sync(0xffffffffu, p, 1);
        if (n == 0) {
            float s = z0 / (1.f + expf(-z0));
            yrow[(size_t)t*DINNER] = fmaf(ut, Dd, p) * s;
        }
        z0 = z1; z1 = z2;
    }
}

// ---------------- launch ----------------------------------------------------
extern "C" void kernel_launch(void* const* d_in, const int* in_sizes, int n_in,
                              void* d_out, int out_size)
{
    const float* x      = (const float*)d_in[0];
    const float* ln_g   = (const float*)d_in[1];
    const float* ln_b   = (const float*)d_in[2];
    const float* w_in   = (const float*)d_in[3];
    const float* conv_w = (const float*)d_in[4];
    const float* conv_b = (const float*)d_in[5];
    const float* w_x    = (const float*)d_in[6];
    const float* w_dt   = (const float*)d_in[7];
    const float* b_dt   = (const float*)d_in[8];
    const float* A_log  = (const float*)d_in[9];
    const float* Dsk    = (const float*)d_in[10];
    const float* w_out  = (const float*)d_in[11];
    float* out = (float*)d_out;

    float *xn, *xz, *u, *uT, *xdbl, *xpart, *deltaT, *yg;
    __nv_bfloat16 *xn2, *win2, *yg2, *wout2;
    cudaGetSymbolAddress((void**)&xn,     g_xn);
    cudaGetSymbolAddress((void**)&xz,     g_xz);
    cudaGetSymbolAddress((void**)&u,      g_u);
    cudaGetSymbolAddress((void**)&uT,     g_uT);
    cudaGetSymbolAddress((void**)&xdbl,   g_xdbl);
    cudaGetSymbolAddress((void**)&xpart,  g_xpart);
    cudaGetSymbolAddress((void**)&deltaT, g_deltaT);
    cudaGetSymbolAddress((void**)&yg,     g_yg);
    cudaGetSymbolAddress((void**)&xn2,    g_xn2);
    cudaGetSymbolAddress((void**)&win2,   g_win2);
    cudaGetSymbolAddress((void**)&yg2,    g_yg2);
    cudaGetSymbolAddress((void**)&wout2,  g_wout2);

    int nelem = ROWS*DINNER;

    // 1. layernorm
    ln_kernel<<<ROWS, 256>>>(x, ln_g, ln_b, xn);

    // 2. in_proj on tensor cores: split xn and w_in, then bf16 GEMM K3=3072
    split_kernel<<<(ROWS*DMODEL+255)/256, 256>>>(xn, xn2, DMODEL, ROWS*DMODEL, 0);
    split_kernel<<<(2*DINNER*DMODEL+255)/256, 256>>>(w_in, win2, DMODEL, 2*DINNER*DMODEL, 1);
    {
        dim3 g(2*DINNER/WBN, ROWS/WBM);
        wmma_nt<<<g, 256>>>(xn2, win2, xz, 2*DINNER, nullptr, 0,
                            ROWS, 2*DINNER, 3*DMODEL, 0);
    }

    // 3. causal depthwise conv + SiLU -> u, u^T
    conv_silu_kernel<<<(nelem+255)/256, 256>>>(xz, conv_w, conv_b, u, uT);

    // 4. x_proj (split-K): xdbl[2048,96] = u @ w_x[96,2048]^T
    {
        dim3 g(ROWS/XP_BM, XP_KSPLIT);
        xproj_kernel<<<g, 256>>>(u, w_x, xpart);
        xpart_reduce<<<(ROWS*XPROJ_OUT+255)/256, 256>>>(xpart, xdbl);
    }

    // 5. dt_proj TRANSPOSED + fused softplus
    {
        dim3 g(ROWS/BN, DINNER/BM);
        sgemm_nt<<<g, 256>>>(w_dt, DTRANK, xdbl, XPROJ_OUT, deltaT, ROWS,
                             nullptr, 0, b_dt, DINNER, ROWS, DTRANK, 3);
    }

    // 6. selective scan (+ u*D_skip, fused pipelined gate with silu(z))
    scan_kernel<<<(BATCH*DINNER)/16, 256>>>(deltaT, uT, xdbl, xz, A_log, Dsk, yg);

    // 7. out_proj on tensor cores + residual: K3=6144
    split_kernel<<<(nelem+255)/256, 256>>>(yg, yg2, DINNER, nelem, 0);
    split_kernel<<<(DMODEL*DINNER+255)/256, 256>>>(w_out, wout2, DINNER, DMODEL*DINNER, 1);
    {
        dim3 g(DMODEL/WBN, ROWS/WBM);
        wmma_nt<<<g, 256>>>(yg2, wout2, out, DMODEL, x, DMODEL,
                            ROWS, DMODEL, 3*DINNER, 1);
    }
}

// round 7
// speedup vs baseline: 2.3836x; 1.0510x over previous
#include <cuda_runtime.h>
#include <cuda_bf16.h>
#include <mma.h>
#include <math.h>

using namespace nvcuda;

#define BATCH   2
#define SEQ     1024
#define DMODEL  1024
#define DINNER  2048
#define DTRANK  64
#define DSTATE  16
#define DCONV   4
#define ROWS    (BATCH*SEQ)            // 2048
#define XPROJ_OUT (DTRANK + 2*DSTATE)  // 96

typedef unsigned long long ull;

__device__ __forceinline__ void ffma2(ull &d, ull a, ull b) {
    asm("fma.rn.f32x2 %0, %1, %2, %0;" : "+l"(d) : "l"(a), "l"(b));
}
__device__ __forceinline__ ull pack_dup(float x) {
    ull r; asm("mov.b64 %0, {%1, %1};" : "=l"(r) : "f"(x)); return r;
}
__device__ __forceinline__ float2 unpack2(ull v) {
    float2 f; asm("mov.b64 {%0, %1}, %2;" : "=f"(f.x), "=f"(f.y) : "l"(v)); return f;
}
__device__ __forceinline__ void cp_async16(void* smem, const void* gmem) {
    unsigned s = (unsigned)__cvta_generic_to_shared(smem);
    asm volatile("cp.async.cg.shared.global [%0], [%1], 16;" :: "r"(s), "l"(gmem));
}
#define CP_COMMIT() asm volatile("cp.async.commit_group;")
#define CP_WAIT0()  asm volatile("cp.async.wait_group 0;")

// ---------------- scratch (static device globals; no allocation) ------------
#define XP_KSPLIT 4
__device__ float g_xz    [ROWS*2*DINNER];
__device__ float g_u     [ROWS*DINNER];
__device__ float g_uT    [DINNER*ROWS];
__device__ float g_xdbl  [ROWS*XPROJ_OUT];
__device__ float g_xpart [XP_KSPLIT*ROWS*XPROJ_OUT];
__device__ float g_deltaT[DINNER*ROWS];
// bf16 split-precision operands (K-concatenated: [hi | lo | hi] / [hi | hi | lo])
__device__ __nv_bfloat16 g_xn2  [ROWS*3*DMODEL];
__device__ __nv_bfloat16 g_win2 [2*DINNER*3*DMODEL];
__device__ __nv_bfloat16 g_yg2  [ROWS*3*DINNER];
__device__ __nv_bfloat16 g_wout2[DMODEL*3*DINNER];

// ---------------- split fp32 -> bf16 hi/lo (weights only) -------------------
// modeB: [k]=hi, [K+k]=hi, [2K+k]=lo
__global__ void split_kernel(const float* __restrict__ X, __nv_bfloat16* __restrict__ Y,
                             int K, int total)
{
    int i = blockIdx.x*blockDim.x + threadIdx.x;
    if (i >= total) return;
    int m = i / K, k = i % K;
    float x = X[i];
    __nv_bfloat16 hi = __float2bfloat16(x);
    __nv_bfloat16 lo = __float2bfloat16(x - __bfloat162float(hi));
    __nv_bfloat16* row = Y + (size_t)m*3*K;
    row[k] = hi; row[K+k] = hi; row[2*K+k] = lo;
}

// ---------------- wmma bf16 GEMM NT, cp.async double-buffered ---------------
// C[M,N] = A2[M,K3] @ B2[N,K3]^T; mode: 0 plain, 1 += R
#define WBM 128
#define WBN 128
#define WBK 32
#define WPITCH 40   // bf16 pitch: 80 bytes

__global__ __launch_bounds__(256) void wmma_nt(
    const __nv_bfloat16* __restrict__ A2, const __nv_bfloat16* __restrict__ B2,
    float* __restrict__ C, int ldc, const float* __restrict__ R, int ldr,
    int M, int N, int K3, int mode)
{
    __shared__ __align__(16) __nv_bfloat16 Asm[2][WBM*WPITCH];
    __shared__ __align__(16) __nv_bfloat16 Bsm[2][WBN*WPITCH];

    int tid = threadIdx.x;
    int w   = tid >> 5;
    int wm  = w >> 2;          // 0..1
    int wn  = w & 3;           // 0..3
    int m0  = blockIdx.y * WBM;
    int n0  = blockIdx.x * WBN;

    wmma::fragment<wmma::accumulator, 16,16,16, float> acc[4][2];
    #pragma unroll
    for (int i = 0; i < 4; i++)
        #pragma unroll
        for (int j = 0; j < 2; j++) wmma::fill_fragment(acc[i][j], 0.f);

    // stage tile k0 into buffer buf
    auto stage = [&](int buf, int k0) {
        #pragma unroll
        for (int e = tid; e < WBM*4; e += 256) {
            int row = e >> 2, q = e & 3;
            cp_async16(&Asm[buf][row*WPITCH + q*8],
                       A2 + (size_t)(m0+row)*K3 + k0 + q*8);
        }
        #pragma unroll
        for (int e = tid; e < WBN*4; e += 256) {
            int row = e >> 2, q = e & 3;
            cp_async16(&Bsm[buf][row*WPITCH + q*8],
                       B2 + (size_t)(n0+row)*K3 + k0 + q*8);
        }
        CP_COMMIT();
    };

    stage(0, 0);
    int buf = 0;
    for (int k0 = 0; k0 < K3; k0 += WBK) {
        CP_WAIT0();
        __syncthreads();
        if (k0 + WBK < K3) stage(buf ^ 1, k0 + WBK);

        #pragma unroll
        for (int ks = 0; ks < WBK; ks += 16) {
            wmma::fragment<wmma::matrix_a, 16,16,16, __nv_bfloat16, wmma::row_major> af[4];
            wmma::fragment<wmma::matrix_b, 16,16,16, __nv_bfloat16, wmma::col_major> bf[2];
            #pragma unroll
            for (int i = 0; i < 4; i++)
                wmma::load_matrix_sync(af[i], &Asm[buf][(wm*64 + i*16)*WPITCH + ks], WPITCH);
            #pragma unroll
            for (int j = 0; j < 2; j++)
                wmma::load_matrix_sync(bf[j], &Bsm[buf][(wn*32 + j*16)*WPITCH + ks], WPITCH);
            #pragma unroll
            for (int i = 0; i < 4; i++)
                #pragma unroll
                for (int j = 0; j < 2; j++)
                    wmma::mma_sync(acc[i][j], af[i], bf[j], acc[i][j]);
        }
        buf ^= 1;
        __syncthreads();
    }

    #pragma unroll
    for (int i = 0; i < 4; i++) {
        int m = m0 + wm*64 + i*16;
        #pragma unroll
        for (int j = 0; j < 2; j++) {
            int n = n0 + wn*32 + j*16;
            if (mode == 1) {
                wmma::fragment<wmma::accumulator, 16,16,16, float> rf;
                wmma::load_matrix_sync(rf, R + (size_t)m*ldr + n, ldr, wmma::mem_row_major);
                #pragma unroll
                for (int t = 0; t < acc[i][j].num_elements; t++)
                    acc[i][j].x[t] += rf.x[t];
            }
            wmma::store_matrix_sync(C + (size_t)m*ldc + n, acc[i][j], ldc, wmma::mem_row_major);
        }
    }
}

// ---------------- LayerNorm -> split bf16 [hi|lo|hi] directly ---------------
__global__ void ln_kernel(const float* __restrict__ x, const float* __restrict__ g,
                          const float* __restrict__ b, __nv_bfloat16* __restrict__ xn2)
{
    int row = blockIdx.x;
    int tid = threadIdx.x;
    const float* xr = x + (size_t)row*DMODEL;
    float v[4];
    float s1 = 0.f, s2 = 0.f;
    #pragma unroll
    for (int i = 0; i < 4; i++) {
        v[i] = xr[tid + 256*i];
        s1 += v[i];
        s2 += v[i]*v[i];
    }
    __shared__ float sh1[8], sh2[8];
    #pragma unroll
    for (int o = 16; o; o >>= 1) {
        s1 += __shfl_xor_sync(0xffffffffu, s1, o);
        s2 += __shfl_xor_sync(0xffffffffu, s2, o);
    }
    if ((tid & 31) == 0) { sh1[tid>>5] = s1; sh2[tid>>5] = s2; }
    __syncthreads();
    if (tid < 32) {
        float a = (tid < 8) ? sh1[tid] : 0.f;
        float c = (tid < 8) ? sh2[tid] : 0.f;
        #pragma unroll
        for (int o = 4; o; o >>= 1) {
            a += __shfl_xor_sync(0xffffffffu, a, o);
            c += __shfl_xor_sync(0xffffffffu, c, o);
        }
        if (tid == 0) { sh1[0] = a; sh2[0] = c; }
    }
    __syncthreads();
    float mu  = sh1[0] * (1.f/DMODEL);
    float var = sh2[0] * (1.f/DMODEL) - mu*mu;
    float r   = rsqrtf(var + 1e-5f);
    __nv_bfloat16* o = xn2 + (size_t)row*3*DMODEL;
    #pragma unroll
    for (int i = 0; i < 4; i++) {
        int c = tid + 256*i;
        float val = (v[i]-mu)*r*g[c] + b[c];
        __nv_bfloat16 hi = __float2bfloat16(val);
        __nv_bfloat16 lo = __float2bfloat16(val - __bfloat162float(hi));
        o[c] = hi; o[DMODEL+c] = lo; o[2*DMODEL+c] = hi;
    }
}

// ---------------- SGEMM NT (scalar FFMA) — small GEMMs ----------------------
//   0: plain store, 1: += R, 3: softplus(v + bias[m])
#define BM 128
#define BN 128
#define BKT 8

__global__ __launch_bounds__(256) void sgemm_nt(
    const float* __restrict__ A, int lda,
    const float* __restrict__ B, int ldb,
    float* __restrict__ C, int ldc,
    const float* __restrict__ R, int ldr,
    const float* __restrict__ bias,
    int M, int N, int K, int mode)
{
    __shared__ float As[BKT][BM+4];
    __shared__ float Bs[BKT][BN+4];

    int tid = threadIdx.x;
    int tx  = tid & 15;
    int ty  = tid >> 4;
    int m0  = blockIdx.y * BM;
    int n0  = blockIdx.x * BN;

    int lrow = tid >> 1;
    int lk4  = (tid & 1) * 4;

    float acc[8][8];
    #pragma unroll
    for (int i = 0; i < 8; i++)
        #pragma unroll
        for (int j = 0; j < 8; j++) acc[i][j] = 0.f;

    for (int k0 = 0; k0 < K; k0 += BKT) {
        float4 a = make_float4(0.f,0.f,0.f,0.f);
        int am = m0 + lrow;
        if (am < M) a = *reinterpret_cast<const float4*>(A + (size_t)am*lda + k0 + lk4);
        As[lk4+0][lrow] = a.x; As[lk4+1][lrow] = a.y;
        As[lk4+2][lrow] = a.z; As[lk4+3][lrow] = a.w;

        float4 bv = make_float4(0.f,0.f,0.f,0.f);
        int bn = n0 + lrow;
        if (bn < N) bv = *reinterpret_cast<const float4*>(B + (size_t)bn*ldb + k0 + lk4);
        Bs[lk4+0][lrow] = bv.x; Bs[lk4+1][lrow] = bv.y;
        Bs[lk4+2][lrow] = bv.z; Bs[lk4+3][lrow] = bv.w;

        __syncthreads();

        #pragma unroll
        for (int kk = 0; kk < BKT; kk++) {
            float ra[8], rb[8];
            #pragma unroll
            for (int i = 0; i < 4; i++) {
                ra[i]   = As[kk][ty*4 + i];
                ra[i+4] = As[kk][64 + ty*4 + i];
                rb[i]   = Bs[kk][tx*4 + i];
                rb[i+4] = Bs[kk][64 + tx*4 + i];
            }
            #pragma unroll
            for (int i = 0; i < 8; i++)
                #pragma unroll
                for (int j = 0; j < 8; j++)
                    acc[i][j] = fmaf(ra[i], rb[j], acc[i][j]);
        }
        __syncthreads();
    }

    #pragma unroll
    for (int i = 0; i < 8; i++) {
        int m = m0 + ((i < 4) ? (ty*4 + i) : (64 + ty*4 + i - 4));
        if (m >= M) continue;
        float bm = (mode == 3) ? bias[m] : 0.f;
        #pragma unroll
        for (int j = 0; j < 8; j++) {
            int n = n0 + ((j < 4) ? (tx*4 + j) : (64 + tx*4 + j - 4));
            if (n < N) {
                float val = acc[i][j];
                if (mode == 1) {
                    val += R[(size_t)m*ldr + n];
                } else if (mode == 3) {
                    float v = val + bm;
                    val = (v > 20.f) ? v : log1pf(expf(v));
                }
                C[(size_t)m*ldc + n] = val;
            }
        }
    }
}

// ---------------- x_proj tall-skinny GEMM, split-K --------------------------
#define XP_BM 16
#define XP_BK 32
#define XP_BSROW 98

__global__ __launch_bounds__(256) void xproj_kernel(
    const float* __restrict__ u, const float* __restrict__ w, float* __restrict__ part)
{
    __shared__ float As[XP_BK][XP_BM+1];
    __shared__ float Bs[XP_BK][XP_BSROW];

    int tid  = threadIdx.x;
    int m0   = blockIdx.x * XP_BM;
    int kc   = blockIdx.y;
    int kbeg = kc * (DINNER/XP_KSPLIT);
    int kend = kbeg + (DINNER/XP_KSPLIT);
    int r    = tid >> 4;
    int cg   = tid & 15;

    ull acc[2][3];
    #pragma unroll
    for (int p = 0; p < 2; p++)
        #pragma unroll
        for (int j = 0; j < 3; j++) acc[p][j] = 0ull;

    for (int k0 = kbeg; k0 < kend; k0 += XP_BK) {
        #pragma unroll
        for (int e = tid; e < XP_BM*XP_BK; e += 256) {
            int k = e & 31, m = e >> 5;
            As[k][m] = u[(size_t)(m0+m)*DINNER + k0 + k];
        }
        #pragma unroll
        for (int e = tid; e < XPROJ_OUT*XP_BK; e += 256) {
            int k = e & 31, n = e >> 5;
            Bs[k][n] = w[(size_t)n*DINNER + k0 + k];
        }
        __syncthreads();
        #pragma unroll
        for (int kk = 0; kk < XP_BK; kk += 2) {
            ull a0 = pack_dup(As[kk  ][r]);
            ull a1 = pack_dup(As[kk+1][r]);
            const ull* b0 = reinterpret_cast<const ull*>(&Bs[kk  ][cg*6]);
            const ull* b1 = reinterpret_cast<const ull*>(&Bs[kk+1][cg*6]);
            ffma2(acc[0][0], a0, b0[0]);
            ffma2(acc[0][1], a0, b0[1]);
            ffma2(acc[0][2], a0, b0[2]);
            ffma2(acc[1][0], a1, b1[0]);
            ffma2(acc[1][1], a1, b1[1]);
            ffma2(acc[1][2], a1, b1[2]);
        }
        __syncthreads();
    }

    float* o = part + (size_t)kc*ROWS*XPROJ_OUT + (size_t)(m0 + r)*XPROJ_OUT + cg*6;
    #pragma unroll
    for (int j = 0; j < 3; j++) {
        float2 v0 = unpack2(acc[0][j]);
        float2 v1 = unpack2(acc[1][j]);
        v0.x += v1.x; v0.y += v1.y;
        *reinterpret_cast<float2*>(o + 2*j) = v0;
    }
}

__global__ void xpart_reduce(const float* __restrict__ part, float* __restrict__ xdbl)
{
    int i = blockIdx.x*blockDim.x + threadIdx.x;
    if (i >= ROWS*XPROJ_OUT) return;
    const int S = ROWS*XPROJ_OUT;
    xdbl[i] = (part[i] + part[i+S]) + (part[i+2*S] + part[i+3*S]);
}

// ---------------- causal conv1d + SiLU, coalesced u and u^T -----------------
// 32x32 (row x d) tiles, smem transpose for uT.
__global__ __launch_bounds__(256) void conv_silu_kernel(
    const float* __restrict__ xz, const float* __restrict__ w,
    const float* __restrict__ bias, float* __restrict__ u, float* __restrict__ uT)
{
    __shared__ float s[32][33];
    int tid  = threadIdx.x;
    int ld   = tid & 31;     // d offset
    int lr   = tid >> 5;     // 0..7
    int d0   = blockIdx.x * 32;
    int row0 = blockIdx.y * 32;
    int d    = d0 + ld;

    float w0 = w[d*DCONV+0], w1 = w[d*DCONV+1], w2 = w[d*DCONV+2], w3 = w[d*DCONV+3];
    float bs = bias[d];

    #pragma unroll
    for (int i = 0; i < 4; i++) {
        int row = row0 + lr + 8*i;
        int l   = row % SEQ;
        const float* base = xz + (size_t)row*(2*DINNER) + d;
        float acc = bs + base[0] * w3;
        if (l >= 1) acc += base[-(ptrdiff_t)(2*DINNER)]   * w2;
        if (l >= 2) acc += base[-(ptrdiff_t)(4*DINNER)]   * w1;
        if (l >= 3) acc += base[-(ptrdiff_t)(6*DINNER)]   * w0;
        float sig = 1.f / (1.f + expf(-acc));
        float val = acc * sig;
        u[(size_t)row*DINNER + d] = val;
        s[ld][lr + 8*i] = val;
    }
    __syncthreads();
    // transposed write: warp lr handles d-indices lr, lr+8, lr+16, lr+24
    #pragma unroll
    for (int i = 0; i < 4; i++) {
        int wd = lr + 8*i;
        uT[(size_t)(d0 + wd)*ROWS + row0 + ld] = s[wd][ld];
    }
}

// ---------------- selective scan: writes split bf16 yg2 directly ------------
__global__ __launch_bounds__(256) void scan_kernel(
    const float* __restrict__ deltaT, const float* __restrict__ uT,
    const float* __restrict__ xdbl, const float* __restrict__ xz,
    const float* __restrict__ A_log, const float* __restrict__ Dskip,
    __nv_bfloat16* __restrict__ yg2)
{
    int warp = threadIdx.x >> 5;
    int lane = threadIdx.x & 31;
    int half = lane >> 4;
    int n    = lane & 15;
    int c    = blockIdx.x*16 + warp*2 + half;
    int b    = c / DINNER;
    int d    = c % DINNER;

    float A  = -expf(A_log[d*DSTATE + n]);
    float Dd = Dskip[d];
    float h  = 0.f;

    const float* drow = deltaT + (size_t)d*ROWS + b*SEQ;
    const float* urow = uT     + (size_t)d*ROWS + b*SEQ;
    const float* xrow = xdbl   + (size_t)b*SEQ*XPROJ_OUT;
    const float* zp   = xz     + (size_t)b*SEQ*(2*DINNER) + DINNER + d;

    const size_t ZS = 2*DINNER;
    float z0 = zp[0];
    float z1 = zp[ZS];

    for (int t = 0; t < SEQ; t++) {
        float z2 = (t+2 < SEQ) ? zp[(size_t)(t+2)*ZS] : 0.f;
        float dt = drow[t];
        float ut = urow[t];
        float Bn = xrow[t*XPROJ_OUT + DTRANK + n];
        float Cn = xrow[t*XPROJ_OUT + DTRANK + DSTATE + n];
        float dA = expf(dt * A);
        h = fmaf(dA, h, dt*ut*Bn);
        float p = h * Cn;
        p += __shfl_xor_sync(0xffffffffu, p, 8);
        p += __shfl_xor_sync(0xffffffffu, p, 4);
        p += __shfl_xor_sync(0xffffffffu, p, 2);
        p += __shfl_xor_sync(0xffffffffu, p, 1);
        if (n == 0) {
            float sg  = z0 / (1.f + expf(-z0));
            float val = fmaf(ut, Dd, p) * sg;
            __nv_bfloat16 hi = __float2bfloat16(val);
            __nv_bfloat16 lo = __float2bfloat16(val - __bfloat162float(hi));
            size_t base = (size_t)(b*SEQ + t)*3*DINNER;
            yg2[base + d]            = hi;
            yg2[base + DINNER + d]   = lo;
            yg2[base + 2*DINNER + d] = hi;
        }
        z0 = z1; z1 = z2;
    }
}

// ---------------- launch ----------------------------------------------------
extern "C" void kernel_launch(void* const* d_in, const int* in_sizes, int n_in,
                              void* d_out, int out_size)
{
    const float* x      = (const float*)d_in[0];
    const float* ln_g   = (const float*)d_in[1];
    const float* ln_b   = (const float*)d_in[2];
    const float* w_in   = (const float*)d_in[3];
    const float* conv_w = (const float*)d_in[4];
    const float* conv_b = (const float*)d_in[5];
    const float* w_x    = (const float*)d_in[6];
    const float* w_dt   = (const float*)d_in[7];
    const float* b_dt   = (const float*)d_in[8];
    const float* A_log  = (const float*)d_in[9];
    const float* Dsk    = (const float*)d_in[10];
    const float* w_out  = (const float*)d_in[11];
    float* out = (float*)d_out;

    float *xz, *u, *uT, *xdbl, *xpart, *deltaT;
    __nv_bfloat16 *xn2, *win2, *yg2, *wout2;
    cudaGetSymbolAddress((void**)&xz,     g_xz);
    cudaGetSymbolAddress((void**)&u,      g_u);
    cudaGetSymbolAddress((void**)&uT,     g_uT);
    cudaGetSymbolAddress((void**)&xdbl,   g_xdbl);
    cudaGetSymbolAddress((void**)&xpart,  g_xpart);
    cudaGetSymbolAddress((void**)&deltaT, g_deltaT);
    cudaGetSymbolAddress((void**)&xn2,    g_xn2);
    cudaGetSymbolAddress((void**)&win2,   g_win2);
    cudaGetSymbolAddress((void**)&yg2,    g_yg2);
    cudaGetSymbolAddress((void**)&wout2,  g_wout2);

    // 1. layernorm -> xn2 (split bf16)
    ln_kernel<<<ROWS, 256>>>(x, ln_g, ln_b, xn2);

    // 2. in_proj on tensor cores: split w_in, then bf16 GEMM K3=3072
    split_kernel<<<(2*DINNER*DMODEL+255)/256, 256>>>(w_in, win2, DMODEL, 2*DINNER*DMODEL);
    {
        dim3 g(2*DINNER/WBN, ROWS/WBM);
        wmma_nt<<<g, 256>>>(xn2, win2, xz, 2*DINNER, nullptr, 0,
                            ROWS, 2*DINNER, 3*DMODEL, 0);
    }

    // 3. causal depthwise conv + SiLU -> u, u^T (coalesced)
    {
        dim3 g(DINNER/32, ROWS/32);
        conv_silu_kernel<<<g, 256>>>(xz, conv_w, conv_b, u, uT);
    }

    // 4. x_proj (split-K): xdbl[2048,96] = u @ w_x[96,2048]^T
    {
        dim3 g(ROWS/XP_BM, XP_KSPLIT);
        xproj_kernel<<<g, 256>>>(u, w_x, xpart);
        xpart_reduce<<<(ROWS*XPROJ_OUT+255)/256, 256>>>(xpart, xdbl);
    }

    // 5. dt_proj TRANSPOSED + fused softplus
    {
        dim3 g(ROWS/BN, DINNER/BM);
        sgemm_nt<<<g, 256>>>(w_dt, DTRANK, xdbl, XPROJ_OUT, deltaT, ROWS,
                             nullptr, 0, b_dt, DINNER, ROWS, DTRANK, 3);
    }

    // 6. selective scan -> yg2 (split bf16, gate fused)
    scan_kernel<<<(BATCH*DINNER)/16, 256>>>(deltaT, uT, xdbl, xz, A_log, Dsk, yg2);

    // 7. out_proj on tensor cores + residual: K3=6144
    split_kernel<<<(DMODEL*DINNER+255)/256, 256>>>(w_out, wout2, DINNER, DMODEL*DINNER);
    {
        dim3 g(DMODEL/WBN, ROWS/WBM);
        wmma_nt<<<g, 256>>>(yg2, wout2, out, DMODEL, x, DMODEL,
                            ROWS, DMODEL, 3*DINNER, 1);
    }
}

// round 8
// speedup vs baseline: 2.4524x; 1.0289x over previous
#include <cuda_runtime.h>
#include <cuda_bf16.h>
#include <mma.h>
#include <math.h>

using namespace nvcuda;

#define BATCH   2
#define SEQ     1024
#define DMODEL  1024
#define DINNER  2048
#define DTRANK  64
#define DSTATE  16
#define DCONV   4
#define ROWS    (BATCH*SEQ)            // 2048
#define XPROJ_OUT (DTRANK + 2*DSTATE)  // 96

typedef unsigned long long ull;

__device__ __forceinline__ void ffma2(ull &d, ull a, ull b) {
    asm("fma.rn.f32x2 %0, %1, %2, %0;" : "+l"(d) : "l"(a), "l"(b));
}
__device__ __forceinline__ ull pack_dup(float x) {
    ull r; asm("mov.b64 %0, {%1, %1};" : "=l"(r) : "f"(x)); return r;
}
__device__ __forceinline__ float2 unpack2(ull v) {
    float2 f; asm("mov.b64 {%0, %1}, %2;" : "=f"(f.x), "=f"(f.y) : "l"(v)); return f;
}
__device__ __forceinline__ void cp_async16(void* smem, const void* gmem) {
    unsigned s = (unsigned)__cvta_generic_to_shared(smem);
    asm volatile("cp.async.cg.shared.global [%0], [%1], 16;" :: "r"(s), "l"(gmem));
}
#define CP_COMMIT()  asm volatile("cp.async.commit_group;")
#define CP_WAITG(n)  asm volatile("cp.async.wait_group %0;" :: "n"(n))

// ---------------- scratch (static device globals; no allocation) ------------
#define XP_KSPLIT 4
__device__ float g_xz    [ROWS*2*DINNER];
__device__ float g_u     [ROWS*DINNER];
__device__ float g_uT    [DINNER*ROWS];
__device__ float g_xdbl  [ROWS*XPROJ_OUT];
__device__ float g_xpart [XP_KSPLIT*ROWS*XPROJ_OUT];
__device__ float g_deltaT[DINNER*ROWS];
__device__ __nv_bfloat16 g_xn2  [ROWS*3*DMODEL];
__device__ __nv_bfloat16 g_win2 [2*DINNER*3*DMODEL];
__device__ __nv_bfloat16 g_yg2  [ROWS*3*DINNER];
__device__ __nv_bfloat16 g_wout2[DMODEL*3*DINNER];

// ---------------- split fp32 -> bf16 hi/lo (weights: [hi|hi|lo]) ------------
__global__ void split_kernel(const float* __restrict__ X, __nv_bfloat16* __restrict__ Y,
                             int K, int total)
{
    int i = blockIdx.x*blockDim.x + threadIdx.x;
    if (i >= total) return;
    int m = i / K, k = i % K;
    float x = X[i];
    __nv_bfloat16 hi = __float2bfloat16(x);
    __nv_bfloat16 lo = __float2bfloat16(x - __bfloat162float(hi));
    __nv_bfloat16* row = Y + (size_t)m*3*K;
    row[k] = hi; row[K+k] = hi; row[2*K+k] = lo;
}

// ---------------- wmma bf16 GEMM NT, 3-stage cp.async pipeline --------------
// C[M,N] = A2[M,K3] @ B2[N,K3]^T; mode: 0 plain, 1 += R
#define WBM 128
#define WBN 128
#define WBK 32
#define WPITCH 40       // bf16 pitch: 80 bytes
#define NSTAGE 3
#define WMMA_SMEM (NSTAGE * 2 * WBM * WPITCH * 2)   // 61440 bytes

__global__ __launch_bounds__(256) void wmma_nt(
    const __nv_bfloat16* __restrict__ A2, const __nv_bfloat16* __restrict__ B2,
    float* __restrict__ C, int ldc, const float* __restrict__ R, int ldr,
    int M, int N, int K3, int mode)
{
    extern __shared__ __align__(16) __nv_bfloat16 sm[];
    __nv_bfloat16* Asm = sm;                              // NSTAGE x (WBM*WPITCH)
    __nv_bfloat16* Bsm = sm + NSTAGE*WBM*WPITCH;

    int tid = threadIdx.x;
    int w   = tid >> 5;
    int wm  = w >> 2;          // 0..1
    int wn  = w & 3;           // 0..3
    int m0  = blockIdx.y * WBM;
    int n0  = blockIdx.x * WBN;

    wmma::fragment<wmma::accumulator, 16,16,16, float> acc[4][2];
    #pragma unroll
    for (int i = 0; i < 4; i++)
        #pragma unroll
        for (int j = 0; j < 2; j++) wmma::fill_fragment(acc[i][j], 0.f);

    auto stage = [&](int s, int k0) {
        __nv_bfloat16* As = Asm + s*WBM*WPITCH;
        __nv_bfloat16* Bs = Bsm + s*WBM*WPITCH;
        #pragma unroll
        for (int e = tid; e < WBM*4; e += 256) {
            int row = e >> 2, q = e & 3;
            cp_async16(&As[row*WPITCH + q*8], A2 + (size_t)(m0+row)*K3 + k0 + q*8);
        }
        #pragma unroll
        for (int e = tid; e < WBN*4; e += 256) {
            int row = e >> 2, q = e & 3;
            cp_async16(&Bs[row*WPITCH + q*8], B2 + (size_t)(n0+row)*K3 + k0 + q*8);
        }
        CP_COMMIT();
    };

    int NT = K3 / WBK;
    stage(0, 0);
    if (NT > 1) stage(1, WBK);

    for (int kt = 0; kt < NT; kt++) {
        __syncthreads();   // all warps done with the buffer about to be restaged
        if (kt + 2 < NT)      { stage((kt+2)%NSTAGE, (kt+2)*WBK); CP_WAITG(2); }
        else if (kt + 1 < NT) { CP_WAITG(1); }
        else                  { CP_WAITG(0); }
        __syncthreads();   // staged data visible to all warps

        const __nv_bfloat16* As = Asm + (kt%NSTAGE)*WBM*WPITCH;
        const __nv_bfloat16* Bs = Bsm + (kt%NSTAGE)*WBM*WPITCH;
        #pragma unroll
        for (int ks = 0; ks < WBK; ks += 16) {
            wmma::fragment<wmma::matrix_a, 16,16,16, __nv_bfloat16, wmma::row_major> af[4];
            wmma::fragment<wmma::matrix_b, 16,16,16, __nv_bfloat16, wmma::col_major> bf[2];
            #pragma unroll
            for (int i = 0; i < 4; i++)
                wmma::load_matrix_sync(af[i], &As[(wm*64 + i*16)*WPITCH + ks], WPITCH);
            #pragma unroll
            for (int j = 0; j < 2; j++)
                wmma::load_matrix_sync(bf[j], &Bs[(wn*32 + j*16)*WPITCH + ks], WPITCH);
            #pragma unroll
            for (int i = 0; i < 4; i++)
                #pragma unroll
                for (int j = 0; j < 2; j++)
                    wmma::mma_sync(acc[i][j], af[i], bf[j], acc[i][j]);
        }
    }

    #pragma unroll
    for (int i = 0; i < 4; i++) {
        int m = m0 + wm*64 + i*16;
        #pragma unroll
        for (int j = 0; j < 2; j++) {
            int n = n0 + wn*32 + j*16;
            if (mode == 1) {
                wmma::fragment<wmma::accumulator, 16,16,16, float> rf;
                wmma::load_matrix_sync(rf, R + (size_t)m*ldr + n, ldr, wmma::mem_row_major);
                #pragma unroll
                for (int t = 0; t < acc[i][j].num_elements; t++)
                    acc[i][j].x[t] += rf.x[t];
            }
            wmma::store_matrix_sync(C + (size_t)m*ldc + n, acc[i][j], ldc, wmma::mem_row_major);
        }
    }
}

// ---------------- LayerNorm -> split bf16 [hi|lo|hi] directly ---------------
__global__ void ln_kernel(const float* __restrict__ x, const float* __restrict__ g,
                          const float* __restrict__ b, __nv_bfloat16* __restrict__ xn2)
{
    int row = blockIdx.x;
    int tid = threadIdx.x;
    const float* xr = x + (size_t)row*DMODEL;
    float v[4];
    float s1 = 0.f, s2 = 0.f;
    #pragma unroll
    for (int i = 0; i < 4; i++) {
        v[i] = xr[tid + 256*i];
        s1 += v[i];
        s2 += v[i]*v[i];
    }
    __shared__ float sh1[8], sh2[8];
    #pragma unroll
    for (int o = 16; o; o >>= 1) {
        s1 += __shfl_xor_sync(0xffffffffu, s1, o);
        s2 += __shfl_xor_sync(0xffffffffu, s2, o);
    }
    if ((tid & 31) == 0) { sh1[tid>>5] = s1; sh2[tid>>5] = s2; }
    __syncthreads();
    if (tid < 32) {
        float a = (tid < 8) ? sh1[tid] : 0.f;
        float c = (tid < 8) ? sh2[tid] : 0.f;
        #pragma unroll
        for (int o = 4; o; o >>= 1) {
            a += __shfl_xor_sync(0xffffffffu, a, o);
            c += __shfl_xor_sync(0xffffffffu, c, o);
        }
        if (tid == 0) { sh1[0] = a; sh2[0] = c; }
    }
    __syncthreads();
    float mu  = sh1[0] * (1.f/DMODEL);
    float var = sh2[0] * (1.f/DMODEL) - mu*mu;
    float r   = rsqrtf(var + 1e-5f);
    __nv_bfloat16* o = xn2 + (size_t)row*3*DMODEL;
    #pragma unroll
    for (int i = 0; i < 4; i++) {
        int c = tid + 256*i;
        float val = (v[i]-mu)*r*g[c] + b[c];
        __nv_bfloat16 hi = __float2bfloat16(val);
        __nv_bfloat16 lo = __float2bfloat16(val - __bfloat162float(hi));
        o[c] = hi; o[DMODEL+c] = lo; o[2*DMODEL+c] = hi;
    }
}

// ---------------- SGEMM NT (scalar FFMA) — dt_proj --------------------------
//   0: plain store, 1: += R, 3: softplus(v + bias[m])
#define BM 128
#define BN 128
#define BKT 8

__global__ __launch_bounds__(256) void sgemm_nt(
    const float* __restrict__ A, int lda,
    const float* __restrict__ B, int ldb,
    float* __restrict__ C, int ldc,
    const float* __restrict__ R, int ldr,
    const float* __restrict__ bias,
    int M, int N, int K, int mode)
{
    __shared__ float As[BKT][BM+4];
    __shared__ float Bs[BKT][BN+4];

    int tid = threadIdx.x;
    int tx  = tid & 15;
    int ty  = tid >> 4;
    int m0  = blockIdx.y * BM;
    int n0  = blockIdx.x * BN;

    int lrow = tid >> 1;
    int lk4  = (tid & 1) * 4;

    float acc[8][8];
    #pragma unroll
    for (int i = 0; i < 8; i++)
        #pragma unroll
        for (int j = 0; j < 8; j++) acc[i][j] = 0.f;

    for (int k0 = 0; k0 < K; k0 += BKT) {
        float4 a = make_float4(0.f,0.f,0.f,0.f);
        int am = m0 + lrow;
        if (am < M) a = *reinterpret_cast<const float4*>(A + (size_t)am*lda + k0 + lk4);
        As[lk4+0][lrow] = a.x; As[lk4+1][lrow] = a.y;
        As[lk4+2][lrow] = a.z; As[lk4+3][lrow] = a.w;

        float4 bv = make_float4(0.f,0.f,0.f,0.f);
        int bn = n0 + lrow;
        if (bn < N) bv = *reinterpret_cast<const float4*>(B + (size_t)bn*ldb + k0 + lk4);
        Bs[lk4+0][lrow] = bv.x; Bs[lk4+1][lrow] = bv.y;
        Bs[lk4+2][lrow] = bv.z; Bs[lk4+3][lrow] = bv.w;

        __syncthreads();

        #pragma unroll
        for (int kk = 0; kk < BKT; kk++) {
            float ra[8], rb[8];
            #pragma unroll
            for (int i = 0; i < 4; i++) {
                ra[i]   = As[kk][ty*4 + i];
                ra[i+4] = As[kk][64 + ty*4 + i];
                rb[i]   = Bs[kk][tx*4 + i];
                rb[i+4] = Bs[kk][64 + tx*4 + i];
            }
            #pragma unroll
            for (int i = 0; i < 8; i++)
                #pragma unroll
                for (int j = 0; j < 8; j++)
                    acc[i][j] = fmaf(ra[i], rb[j], acc[i][j]);
        }
        __syncthreads();
    }

    #pragma unroll
    for (int i = 0; i < 8; i++) {
        int m = m0 + ((i < 4) ? (ty*4 + i) : (64 + ty*4 + i - 4));
        if (m >= M) continue;
        float bm = (mode == 3) ? bias[m] : 0.f;
        #pragma unroll
        for (int j = 0; j < 8; j++) {
            int n = n0 + ((j < 4) ? (tx*4 + j) : (64 + tx*4 + j - 4));
            if (n < N) {
                float val = acc[i][j];
                if (mode == 1) {
                    val += R[(size_t)m*ldr + n];
                } else if (mode == 3) {
                    float v = val + bm;
                    val = (v > 20.f) ? v : __logf(1.f + __expf(v));
                }
                C[(size_t)m*ldc + n] = val;
            }
        }
    }
}

// ---------------- x_proj tall-skinny GEMM, split-K --------------------------
#define XP_BM 16
#define XP_BK 32
#define XP_BSROW 98

__global__ __launch_bounds__(256) void xproj_kernel(
    const float* __restrict__ u, const float* __restrict__ w, float* __restrict__ part)
{
    __shared__ float As[XP_BK][XP_BM+1];
    __shared__ float Bs[XP_BK][XP_BSROW];

    int tid  = threadIdx.x;
    int m0   = blockIdx.x * XP_BM;
    int kc   = blockIdx.y;
    int kbeg = kc * (DINNER/XP_KSPLIT);
    int kend = kbeg + (DINNER/XP_KSPLIT);
    int r    = tid >> 4;
    int cg   = tid & 15;

    ull acc[2][3];
    #pragma unroll
    for (int p = 0; p < 2; p++)
        #pragma unroll
        for (int j = 0; j < 3; j++) acc[p][j] = 0ull;

    for (int k0 = kbeg; k0 < kend; k0 += XP_BK) {
        #pragma unroll
        for (int e = tid; e < XP_BM*XP_BK; e += 256) {
            int k = e & 31, m = e >> 5;
            As[k][m] = u[(size_t)(m0+m)*DINNER + k0 + k];
        }
        #pragma unroll
        for (int e = tid; e < XPROJ_OUT*XP_BK; e += 256) {
            int k = e & 31, n = e >> 5;
            Bs[k][n] = w[(size_t)n*DINNER + k0 + k];
        }
        __syncthreads();
        #pragma unroll
        for (int kk = 0; kk < XP_BK; kk += 2) {
            ull a0 = pack_dup(As[kk  ][r]);
            ull a1 = pack_dup(As[kk+1][r]);
            const ull* b0 = reinterpret_cast<const ull*>(&Bs[kk  ][cg*6]);
            const ull* b1 = reinterpret_cast<const ull*>(&Bs[kk+1][cg*6]);
            ffma2(acc[0][0], a0, b0[0]);
            ffma2(acc[0][1], a0, b0[1]);
            ffma2(acc[0][2], a0, b0[2]);
            ffma2(acc[1][0], a1, b1[0]);
            ffma2(acc[1][1], a1, b1[1]);
            ffma2(acc[1][2], a1, b1[2]);
        }
        __syncthreads();
    }

    float* o = part + (size_t)kc*ROWS*XPROJ_OUT + (size_t)(m0 + r)*XPROJ_OUT + cg*6;
    #pragma unroll
    for (int j = 0; j < 3; j++) {
        float2 v0 = unpack2(acc[0][j]);
        float2 v1 = unpack2(acc[1][j]);
        v0.x += v1.x; v0.y += v1.y;
        *reinterpret_cast<float2*>(o + 2*j) = v0;
    }
}

__global__ void xpart_reduce(const float* __restrict__ part, float* __restrict__ xdbl)
{
    int i = blockIdx.x*blockDim.x + threadIdx.x;
    if (i >= ROWS*XPROJ_OUT) return;
    const int S = ROWS*XPROJ_OUT;
    xdbl[i] = (part[i] + part[i+S]) + (part[i+2*S] + part[i+3*S]);
}

// ---------------- causal conv1d + SiLU, coalesced u and u^T -----------------
__global__ __launch_bounds__(256) void conv_silu_kernel(
    const float* __restrict__ xz, const float* __restrict__ w,
    const float* __restrict__ bias, float* __restrict__ u, float* __restrict__ uT)
{
    __shared__ float s[32][33];
    int tid  = threadIdx.x;
    int ld   = tid & 31;
    int lr   = tid >> 5;
    int d0   = blockIdx.x * 32;
    int row0 = blockIdx.y * 32;
    int d    = d0 + ld;

    float w0 = w[d*DCONV+0], w1 = w[d*DCONV+1], w2 = w[d*DCONV+2], w3 = w[d*DCONV+3];
    float bs = bias[d];

    #pragma unroll
    for (int i = 0; i < 4; i++) {
        int row = row0 + lr + 8*i;
        int l   = row % SEQ;
        const float* base = xz + (size_t)row*(2*DINNER) + d;
        float acc = bs + base[0] * w3;
        if (l >= 1) acc += base[-(ptrdiff_t)(2*DINNER)]   * w2;
        if (l >= 2) acc += base[-(ptrdiff_t)(4*DINNER)]   * w1;
        if (l >= 3) acc += base[-(ptrdiff_t)(6*DINNER)]   * w0;
        float sig = 1.f / (1.f + __expf(-acc));
        float val = acc * sig;
        u[(size_t)row*DINNER + d] = val;
        s[ld][lr + 8*i] = val;
    }
    __syncthreads();
    #pragma unroll
    for (int i = 0; i < 4; i++) {
        int wd = lr + 8*i;
        uT[(size_t)(d0 + wd)*ROWS + row0 + ld] = s[wd][ld];
    }
}

// ---------------- selective scan: fast exp, split bf16 yg2 out --------------
__global__ __launch_bounds__(256) void scan_kernel(
    const float* __restrict__ deltaT, const float* __restrict__ uT,
    const float* __restrict__ xdbl, const float* __restrict__ xz,
    const float* __restrict__ A_log, const float* __restrict__ Dskip,
    __nv_bfloat16* __restrict__ yg2)
{
    int warp = threadIdx.x >> 5;
    int lane = threadIdx.x & 31;
    int half = lane >> 4;
    int n    = lane & 15;
    int c    = blockIdx.x*16 + warp*2 + half;
    int b    = c / DINNER;
    int d    = c % DINNER;

    float A  = -__expf(A_log[d*DSTATE + n]);
    float Dd = Dskip[d];
    float h  = 0.f;

    const float* drow = deltaT + (size_t)d*ROWS + b*SEQ;
    const float* urow = uT     + (size_t)d*ROWS + b*SEQ;
    const float* xrow = xdbl   + (size_t)b*SEQ*XPROJ_OUT;
    const float* zp   = xz     + (size_t)b*SEQ*(2*DINNER) + DINNER + d;

    const size_t ZS = 2*DINNER;
    float z0 = zp[0];
    float z1 = zp[ZS];

    for (int t = 0; t < SEQ; t++) {
        float z2 = (t+2 < SEQ) ? zp[(size_t)(t+2)*ZS] : 0.f;
        float dt = drow[t];
        float ut = urow[t];
        float Bn = xrow[t*XPROJ_OUT + DTRANK + n];
        float Cn = xrow[t*XPROJ_OUT + DTRANK + DSTATE + n];
        float dA = __expf(dt * A);
        h = fmaf(dA, h, dt*ut*Bn);
        float p = h * Cn;
        p += __shfl_xor_sync(0xffffffffu, p, 8);
        p += __shfl_xor_sync(0xffffffffu, p, 4);
        p += __shfl_xor_sync(0xffffffffu, p, 2);
        p += __shfl_xor_sync(0xffffffffu, p, 1);
        if (n == 0) {
            float sg  = z0 / (1.f + __expf(-z0));
            float val = fmaf(ut, Dd, p) * sg;
            __nv_bfloat16 hi = __float2bfloat16(val);
            __nv_bfloat16 lo = __float2bfloat16(val - __bfloat162float(hi));
            size_t base = (size_t)(b*SEQ + t)*3*DINNER;
            yg2[base + d]            = hi;
            yg2[base + DINNER + d]   = lo;
            yg2[base + 2*DINNER + d] = hi;
        }
        z0 = z1; z1 = z2;
    }
}

// ---------------- launch ----------------------------------------------------
extern "C" void kernel_launch(void* const* d_in, const int* in_sizes, int n_in,
                              void* d_out, int out_size)
{
    const float* x      = (const float*)d_in[0];
    const float* ln_g   = (const float*)d_in[1];
    const float* ln_b   = (const float*)d_in[2];
    const float* w_in   = (const float*)d_in[3];
    const float* conv_w = (const float*)d_in[4];
    const float* conv_b = (const float*)d_in[5];
    const float* w_x    = (const float*)d_in[6];
    const float* w_dt   = (const float*)d_in[7];
    const float* b_dt   = (const float*)d_in[8];
    const float* A_log  = (const float*)d_in[9];
    const float* Dsk    = (const float*)d_in[10];
    const float* w_out  = (const float*)d_in[11];
    float* out = (float*)d_out;

    float *xz, *u, *uT, *xdbl, *xpart, *deltaT;
    __nv_bfloat16 *xn2, *win2, *yg2, *wout2;
    cudaGetSymbolAddress((void**)&xz,     g_xz);
    cudaGetSymbolAddress((void**)&u,      g_u);
    cudaGetSymbolAddress((void**)&uT,     g_uT);
    cudaGetSymbolAddress((void**)&xdbl,   g_xdbl);
    cudaGetSymbolAddress((void**)&xpart,  g_xpart);
    cudaGetSymbolAddress((void**)&deltaT, g_deltaT);
    cudaGetSymbolAddress((void**)&xn2,    g_xn2);
    cudaGetSymbolAddress((void**)&win2,   g_win2);
    cudaGetSymbolAddress((void**)&yg2,    g_yg2);
    cudaGetSymbolAddress((void**)&wout2,  g_wout2);

    static int smem_set = 0;
    if (!smem_set) {
        cudaFuncSetAttribute(wmma_nt, cudaFuncAttributeMaxDynamicSharedMemorySize, WMMA_SMEM);
        smem_set = 1;
    }

    // 1. layernorm -> xn2 (split bf16)
    ln_kernel<<<ROWS, 256>>>(x, ln_g, ln_b, xn2);

    // 2. in_proj on tensor cores: split w_in, then bf16 GEMM K3=3072
    split_kernel<<<(2*DINNER*DMODEL+255)/256, 256>>>(w_in, win2, DMODEL, 2*DINNER*DMODEL);
    {
        dim3 g(2*DINNER/WBN, ROWS/WBM);
        wmma_nt<<<g, 256, WMMA_SMEM>>>(xn2, win2, xz, 2*DINNER, nullptr, 0,
                                       ROWS, 2*DINNER, 3*DMODEL, 0);
    }

    // 3. causal depthwise conv + SiLU -> u, u^T (coalesced)
    {
        dim3 g(DINNER/32, ROWS/32);
        conv_silu_kernel<<<g, 256>>>(xz, conv_w, conv_b, u, uT);
    }

    // 4. x_proj (split-K): xdbl[2048,96] = u @ w_x[96,2048]^T
    {
        dim3 g(ROWS/XP_BM, XP_KSPLIT);
        xproj_kernel<<<g, 256>>>(u, w_x, xpart);
        xpart_reduce<<<(ROWS*XPROJ_OUT+255)/256, 256>>>(xpart, xdbl);
    }

    // 5. dt_proj TRANSPOSED + fused softplus
    {
        dim3 g(ROWS/BN, DINNER/BM);
        sgemm_nt<<<g, 256>>>(w_dt, DTRANK, xdbl, XPROJ_OUT, deltaT, ROWS,
                             nullptr, 0, b_dt, DINNER, ROWS, DTRANK, 3);
    }

    // 6. selective scan -> yg2 (split bf16, gate fused)
    scan_kernel<<<(BATCH*DINNER)/16, 256>>>(deltaT, uT, xdbl, xz, A_log, Dsk, yg2);

    // 7. out_proj on tensor cores + residual: K3=6144
    split_kernel<<<(DMODEL*DINNER+255)/256, 256>>>(w_out, wout2, DINNER, DMODEL*DINNER);
    {
        dim3 g(DMODEL/WBN, ROWS/WBM);
        wmma_nt<<<g, 256, WMMA_SMEM>>>(yg2, wout2, out, DMODEL, x, DMODEL,
                                       ROWS, DMODEL, 3*DINNER, 1);
    }
}

// round 9
// speedup vs baseline: 2.4768x; 1.0099x over previous
#include <cuda_runtime.h>
#include <cuda_bf16.h>
#include <mma.h>
#include <math.h>

using namespace nvcuda;

#define BATCH   2
#define SEQ     1024
#define DMODEL  1024
#define DINNER  2048
#define DTRANK  64
#define DSTATE  16
#define DCONV   4
#define ROWS    (BATCH*SEQ)            // 2048
#define XPROJ_OUT (DTRANK + 2*DSTATE)  // 96

typedef unsigned long long ull;

__device__ __forceinline__ void ffma2(ull &d, ull a, ull b) {
    asm("fma.rn.f32x2 %0, %1, %2, %0;" : "+l"(d) : "l"(a), "l"(b));
}
__device__ __forceinline__ ull pack_dup(float x) {
    ull r; asm("mov.b64 %0, {%1, %1};" : "=l"(r) : "f"(x)); return r;
}
__device__ __forceinline__ float2 unpack2(ull v) {
    float2 f; asm("mov.b64 {%0, %1}, %2;" : "=f"(f.x), "=f"(f.y) : "l"(v)); return f;
}
__device__ __forceinline__ void cp_async16(void* smem, const void* gmem) {
    unsigned s = (unsigned)__cvta_generic_to_shared(smem);
    asm volatile("cp.async.cg.shared.global [%0], [%1], 16;" :: "r"(s), "l"(gmem));
}
#define CP_COMMIT()  asm volatile("cp.async.commit_group;")
#define CP_WAITG(n)  asm volatile("cp.async.wait_group %0;" :: "n"(n))

// ---------------- scratch (static device globals; no allocation) ------------
#define XP_KSPLIT 4
__device__ float g_xz    [ROWS*2*DINNER];
__device__ float g_u     [ROWS*DINNER];
__device__ float g_uT    [DINNER*ROWS];
__device__ float g_xdbl  [ROWS*XPROJ_OUT];
__device__ float g_xpart [XP_KSPLIT*ROWS*XPROJ_OUT];
__device__ float g_deltaT[DINNER*ROWS];
__device__ __nv_bfloat16 g_xn2  [ROWS*3*DMODEL];
__device__ __nv_bfloat16 g_win2 [2*DINNER*3*DMODEL];
__device__ __nv_bfloat16 g_yg2  [ROWS*3*DINNER];
__device__ __nv_bfloat16 g_wout2[DMODEL*3*DINNER];

// ---------------- split fp32 -> bf16 hi/lo (weights: [hi|hi|lo]) ------------
__global__ void split_kernel(const float* __restrict__ X, __nv_bfloat16* __restrict__ Y,
                             int K, int total)
{
    int i = blockIdx.x*blockDim.x + threadIdx.x;
    if (i >= total) return;
    int m = i / K, k = i % K;
    float x = X[i];
    __nv_bfloat16 hi = __float2bfloat16(x);
    __nv_bfloat16 lo = __float2bfloat16(x - __bfloat162float(hi));
    __nv_bfloat16* row = Y + (size_t)m*3*K;
    row[k] = hi; row[K+k] = hi; row[2*K+k] = lo;
}

// ---------------- wmma bf16 GEMM NT, 4-stage cp.async pipeline --------------
// C[M,N] = A2[M,K3] @ B2[N,K3]^T; mode: 0 plain, 1 += R
// Block tile: 128 x (64*NFRAG). 8 warps as 2x4; warp tile 64 x (16*NFRAG).
#define WBM 128
#define WBK 32
#define WPITCH 40       // bf16 pitch: 80 bytes, conflict-free for ldmatrix
#define NSTAGE 4
#define ASZ (WBM*WPITCH)

template<int NFRAG>
__global__ __launch_bounds__(256) void wmma_nt(
    const __nv_bfloat16* __restrict__ A2, const __nv_bfloat16* __restrict__ B2,
    float* __restrict__ C, int ldc, const float* __restrict__ R, int ldr,
    int M, int N, int K3, int mode)
{
    constexpr int WBN = 64*NFRAG;
    constexpr int BSZ = WBN*WPITCH;

    extern __shared__ __align__(16) __nv_bfloat16 sm[];
    __nv_bfloat16* Asm = sm;
    __nv_bfloat16* Bsm = sm + NSTAGE*ASZ;

    int tid = threadIdx.x;
    int w   = tid >> 5;
    int wm  = w >> 2;          // 0..1
    int wn  = w & 3;           // 0..3
    int m0  = blockIdx.y * WBM;
    int n0  = blockIdx.x * WBN;

    wmma::fragment<wmma::accumulator, 16,16,16, float> acc[4][NFRAG];
    #pragma unroll
    for (int i = 0; i < 4; i++)
        #pragma unroll
        for (int j = 0; j < NFRAG; j++) wmma::fill_fragment(acc[i][j], 0.f);

    auto stage = [&](int s, int k0) {
        __nv_bfloat16* As = Asm + s*ASZ;
        __nv_bfloat16* Bs = Bsm + s*BSZ;
        #pragma unroll
        for (int e = tid; e < WBM*4; e += 256) {
            int row = e >> 2, q = e & 3;
            cp_async16(&As[row*WPITCH + q*8], A2 + (size_t)(m0+row)*K3 + k0 + q*8);
        }
        #pragma unroll
        for (int e = tid; e < WBN*4; e += 256) {
            int row = e >> 2, q = e & 3;
            cp_async16(&Bs[row*WPITCH + q*8], B2 + (size_t)(n0+row)*K3 + k0 + q*8);
        }
        CP_COMMIT();
    };

    int NT = K3 / WBK;
    stage(0, 0);
    stage(1, WBK);
    stage(2, 2*WBK);

    for (int kt = 0; kt < NT; kt++) {
        __syncthreads();   // all warps done with the buffer about to be restaged
        if (kt + 3 < NT)      { stage((kt+3)%NSTAGE, (kt+3)*WBK); CP_WAITG(3); }
        else if (kt + 3 == NT) { CP_WAITG(2); }
        else if (kt + 2 == NT) { CP_WAITG(1); }
        else                   { CP_WAITG(0); }
        __syncthreads();   // staged data visible to all warps

        const __nv_bfloat16* As = Asm + (kt%NSTAGE)*ASZ;
        const __nv_bfloat16* Bs = Bsm + (kt%NSTAGE)*BSZ;
        #pragma unroll
        for (int ks = 0; ks < WBK; ks += 16) {
            wmma::fragment<wmma::matrix_a, 16,16,16, __nv_bfloat16, wmma::row_major> af[4];
            wmma::fragment<wmma::matrix_b, 16,16,16, __nv_bfloat16, wmma::col_major> bf[NFRAG];
            #pragma unroll
            for (int i = 0; i < 4; i++)
                wmma::load_matrix_sync(af[i], &As[(wm*64 + i*16)*WPITCH + ks], WPITCH);
            #pragma unroll
            for (int j = 0; j < NFRAG; j++)
                wmma::load_matrix_sync(bf[j], &Bs[(wn*16*NFRAG + j*16)*WPITCH + ks], WPITCH);
            #pragma unroll
            for (int i = 0; i < 4; i++)
                #pragma unroll
                for (int j = 0; j < NFRAG; j++)
                    wmma::mma_sync(acc[i][j], af[i], bf[j], acc[i][j]);
        }
    }

    #pragma unroll
    for (int i = 0; i < 4; i++) {
        int m = m0 + wm*64 + i*16;
        #pragma unroll
        for (int j = 0; j < NFRAG; j++) {
            int n = n0 + wn*16*NFRAG + j*16;
            if (mode == 1) {
                wmma::fragment<wmma::accumulator, 16,16,16, float> rf;
                wmma::load_matrix_sync(rf, R + (size_t)m*ldr + n, ldr, wmma::mem_row_major);
                #pragma unroll
                for (int t = 0; t < acc[i][j].num_elements; t++)
                    acc[i][j].x[t] += rf.x[t];
            }
            wmma::store_matrix_sync(C + (size_t)m*ldc + n, acc[i][j], ldc, wmma::mem_row_major);
        }
    }
}

#define WMMA_SMEM_W (NSTAGE*(ASZ + 256*WPITCH)*2)   // NFRAG=4: 122880 B
#define WMMA_SMEM_N (NSTAGE*(ASZ + 128*WPITCH)*2)   // NFRAG=2: 81920 B

// ---------------- LayerNorm -> split bf16 [hi|lo|hi] directly ---------------
__global__ void ln_kernel(const float* __restrict__ x, const float* __restrict__ g,
                          const float* __restrict__ b, __nv_bfloat16* __restrict__ xn2)
{
    int row = blockIdx.x;
    int tid = threadIdx.x;
    const float* xr = x + (size_t)row*DMODEL;
    float v[4];
    float s1 = 0.f, s2 = 0.f;
    #pragma unroll
    for (int i = 0; i < 4; i++) {
        v[i] = xr[tid + 256*i];
        s1 += v[i];
        s2 += v[i]*v[i];
    }
    __shared__ float sh1[8], sh2[8];
    #pragma unroll
    for (int o = 16; o; o >>= 1) {
        s1 += __shfl_xor_sync(0xffffffffu, s1, o);
        s2 += __shfl_xor_sync(0xffffffffu, s2, o);
    }
    if ((tid & 31) == 0) { sh1[tid>>5] = s1; sh2[tid>>5] = s2; }
    __syncthreads();
    if (tid < 32) {
        float a = (tid < 8) ? sh1[tid] : 0.f;
        float c = (tid < 8) ? sh2[tid] : 0.f;
        #pragma unroll
        for (int o = 4; o; o >>= 1) {
            a += __shfl_xor_sync(0xffffffffu, a, o);
            c += __shfl_xor_sync(0xffffffffu, c, o);
        }
        if (tid == 0) { sh1[0] = a; sh2[0] = c; }
    }
    __syncthreads();
    float mu  = sh1[0] * (1.f/DMODEL);
    float var = sh2[0] * (1.f/DMODEL) - mu*mu;
    float r   = rsqrtf(var + 1e-5f);
    __nv_bfloat16* o = xn2 + (size_t)row*3*DMODEL;
    #pragma unroll
    for (int i = 0; i < 4; i++) {
        int c = tid + 256*i;
        float val = (v[i]-mu)*r*g[c] + b[c];
        __nv_bfloat16 hi = __float2bfloat16(val);
        __nv_bfloat16 lo = __float2bfloat16(val - __bfloat162float(hi));
        o[c] = hi; o[DMODEL+c] = lo; o[2*DMODEL+c] = hi;
    }
}

// ---------------- SGEMM NT (scalar FFMA) — dt_proj --------------------------
//   0: plain store, 1: += R, 3: softplus(v + bias[m])
#define BM 128
#define BN 128
#define BKT 8

__global__ __launch_bounds__(256) void sgemm_nt(
    const float* __restrict__ A, int lda,
    const float* __restrict__ B, int ldb,
    float* __restrict__ C, int ldc,
    const float* __restrict__ R, int ldr,
    const float* __restrict__ bias,
    int M, int N, int K, int mode)
{
    __shared__ float As[BKT][BM+4];
    __shared__ float Bs[BKT][BN+4];

    int tid = threadIdx.x;
    int tx  = tid & 15;
    int ty  = tid >> 4;
    int m0  = blockIdx.y * BM;
    int n0  = blockIdx.x * BN;

    int lrow = tid >> 1;
    int lk4  = (tid & 1) * 4;

    float acc[8][8];
    #pragma unroll
    for (int i = 0; i < 8; i++)
        #pragma unroll
        for (int j = 0; j < 8; j++) acc[i][j] = 0.f;

    for (int k0 = 0; k0 < K; k0 += BKT) {
        float4 a = make_float4(0.f,0.f,0.f,0.f);
        int am = m0 + lrow;
        if (am < M) a = *reinterpret_cast<const float4*>(A + (size_t)am*lda + k0 + lk4);
        As[lk4+0][lrow] = a.x; As[lk4+1][lrow] = a.y;
        As[lk4+2][lrow] = a.z; As[lk4+3][lrow] = a.w;

        float4 bv = make_float4(0.f,0.f,0.f,0.f);
        int bn = n0 + lrow;
        if (bn < N) bv = *reinterpret_cast<const float4*>(B + (size_t)bn*ldb + k0 + lk4);
        Bs[lk4+0][lrow] = bv.x; Bs[lk4+1][lrow] = bv.y;
        Bs[lk4+2][lrow] = bv.z; Bs[lk4+3][lrow] = bv.w;

        __syncthreads();

        #pragma unroll
        for (int kk = 0; kk < BKT; kk++) {
            float ra[8], rb[8];
            #pragma unroll
            for (int i = 0; i < 4; i++) {
                ra[i]   = As[kk][ty*4 + i];
                ra[i+4] = As[kk][64 + ty*4 + i];
                rb[i]   = Bs[kk][tx*4 + i];
                rb[i+4] = Bs[kk][64 + tx*4 + i];
            }
            #pragma unroll
            for (int i = 0; i < 8; i++)
                #pragma unroll
                for (int j = 0; j < 8; j++)
                    acc[i][j] = fmaf(ra[i], rb[j], acc[i][j]);
        }
        __syncthreads();
    }

    #pragma unroll
    for (int i = 0; i < 8; i++) {
        int m = m0 + ((i < 4) ? (ty*4 + i) : (64 + ty*4 + i - 4));
        if (m >= M) continue;
        float bm = (mode == 3) ? bias[m] : 0.f;
        #pragma unroll
        for (int j = 0; j < 8; j++) {
            int n = n0 + ((j < 4) ? (tx*4 + j) : (64 + tx*4 + j - 4));
            if (n < N) {
                float val = acc[i][j];
                if (mode == 1) {
                    val += R[(size_t)m*ldr + n];
                } else if (mode == 3) {
                    float v = val + bm;
                    val = (v > 20.f) ? v : __logf(1.f + __expf(v));
                }
                C[(size_t)m*ldc + n] = val;
            }
        }
    }
}

// ---------------- x_proj tall-skinny GEMM, split-K --------------------------
#define XP_BM 16
#define XP_BK 32
#define XP_BSROW 98

__global__ __launch_bounds__(256) void xproj_kernel(
    const float* __restrict__ u, const float* __restrict__ w, float* __restrict__ part)
{
    __shared__ float As[XP_BK][XP_BM+1];
    __shared__ float Bs[XP_BK][XP_BSROW];

    int tid  = threadIdx.x;
    int m0   = blockIdx.x * XP_BM;
    int kc   = blockIdx.y;
    int kbeg = kc * (DINNER/XP_KSPLIT);
    int kend = kbeg + (DINNER/XP_KSPLIT);
    int r    = tid >> 4;
    int cg   = tid & 15;

    ull acc[2][3];
    #pragma unroll
    for (int p = 0; p < 2; p++)
        #pragma unroll
        for (int j = 0; j < 3; j++) acc[p][j] = 0ull;

    for (int k0 = kbeg; k0 < kend; k0 += XP_BK) {
        #pragma unroll
        for (int e = tid; e < XP_BM*XP_BK; e += 256) {
            int k = e & 31, m = e >> 5;
            As[k][m] = u[(size_t)(m0+m)*DINNER + k0 + k];
        }
        #pragma unroll
        for (int e = tid; e < XPROJ_OUT*XP_BK; e += 256) {
            int k = e & 31, n = e >> 5;
            Bs[k][n] = w[(size_t)n*DINNER + k0 + k];
        }
        __syncthreads();
        #pragma unroll
        for (int kk = 0; kk < XP_BK; kk += 2) {
            ull a0 = pack_dup(As[kk  ][r]);
            ull a1 = pack_dup(As[kk+1][r]);
            const ull* b0 = reinterpret_cast<const ull*>(&Bs[kk  ][cg*6]);
            const ull* b1 = reinterpret_cast<const ull*>(&Bs[kk+1][cg*6]);
            ffma2(acc[0][0], a0, b0[0]);
            ffma2(acc[0][1], a0, b0[1]);
            ffma2(acc[0][2], a0, b0[2]);
            ffma2(acc[1][0], a1, b1[0]);
            ffma2(acc[1][1], a1, b1[1]);
            ffma2(acc[1][2], a1, b1[2]);
        }
        __syncthreads();
    }

    float* o = part + (size_t)kc*ROWS*XPROJ_OUT + (size_t)(m0 + r)*XPROJ_OUT + cg*6;
    #pragma unroll
    for (int j = 0; j < 3; j++) {
        float2 v0 = unpack2(acc[0][j]);
        float2 v1 = unpack2(acc[1][j]);
        v0.x += v1.x; v0.y += v1.y;
        *reinterpret_cast<float2*>(o + 2*j) = v0;
    }
}

__global__ void xpart_reduce(const float* __restrict__ part, float* __restrict__ xdbl)
{
    int i = blockIdx.x*blockDim.x + threadIdx.x;
    if (i >= ROWS*XPROJ_OUT) return;
    const int S = ROWS*XPROJ_OUT;
    xdbl[i] = (part[i] + part[i+S]) + (part[i+2*S] + part[i+3*S]);
}

// ---------------- causal conv1d + SiLU, coalesced u and u^T -----------------
__global__ __launch_bounds__(256) void conv_silu_kernel(
    const float* __restrict__ xz, const float* __restrict__ w,
    const float* __restrict__ bias, float* __restrict__ u, float* __restrict__ uT)
{
    __shared__ float s[32][33];
    int tid  = threadIdx.x;
    int ld   = tid & 31;
    int lr   = tid >> 5;
    int d0   = blockIdx.x * 32;
    int row0 = blockIdx.y * 32;
    int d    = d0 + ld;

    float w0 = w[d*DCONV+0], w1 = w[d*DCONV+1], w2 = w[d*DCONV+2], w3 = w[d*DCONV+3];
    float bs = bias[d];

    #pragma unroll
    for (int i = 0; i < 4; i++) {
        int row = row0 + lr + 8*i;
        int l   = row % SEQ;
        const float* base = xz + (size_t)row*(2*DINNER) + d;
        float acc = bs + base[0] * w3;
        if (l >= 1) acc += base[-(ptrdiff_t)(2*DINNER)]   * w2;
        if (l >= 2) acc += base[-(ptrdiff_t)(4*DINNER)]   * w1;
        if (l >= 3) acc += base[-(ptrdiff_t)(6*DINNER)]   * w0;
        float sig = 1.f / (1.f + __expf(-acc));
        float val = acc * sig;
        u[(size_t)row*DINNER + d] = val;
        s[ld][lr + 8*i] = val;
    }
    __syncthreads();
    #pragma unroll
    for (int i = 0; i < 4; i++) {
        int wd = lr + 8*i;
        uT[(size_t)(d0 + wd)*ROWS + row0 + ld] = s[wd][ld];
    }
}

// ---------------- selective scan: fast exp, split bf16 yg2 out --------------
__global__ __launch_bounds__(256) void scan_kernel(
    const float* __restrict__ deltaT, const float* __restrict__ uT,
    const float* __restrict__ xdbl, const float* __restrict__ xz,
    const float* __restrict__ A_log, const float* __restrict__ Dskip,
    __nv_bfloat16* __restrict__ yg2)
{
    int warp = threadIdx.x >> 5;
    int lane = threadIdx.x & 31;
    int half = lane >> 4;
    int n    = lane & 15;
    int c    = blockIdx.x*16 + warp*2 + half;
    int b    = c / DINNER;
    int d    = c % DINNER;

    float A  = -__expf(A_log[d*DSTATE + n]);
    float Dd = Dskip[d];
    float h  = 0.f;

    const float* drow = deltaT + (size_t)d*ROWS + b*SEQ;
    const float* urow = uT     + (size_t)d*ROWS + b*SEQ;
    const float* xrow = xdbl   + (size_t)b*SEQ*XPROJ_OUT;
    const float* zp   = xz     + (size_t)b*SEQ*(2*DINNER) + DINNER + d;

    const size_t ZS = 2*DINNER;
    float z0 = zp[0];
    float z1 = zp[ZS];

    for (int t = 0; t < SEQ; t++) {
        float z2 = (t+2 < SEQ) ? zp[(size_t)(t+2)*ZS] : 0.f;
        float dt = drow[t];
        float ut = urow[t];
        float Bn = xrow[t*XPROJ_OUT + DTRANK + n];
        float Cn = xrow[t*XPROJ_OUT + DTRANK + DSTATE + n];
        float dA = __expf(dt * A);
        h = fmaf(dA, h, dt*ut*Bn);
        float p = h * Cn;
        p += __shfl_xor_sync(0xffffffffu, p, 8);
        p += __shfl_xor_sync(0xffffffffu, p, 4);
        p += __shfl_xor_sync(0xffffffffu, p, 2);
        p += __shfl_xor_sync(0xffffffffu, p, 1);
        if (n == 0) {
            float sg  = z0 / (1.f + __expf(-z0));
            float val = fmaf(ut, Dd, p) * sg;
            __nv_bfloat16 hi = __float2bfloat16(val);
            __nv_bfloat16 lo = __float2bfloat16(val - __bfloat162float(hi));
            size_t base = (size_t)(b*SEQ + t)*3*DINNER;
            yg2[base + d]            = hi;
            yg2[base + DINNER + d]   = lo;
            yg2[base + 2*DINNER + d] = hi;
        }
        z0 = z1; z1 = z2;
    }
}

// ---------------- launch ----------------------------------------------------
extern "C" void kernel_launch(void* const* d_in, const int* in_sizes, int n_in,
                              void* d_out, int out_size)
{
    const float* x      = (const float*)d_in[0];
    const float* ln_g   = (const float*)d_in[1];
    const float* ln_b   = (const float*)d_in[2];
    const float* w_in   = (const float*)d_in[3];
    const float* conv_w = (const float*)d_in[4];
    const float* conv_b = (const float*)d_in[5];
    const float* w_x    = (const float*)d_in[6];
    const float* w_dt   = (const float*)d_in[7];
    const float* b_dt   = (const float*)d_in[8];
    const float* A_log  = (const float*)d_in[9];
    const float* Dsk    = (const float*)d_in[10];
    const float* w_out  = (const float*)d_in[11];
    float* out = (float*)d_out;

    float *xz, *u, *uT, *xdbl, *xpart, *deltaT;
    __nv_bfloat16 *xn2, *win2, *yg2, *wout2;
    cudaGetSymbolAddress((void**)&xz,     g_xz);
    cudaGetSymbolAddress((void**)&u,      g_u);
    cudaGetSymbolAddress((void**)&uT,     g_uT);
    cudaGetSymbolAddress((void**)&xdbl,   g_xdbl);
    cudaGetSymbolAddress((void**)&xpart,  g_xpart);
    cudaGetSymbolAddress((void**)&deltaT, g_deltaT);
    cudaGetSymbolAddress((void**)&xn2,    g_xn2);
    cudaGetSymbolAddress((void**)&win2,   g_win2);
    cudaGetSymbolAddress((void**)&yg2,    g_yg2);
    cudaGetSymbolAddress((void**)&wout2,  g_wout2);

    static int smem_set = 0;
    if (!smem_set) {
        cudaFuncSetAttribute(wmma_nt<4>, cudaFuncAttributeMaxDynamicSharedMemorySize, WMMA_SMEM_W);
        cudaFuncSetAttribute(wmma_nt<2>, cudaFuncAttributeMaxDynamicSharedMemorySize, WMMA_SMEM_N);
        smem_set = 1;
    }

    // 1. layernorm -> xn2 (split bf16)
    ln_kernel<<<ROWS, 256>>>(x, ln_g, ln_b, xn2);

    // 2. in_proj on tensor cores: split w_in, then bf16 GEMM K3=3072 (wide tiles)
    split_kernel<<<(2*DINNER*DMODEL+255)/256, 256>>>(w_in, win2, DMODEL, 2*DINNER*DMODEL);
    {
        dim3 g(2*DINNER/256, ROWS/WBM);
        wmma_nt<4><<<g, 256, WMMA_SMEM_W>>>(xn2, win2, xz, 2*DINNER, nullptr, 0,
                                            ROWS, 2*DINNER, 3*DMODEL, 0);
    }

    // 3. causal depthwise conv + SiLU -> u, u^T (coalesced)
    {
        dim3 g(DINNER/32, ROWS/32);
        conv_silu_kernel<<<g, 256>>>(xz, conv_w, conv_b, u, uT);
    }

    // 4. x_proj (split-K): xdbl[2048,96] = u @ w_x[96,2048]^T
    {
        dim3 g(ROWS/XP_BM, XP_KSPLIT);
        xproj_kernel<<<g, 256>>>(u, w_x, xpart);
        xpart_reduce<<<(ROWS*XPROJ_OUT+255)/256, 256>>>(xpart, xdbl);
    }

    // 5. dt_proj TRANSPOSED + fused softplus
    {
        dim3 g(ROWS/BN, DINNER/BM);
        sgemm_nt<<<g, 256>>>(w_dt, DTRANK, xdbl, XPROJ_OUT, deltaT, ROWS,
                             nullptr, 0, b_dt, DINNER, ROWS, DTRANK, 3);
    }

    // 6. selective scan -> yg2 (split bf16, gate fused)
    scan_kernel<<<(BATCH*DINNER)/16, 256>>>(deltaT, uT, xdbl, xz, A_log, Dsk, yg2);

    // 7. out_proj on tensor cores + residual: K3=6144 (narrow tiles: N=1024)
    split_kernel<<<(DMODEL*DINNER+255)/256, 256>>>(w_out, wout2, DINNER, DMODEL*DINNER);
    {
        dim3 g(DMODEL/128, ROWS/WBM);
        wmma_nt<2><<<g, 256, WMMA_SMEM_N>>>(yg2, wout2, out, DMODEL, x, DMODEL,
                                            ROWS, DMODEL, 3*DINNER, 1);
    }
}

// round 10
// speedup vs baseline: 3.6513x; 1.4742x over previous
#include <cuda_runtime.h>
#include <cuda_bf16.h>
#include <mma.h>
#include <math.h>

using namespace nvcuda;

#define BATCH   2
#define SEQ     1024
#define DMODEL  1024
#define DINNER  2048
#define DTRANK  64
#define DSTATE  16
#define DCONV   4
#define ROWS    (BATCH*SEQ)            // 2048
#define XPROJ_OUT (DTRANK + 2*DSTATE)  // 96

typedef unsigned long long ull;

__device__ __forceinline__ void ffma2(ull &d, ull a, ull b) {
    asm("fma.rn.f32x2 %0, %1, %2, %0;" : "+l"(d) : "l"(a), "l"(b));
}
__device__ __forceinline__ ull pack_dup(float x) {
    ull r; asm("mov.b64 %0, {%1, %1};" : "=l"(r) : "f"(x)); return r;
}
__device__ __forceinline__ float2 unpack2(ull v) {
    float2 f; asm("mov.b64 {%0, %1}, %2;" : "=f"(f.x), "=f"(f.y) : "l"(v)); return f;
}
__device__ __forceinline__ void cp_async16(void* smem, const void* gmem) {
    unsigned s = (unsigned)__cvta_generic_to_shared(smem);
    asm volatile("cp.async.cg.shared.global [%0], [%1], 16;" :: "r"(s), "l"(gmem));
}
#define CP_COMMIT()  asm volatile("cp.async.commit_group;")
#define CP_WAITG(n)  asm volatile("cp.async.wait_group %0;" :: "n"(n))

// ---------------- scratch (static device globals; no allocation) ------------
#define XP_KSPLIT 4
__device__ float g_xz    [ROWS*2*DINNER];
__device__ float g_u     [ROWS*DINNER];
__device__ float g_uT    [DINNER*ROWS];
__device__ float g_xdbl  [ROWS*XPROJ_OUT];
__device__ float g_xpart [XP_KSPLIT*ROWS*XPROJ_OUT];
__device__ float g_deltaT[DINNER*ROWS];
__device__ __nv_bfloat16 g_xn2  [ROWS*3*DMODEL];
__device__ __nv_bfloat16 g_win2 [2*DINNER*3*DMODEL];
__device__ __nv_bfloat16 g_yg2  [ROWS*3*DINNER];
__device__ __nv_bfloat16 g_wout2[DMODEL*3*DINNER];

// ---------------- split fp32 -> bf16 hi/lo (weights: [hi|hi|lo]) ------------
__global__ void split_kernel(const float* __restrict__ X, __nv_bfloat16* __restrict__ Y,
                             int K, int total)
{
    int i = blockIdx.x*blockDim.x + threadIdx.x;
    if (i >= total) return;
    int m = i / K, k = i % K;
    float x = X[i];
    __nv_bfloat16 hi = __float2bfloat16(x);
    __nv_bfloat16 lo = __float2bfloat16(x - __bfloat162float(hi));
    __nv_bfloat16* row = Y + (size_t)m*3*K;
    row[k] = hi; row[K+k] = hi; row[2*K+k] = lo;
}

// ---------------- wmma bf16 GEMM NT, 4-stage cp.async pipeline --------------
#define WBM 128
#define WBK 32
#define WPITCH 40
#define NSTAGE 4
#define ASZ (WBM*WPITCH)

template<int NFRAG>
__global__ __launch_bounds__(256) void wmma_nt(
    const __nv_bfloat16* __restrict__ A2, const __nv_bfloat16* __restrict__ B2,
    float* __restrict__ C, int ldc, const float* __restrict__ R, int ldr,
    int M, int N, int K3, int mode)
{
    constexpr int WBN = 64*NFRAG;
    constexpr int BSZ = WBN*WPITCH;

    extern __shared__ __align__(16) __nv_bfloat16 sm[];
    __nv_bfloat16* Asm = sm;
    __nv_bfloat16* Bsm = sm + NSTAGE*ASZ;

    int tid = threadIdx.x;
    int w   = tid >> 5;
    int wm  = w >> 2;
    int wn  = w & 3;
    int m0  = blockIdx.y * WBM;
    int n0  = blockIdx.x * WBN;

    wmma::fragment<wmma::accumulator, 16,16,16, float> acc[4][NFRAG];
    #pragma unroll
    for (int i = 0; i < 4; i++)
        #pragma unroll
        for (int j = 0; j < NFRAG; j++) wmma::fill_fragment(acc[i][j], 0.f);

    auto stage = [&](int s, int k0) {
        __nv_bfloat16* As = Asm + s*ASZ;
        __nv_bfloat16* Bs = Bsm + s*BSZ;
        #pragma unroll
        for (int e = tid; e < WBM*4; e += 256) {
            int row = e >> 2, q = e & 3;
            cp_async16(&As[row*WPITCH + q*8], A2 + (size_t)(m0+row)*K3 + k0 + q*8);
        }
        #pragma unroll
        for (int e = tid; e < WBN*4; e += 256) {
            int row = e >> 2, q = e & 3;
            cp_async16(&Bs[row*WPITCH + q*8], B2 + (size_t)(n0+row)*K3 + k0 + q*8);
        }
        CP_COMMIT();
    };

    int NT = K3 / WBK;
    stage(0, 0);
    stage(1, WBK);
    stage(2, 2*WBK);

    for (int kt = 0; kt < NT; kt++) {
        __syncthreads();
        if (kt + 3 < NT)      { stage((kt+3)%NSTAGE, (kt+3)*WBK); CP_WAITG(3); }
        else if (kt + 3 == NT) { CP_WAITG(2); }
        else if (kt + 2 == NT) { CP_WAITG(1); }
        else                   { CP_WAITG(0); }
        __syncthreads();

        const __nv_bfloat16* As = Asm + (kt%NSTAGE)*ASZ;
        const __nv_bfloat16* Bs = Bsm + (kt%NSTAGE)*BSZ;
        #pragma unroll
        for (int ks = 0; ks < WBK; ks += 16) {
            wmma::fragment<wmma::matrix_a, 16,16,16, __nv_bfloat16, wmma::row_major> af[4];
            wmma::fragment<wmma::matrix_b, 16,16,16, __nv_bfloat16, wmma::col_major> bf[NFRAG];
            #pragma unroll
            for (int i = 0; i < 4; i++)
                wmma::load_matrix_sync(af[i], &As[(wm*64 + i*16)*WPITCH + ks], WPITCH);
            #pragma unroll
            for (int j = 0; j < NFRAG; j++)
                wmma::load_matrix_sync(bf[j], &Bs[(wn*16*NFRAG + j*16)*WPITCH + ks], WPITCH);
            #pragma unroll
            for (int i = 0; i < 4; i++)
                #pragma unroll
                for (int j = 0; j < NFRAG; j++)
                    wmma::mma_sync(acc[i][j], af[i], bf[j], acc[i][j]);
        }
    }

    #pragma unroll
    for (int i = 0; i < 4; i++) {
        int m = m0 + wm*64 + i*16;
        #pragma unroll
        for (int j = 0; j < NFRAG; j++) {
            int n = n0 + wn*16*NFRAG + j*16;
            if (mode == 1) {
                wmma::fragment<wmma::accumulator, 16,16,16, float> rf;
                wmma::load_matrix_sync(rf, R + (size_t)m*ldr + n, ldr, wmma::mem_row_major);
                #pragma unroll
                for (int t = 0; t < acc[i][j].num_elements; t++)
                    acc[i][j].x[t] += rf.x[t];
            }
            wmma::store_matrix_sync(C + (size_t)m*ldc + n, acc[i][j], ldc, wmma::mem_row_major);
        }
    }
}

#define WMMA_SMEM_W (NSTAGE*(ASZ + 256*WPITCH)*2)   // NFRAG=4
#define WMMA_SMEM_N (NSTAGE*(ASZ + 128*WPITCH)*2)   // NFRAG=2

// ---------------- LayerNorm -> split bf16 [hi|lo|hi] directly ---------------
__global__ void ln_kernel(const float* __restrict__ x, const float* __restrict__ g,
                          const float* __restrict__ b, __nv_bfloat16* __restrict__ xn2)
{
    int row = blockIdx.x;
    int tid = threadIdx.x;
    const float* xr = x + (size_t)row*DMODEL;
    float v[4];
    float s1 = 0.f, s2 = 0.f;
    #pragma unroll
    for (int i = 0; i < 4; i++) {
        v[i] = xr[tid + 256*i];
        s1 += v[i];
        s2 += v[i]*v[i];
    }
    __shared__ float sh1[8], sh2[8];
    #pragma unroll
    for (int o = 16; o; o >>= 1) {
        s1 += __shfl_xor_sync(0xffffffffu, s1, o);
        s2 += __shfl_xor_sync(0xffffffffu, s2, o);
    }
    if ((tid & 31) == 0) { sh1[tid>>5] = s1; sh2[tid>>5] = s2; }
    __syncthreads();
    if (tid < 32) {
        float a = (tid < 8) ? sh1[tid] : 0.f;
        float c = (tid < 8) ? sh2[tid] : 0.f;
        #pragma unroll
        for (int o = 4; o; o >>= 1) {
            a += __shfl_xor_sync(0xffffffffu, a, o);
            c += __shfl_xor_sync(0xffffffffu, c, o);
        }
        if (tid == 0) { sh1[0] = a; sh2[0] = c; }
    }
    __syncthreads();
    float mu  = sh1[0] * (1.f/DMODEL);
    float var = sh2[0] * (1.f/DMODEL) - mu*mu;
    float r   = rsqrtf(var + 1e-5f);
    __nv_bfloat16* o = xn2 + (size_t)row*3*DMODEL;
    #pragma unroll
    for (int i = 0; i < 4; i++) {
        int c = tid + 256*i;
        float val = (v[i]-mu)*r*g[c] + b[c];
        __nv_bfloat16 hi = __float2bfloat16(val);
        __nv_bfloat16 lo = __float2bfloat16(val - __bfloat162float(hi));
        o[c] = hi; o[DMODEL+c] = lo; o[2*DMODEL+c] = hi;
    }
}

// ---------------- SGEMM NT (scalar FFMA) — dt_proj --------------------------
#define BM 128
#define BN 128
#define BKT 8

__global__ __launch_bounds__(256) void sgemm_nt(
    const float* __restrict__ A, int lda,
    const float* __restrict__ B, int ldb,
    float* __restrict__ C, int ldc,
    const float* __restrict__ R, int ldr,
    const float* __restrict__ bias,
    int M, int N, int K, int mode)
{
    __shared__ float As[BKT][BM+4];
    __shared__ float Bs[BKT][BN+4];

    int tid = threadIdx.x;
    int tx  = tid & 15;
    int ty  = tid >> 4;
    int m0  = blockIdx.y * BM;
    int n0  = blockIdx.x * BN;

    int lrow = tid >> 1;
    int lk4  = (tid & 1) * 4;

    float acc[8][8];
    #pragma unroll
    for (int i = 0; i < 8; i++)
        #pragma unroll
        for (int j = 0; j < 8; j++) acc[i][j] = 0.f;

    for (int k0 = 0; k0 < K; k0 += BKT) {
        float4 a = make_float4(0.f,0.f,0.f,0.f);
        int am = m0 + lrow;
        if (am < M) a = *reinterpret_cast<const float4*>(A + (size_t)am*lda + k0 + lk4);
        As[lk4+0][lrow] = a.x; As[lk4+1][lrow] = a.y;
        As[lk4+2][lrow] = a.z; As[lk4+3][lrow] = a.w;

        float4 bv = make_float4(0.f,0.f,0.f,0.f);
        int bn = n0 + lrow;
        if (bn < N) bv = *reinterpret_cast<const float4*>(B + (size_t)bn*ldb + k0 + lk4);
        Bs[lk4+0][lrow] = bv.x; Bs[lk4+1][lrow] = bv.y;
        Bs[lk4+2][lrow] = bv.z; Bs[lk4+3][lrow] = bv.w;

        __syncthreads();

        #pragma unroll
        for (int kk = 0; kk < BKT; kk++) {
            float ra[8], rb[8];
            #pragma unroll
            for (int i = 0; i < 4; i++) {
                ra[i]   = As[kk][ty*4 + i];
                ra[i+4] = As[kk][64 + ty*4 + i];
                rb[i]   = Bs[kk][tx*4 + i];
                rb[i+4] = Bs[kk][64 + tx*4 + i];
            }
            #pragma unroll
            for (int i = 0; i < 8; i++)
                #pragma unroll
                for (int j = 0; j < 8; j++)
                    acc[i][j] = fmaf(ra[i], rb[j], acc[i][j]);
        }
        __syncthreads();
    }

    #pragma unroll
    for (int i = 0; i < 8; i++) {
        int m = m0 + ((i < 4) ? (ty*4 + i) : (64 + ty*4 + i - 4));
        if (m >= M) continue;
        float bm = (mode == 3) ? bias[m] : 0.f;
        #pragma unroll
        for (int j = 0; j < 8; j++) {
            int n = n0 + ((j < 4) ? (tx*4 + j) : (64 + tx*4 + j - 4));
            if (n < N) {
                float val = acc[i][j];
                if (mode == 1) {
                    val += R[(size_t)m*ldr + n];
                } else if (mode == 3) {
                    float v = val + bm;
                    val = (v > 20.f) ? v : __logf(1.f + __expf(v));
                }
                C[(size_t)m*ldc + n] = val;
            }
        }
    }
}

// ---------------- x_proj tall-skinny GEMM, split-K --------------------------
#define XP_BM 16
#define XP_BK 32
#define XP_BSROW 98

__global__ __launch_bounds__(256) void xproj_kernel(
    const float* __restrict__ u, const float* __restrict__ w, float* __restrict__ part)
{
    __shared__ float As[XP_BK][XP_BM+1];
    __shared__ float Bs[XP_BK][XP_BSROW];

    int tid  = threadIdx.x;
    int m0   = blockIdx.x * XP_BM;
    int kc   = blockIdx.y;
    int kbeg = kc * (DINNER/XP_KSPLIT);
    int kend = kbeg + (DINNER/XP_KSPLIT);
    int r    = tid >> 4;
    int cg   = tid & 15;

    ull acc[2][3];
    #pragma unroll
    for (int p = 0; p < 2; p++)
        #pragma unroll
        for (int j = 0; j < 3; j++) acc[p][j] = 0ull;

    for (int k0 = kbeg; k0 < kend; k0 += XP_BK) {
        #pragma unroll
        for (int e = tid; e < XP_BM*XP_BK; e += 256) {
            int k = e & 31, m = e >> 5;
            As[k][m] = u[(size_t)(m0+m)*DINNER + k0 + k];
        }
        #pragma unroll
        for (int e = tid; e < XPROJ_OUT*XP_BK; e += 256) {
            int k = e & 31, n = e >> 5;
            Bs[k][n] = w[(size_t)n*DINNER + k0 + k];
        }
        __syncthreads();
        #pragma unroll
        for (int kk = 0; kk < XP_BK; kk += 2) {
            ull a0 = pack_dup(As[kk  ][r]);
            ull a1 = pack_dup(As[kk+1][r]);
            const ull* b0 = reinterpret_cast<const ull*>(&Bs[kk  ][cg*6]);
            const ull* b1 = reinterpret_cast<const ull*>(&Bs[kk+1][cg*6]);
            ffma2(acc[0][0], a0, b0[0]);
            ffma2(acc[0][1], a0, b0[1]);
            ffma2(acc[0][2], a0, b0[2]);
            ffma2(acc[1][0], a1, b1[0]);
            ffma2(acc[1][1], a1, b1[1]);
            ffma2(acc[1][2], a1, b1[2]);
        }
        __syncthreads();
    }

    float* o = part + (size_t)kc*ROWS*XPROJ_OUT + (size_t)(m0 + r)*XPROJ_OUT + cg*6;
    #pragma unroll
    for (int j = 0; j < 3; j++) {
        float2 v0 = unpack2(acc[0][j]);
        float2 v1 = unpack2(acc[1][j]);
        v0.x += v1.x; v0.y += v1.y;
        *reinterpret_cast<float2*>(o + 2*j) = v0;
    }
}

__global__ void xpart_reduce(const float* __restrict__ part, float* __restrict__ xdbl)
{
    int i = blockIdx.x*blockDim.x + threadIdx.x;
    if (i >= ROWS*XPROJ_OUT) return;
    const int S = ROWS*XPROJ_OUT;
    xdbl[i] = (part[i] + part[i+S]) + (part[i+2*S] + part[i+3*S]);
}

// ---------------- causal conv1d + SiLU, coalesced u and u^T -----------------
__global__ __launch_bounds__(256) void conv_silu_kernel(
    const float* __restrict__ xz, const float* __restrict__ w,
    const float* __restrict__ bias, float* __restrict__ u, float* __restrict__ uT)
{
    __shared__ float s[32][33];
    int tid  = threadIdx.x;
    int ld   = tid & 31;
    int lr   = tid >> 5;
    int d0   = blockIdx.x * 32;
    int row0 = blockIdx.y * 32;
    int d    = d0 + ld;

    float w0 = w[d*DCONV+0], w1 = w[d*DCONV+1], w2 = w[d*DCONV+2], w3 = w[d*DCONV+3];
    float bs = bias[d];

    #pragma unroll
    for (int i = 0; i < 4; i++) {
        int row = row0 + lr + 8*i;
        int l   = row % SEQ;
        const float* base = xz + (size_t)row*(2*DINNER) + d;
        float acc = bs + base[0] * w3;
        if (l >= 1) acc += base[-(ptrdiff_t)(2*DINNER)]   * w2;
        if (l >= 2) acc += base[-(ptrdiff_t)(4*DINNER)]   * w1;
        if (l >= 3) acc += base[-(ptrdiff_t)(6*DINNER)]   * w0;
        float sig = 1.f / (1.f + __expf(-acc));
        float val = acc * sig;
        u[(size_t)row*DINNER + d] = val;
        s[ld][lr + 8*i] = val;
    }
    __syncthreads();
    #pragma unroll
    for (int i = 0; i < 4; i++) {
        int wd = lr + 8*i;
        uT[(size_t)(d0 + wd)*ROWS + row0 + ld] = s[wd][ld];
    }
}

// ---------------- selective scan v2: smem-staged, double-buffered -----------
// Block: 16 channels (one batch), 8 warps (2 ch/warp), 32-timestep chunks.
#define SCT 32   // chunk length

__global__ __launch_bounds__(256) void scan_kernel(
    const float* __restrict__ deltaT, const float* __restrict__ uT,
    const float* __restrict__ xdbl, const float* __restrict__ xz,
    const float* __restrict__ A_log, const float* __restrict__ Dskip,
    __nv_bfloat16* __restrict__ yg2)
{
    __shared__ __align__(16) float sBC[2][SCT][32];   // [t][0..15]=B, [16..31]=C
    __shared__ __align__(16) float sdt[2][16][SCT];
    __shared__ __align__(16) float sut[2][16][SCT];
    __shared__ __align__(16) float szT[2][SCT][16];
    __shared__ float sy[16][SCT+1];

    int tid  = threadIdx.x;
    int warp = tid >> 5;
    int lane = tid & 31;
    int half = lane >> 4;
    int n    = lane & 15;
    int ch   = warp*2 + half;            // 0..15
    int c0   = blockIdx.x * 16;
    int b    = c0 / DINNER;
    int dbas = c0 % DINNER;
    int d    = dbas + ch;

    float A  = -__expf(A_log[d*DSTATE + n]);
    float Dd = Dskip[d];
    float h  = 0.f;

    const float* dsrc = deltaT + (size_t)d*ROWS + b*SEQ;
    const float* usrc = uT     + (size_t)d*ROWS + b*SEQ;
    const float* xsrc = xdbl   + (size_t)b*SEQ*XPROJ_OUT;
    const float* zsrc = xz     + (size_t)b*SEQ*(2*DINNER) + DINNER + dbas;

    auto stage = [&](int buf, int t0) {
        // B,C: 32 floats per t, contiguous (xdbl cols 64..95)
        for (int e = tid; e < SCT*8; e += 256) {
            int t = e >> 3, q = e & 7;
            cp_async16(&sBC[buf][t][q*4], xsrc + (size_t)(t0+t)*XPROJ_OUT + DTRANK + q*4);
        }
        // dt, ut: per channel, 32 consecutive t
        for (int e = tid; e < 16*8; e += 256) {
            int cc = e >> 3, q = e & 7;
            cp_async16(&sdt[buf][cc][q*4],
                       deltaT + (size_t)(dbas+cc)*ROWS + b*SEQ + t0 + q*4);
            cp_async16(&sut[buf][cc][q*4],
                       uT + (size_t)(dbas+cc)*ROWS + b*SEQ + t0 + q*4);
        }
        // z: per t, 16 consecutive d
        for (int e = tid; e < SCT*4; e += 256) {
            int t = e >> 2, q = e & 3;
            cp_async16(&szT[buf][t][q*4], zsrc + (size_t)(t0+t)*(2*DINNER) + q*4);
        }
        CP_COMMIT();
    };

    const int NCH = SEQ / SCT;   // 32 chunks
    stage(0, 0);

    for (int j = 0; j < NCH; j++) {
        int buf = j & 1;
        if (j + 1 < NCH) { stage(buf ^ 1, (j+1)*SCT); CP_WAITG(1); }
        else             { CP_WAITG(0); }
        __syncthreads();    // chunk j staged & visible

        #pragma unroll 4
        for (int i = 0; i < SCT; i++) {
            float dt = sdt[buf][ch][i];
            float ut = sut[buf][ch][i];
            float Bn = sBC[buf][i][n];
            float Cn = sBC[buf][i][16+n];
            float dA = __expf(dt * A);
            h = fmaf(dA, h, dt*ut*Bn);
            float p = h * Cn;
            p += __shfl_xor_sync(0xffffffffu, p, 8);
            p += __shfl_xor_sync(0xffffffffu, p, 4);
            p += __shfl_xor_sync(0xffffffffu, p, 2);
            p += __shfl_xor_sync(0xffffffffu, p, 1);
            if (n == 0) sy[ch][i] = fmaf(ut, Dd, p);
        }
        __syncthreads();    // sy complete, all warps done with buf

        // cooperative gated store: 512 values, coalesced bf16 groups
        int t0 = j*SCT;
        #pragma unroll
        for (int e = tid; e < 16*SCT; e += 256) {
            int t = e >> 4, cc = e & 15;
            float val = sy[cc][t];
            float z   = szT[buf][t][cc];
            float sg  = z / (1.f + __expf(-z));
            val *= sg;
            __nv_bfloat16 hi = __float2bfloat16(val);
            __nv_bfloat16 lo = __float2bfloat16(val - __bfloat162float(hi));
            size_t base = (size_t)(b*SEQ + t0 + t)*3*DINNER + dbas + cc;
            yg2[base]            = hi;
            yg2[base + DINNER]   = lo;
            yg2[base + 2*DINNER] = hi;
        }
        __syncthreads();    // szT[buf], sy free before restage
    }
}

// ---------------- launch ----------------------------------------------------
extern "C" void kernel_launch(void* const* d_in, const int* in_sizes, int n_in,
                              void* d_out, int out_size)
{
    const float* x      = (const float*)d_in[0];
    const float* ln_g   = (const float*)d_in[1];
    const float* ln_b   = (const float*)d_in[2];
    const float* w_in   = (const float*)d_in[3];
    const float* conv_w = (const float*)d_in[4];
    const float* conv_b = (const float*)d_in[5];
    const float* w_x    = (const float*)d_in[6];
    const float* w_dt   = (const float*)d_in[7];
    const float* b_dt   = (const float*)d_in[8];
    const float* A_log  = (const float*)d_in[9];
    const float* Dsk    = (const float*)d_in[10];
    const float* w_out  = (const float*)d_in[11];
    float* out = (float*)d_out;

    float *xz, *u, *uT, *xdbl, *xpart, *deltaT;
    __nv_bfloat16 *xn2, *win2, *yg2, *wout2;
    cudaGetSymbolAddress((void**)&xz,     g_xz);
    cudaGetSymbolAddress((void**)&u,      g_u);
    cudaGetSymbolAddress((void**)&uT,     g_uT);
    cudaGetSymbolAddress((void**)&xdbl,   g_xdbl);
    cudaGetSymbolAddress((void**)&xpart,  g_xpart);
    cudaGetSymbolAddress((void**)&deltaT, g_deltaT);
    cudaGetSymbolAddress((void**)&xn2,    g_xn2);
    cudaGetSymbolAddress((void**)&win2,   g_win2);
    cudaGetSymbolAddress((void**)&yg2,    g_yg2);
    cudaGetSymbolAddress((void**)&wout2,  g_wout2);

    static int smem_set = 0;
    if (!smem_set) {
        cudaFuncSetAttribute(wmma_nt<4>, cudaFuncAttributeMaxDynamicSharedMemorySize, WMMA_SMEM_W);
        cudaFuncSetAttribute(wmma_nt<2>, cudaFuncAttributeMaxDynamicSharedMemorySize, WMMA_SMEM_N);
        smem_set = 1;
    }

    // 1. layernorm -> xn2 (split bf16)
    ln_kernel<<<ROWS, 256>>>(x, ln_g, ln_b, xn2);

    // 2. in_proj on tensor cores
    split_kernel<<<(2*DINNER*DMODEL+255)/256, 256>>>(w_in, win2, DMODEL, 2*DINNER*DMODEL);
    {
        dim3 g(2*DINNER/256, ROWS/WBM);
        wmma_nt<4><<<g, 256, WMMA_SMEM_W>>>(xn2, win2, xz, 2*DINNER, nullptr, 0,
                                            ROWS, 2*DINNER, 3*DMODEL, 0);
    }

    // 3. causal depthwise conv + SiLU -> u, u^T
    {
        dim3 g(DINNER/32, ROWS/32);
        conv_silu_kernel<<<g, 256>>>(xz, conv_w, conv_b, u, uT);
    }

    // 4. x_proj (split-K)
    {
        dim3 g(ROWS/XP_BM, XP_KSPLIT);
        xproj_kernel<<<g, 256>>>(u, w_x, xpart);
        xpart_reduce<<<(ROWS*XPROJ_OUT+255)/256, 256>>>(xpart, xdbl);
    }

    // 5. dt_proj TRANSPOSED + fused softplus
    {
        dim3 g(ROWS/BN, DINNER/BM);
        sgemm_nt<<<g, 256>>>(w_dt, DTRANK, xdbl, XPROJ_OUT, deltaT, ROWS,
                             nullptr, 0, b_dt, DINNER, ROWS, DTRANK, 3);
    }

    // 6. selective scan v2 (smem-staged) -> yg2
    scan_kernel<<<(BATCH*DINNER)/16, 256>>>(deltaT, uT, xdbl, xz, A_log, Dsk, yg2);

    // 7. out_proj on tensor cores + residual
    split_kernel<<<(DMODEL*DINNER+255)/256, 256>>>(w_out, wout2, DINNER, DMODEL*DINNER);
    {
        dim3 g(DMODEL/128, ROWS/WBM);
        wmma_nt<2><<<g, 256, WMMA_SMEM_N>>>(yg2, wout2, out, DMODEL, x, DMODEL,
                                            ROWS, DMODEL, 3*DINNER, 1);
    }
}

// round 14
// speedup vs baseline: 5.8711x; 1.6079x over previous
#include <cuda_runtime.h>
#include <cuda_bf16.h>
#include <stdint.h>
#include <math.h>

#define BATCH   2
#define SEQ     1024
#define DMODEL  1024
#define DINNER  2048
#define DTRANK  64
#define DSTATE  16
#define DCONV   4
#define ROWS    (BATCH*SEQ)            // 2048
#define XPROJ_OUT (DTRANK + 2*DSTATE)  // 96

typedef unsigned long long ull;

__device__ __forceinline__ void ffma2(ull &d, ull a, ull b) {
    asm("fma.rn.f32x2 %0, %1, %2, %0;" : "+l"(d) : "l"(a), "l"(b));
}
__device__ __forceinline__ ull pack_dup(float x) {
    ull r; asm("mov.b64 %0, {%1, %1};" : "=l"(r) : "f"(x)); return r;
}
__device__ __forceinline__ float2 unpack2(ull v) {
    float2 f; asm("mov.b64 {%0, %1}, %2;" : "=f"(f.x), "=f"(f.y) : "l"(v)); return f;
}
__device__ __forceinline__ void cp_async16(void* smem, const void* gmem) {
    unsigned s = (unsigned)__cvta_generic_to_shared(smem);
    asm volatile("cp.async.cg.shared.global [%0], [%1], 16;" :: "r"(s), "l"(gmem));
}
#define CP_COMMIT()  asm volatile("cp.async.commit_group;")
#define CP_WAITG(n)  asm volatile("cp.async.wait_group %0;" :: "n"(n))

#include <mma.h>
using namespace nvcuda;

// ---------------- scratch (static device globals; no allocation) ------------
#define XP_KSPLIT 4
__device__ float g_xz    [ROWS*2*DINNER];
__device__ float g_u     [ROWS*DINNER];
__device__ float g_uT    [DINNER*ROWS];
__device__ float g_xdbl  [ROWS*XPROJ_OUT];
__device__ float g_xpart [XP_KSPLIT*ROWS*XPROJ_OUT];
__device__ float g_deltaT[DINNER*ROWS];
// plain bf16 operands
__device__ __nv_bfloat16 g_xn2  [ROWS*DMODEL];
__device__ __nv_bfloat16 g_win2 [2*DINNER*DMODEL];
__device__ __nv_bfloat16 g_yg2  [ROWS*DINNER];
__device__ __nv_bfloat16 g_wout2[DMODEL*DINNER];

// ---------------- cast fp32 -> bf16 (weights) --------------------------------
__global__ void cast_kernel(const float* __restrict__ X, __nv_bfloat16* __restrict__ Y,
                            int total)
{
    int i = blockIdx.x*blockDim.x + threadIdx.x;
    if (i < total) Y[i] = __float2bfloat16(X[i]);
}

// ---------------- wmma bf16 GEMM NT, 4-stage cp.async pipeline --------------
// C[M,N] = A2[M,K3] @ B2[N,K3]^T; mode: 0 plain, 1 += R
// Block tile: 128 x (64*NFRAG). 8 warps as 2x4; warp tile 64 x (16*NFRAG).
#define WBM 128
#define WBK 32
#define WPITCH 40       // bf16 pitch: 80 bytes, conflict-free for ldmatrix
#define NSTAGE 4
#define ASZ (WBM*WPITCH)

template<int NFRAG>
__global__ __launch_bounds__(256) void wmma_nt(
    const __nv_bfloat16* __restrict__ A2, const __nv_bfloat16* __restrict__ B2,
    float* __restrict__ C, int ldc, const float* __restrict__ R, int ldr,
    int M, int N, int K3, int mode)
{
    constexpr int WBN = 64*NFRAG;
    constexpr int BSZ = WBN*WPITCH;

    extern __shared__ __align__(16) __nv_bfloat16 sm[];
    __nv_bfloat16* Asm = sm;
    __nv_bfloat16* Bsm = sm + NSTAGE*ASZ;

    int tid = threadIdx.x;
    int w   = tid >> 5;
    int wm  = w >> 2;
    int wn  = w & 3;
    int m0  = blockIdx.y * WBM;
    int n0  = blockIdx.x * WBN;

    wmma::fragment<wmma::accumulator, 16,16,16, float> acc[4][NFRAG];
    #pragma unroll
    for (int i = 0; i < 4; i++)
        #pragma unroll
        for (int j = 0; j < NFRAG; j++) wmma::fill_fragment(acc[i][j], 0.f);

    auto stage = [&](int s, int k0) {
        __nv_bfloat16* As = Asm + s*ASZ;
        __nv_bfloat16* Bs = Bsm + s*BSZ;
        #pragma unroll
        for (int e = tid; e < WBM*4; e += 256) {
            int row = e >> 2, q = e & 3;
            cp_async16(&As[row*WPITCH + q*8], A2 + (size_t)(m0+row)*K3 + k0 + q*8);
        }
        #pragma unroll
        for (int e = tid; e < WBN*4; e += 256) {
            int row = e >> 2, q = e & 3;
            cp_async16(&Bs[row*WPITCH + q*8], B2 + (size_t)(n0+row)*K3 + k0 + q*8);
        }
        CP_COMMIT();
    };

    int NT = K3 / WBK;
    stage(0, 0);
    stage(1, WBK);
    stage(2, 2*WBK);

    for (int kt = 0; kt < NT; kt++) {
        __syncthreads();
        if (kt + 3 < NT)      { stage((kt+3)%NSTAGE, (kt+3)*WBK); CP_WAITG(3); }
        else if (kt + 3 == NT) { CP_WAITG(2); }
        else if (kt + 2 == NT) { CP_WAITG(1); }
        else                   { CP_WAITG(0); }
        __syncthreads();

        const __nv_bfloat16* As = Asm + (kt%NSTAGE)*ASZ;
        const __nv_bfloat16* Bs = Bsm + (kt%NSTAGE)*BSZ;
        #pragma unroll
        for (int ks = 0; ks < WBK; ks += 16) {
            wmma::fragment<wmma::matrix_a, 16,16,16, __nv_bfloat16, wmma::row_major> af[4];
            wmma::fragment<wmma::matrix_b, 16,16,16, __nv_bfloat16, wmma::col_major> bf[NFRAG];
            #pragma unroll
            for (int i = 0; i < 4; i++)
                wmma::load_matrix_sync(af[i], &As[(wm*64 + i*16)*WPITCH + ks], WPITCH);
            #pragma unroll
            for (int j = 0; j < NFRAG; j++)
                wmma::load_matrix_sync(bf[j], &Bs[(wn*16*NFRAG + j*16)*WPITCH + ks], WPITCH);
            #pragma unroll
            for (int i = 0; i < 4; i++)
                #pragma unroll
                for (int j = 0; j < NFRAG; j++)
                    wmma::mma_sync(acc[i][j], af[i], bf[j], acc[i][j]);
        }
    }

    #pragma unroll
    for (int i = 0; i < 4; i++) {
        int m = m0 + wm*64 + i*16;
        #pragma unroll
        for (int j = 0; j < NFRAG; j++) {
            int n = n0 + wn*16*NFRAG + j*16;
            if (mode == 1) {
                wmma::fragment<wmma::accumulator, 16,16,16, float> rf;
                wmma::load_matrix_sync(rf, R + (size_t)m*ldr + n, ldr, wmma::mem_row_major);
                #pragma unroll
                for (int t = 0; t < acc[i][j].num_elements; t++)
                    acc[i][j].x[t] += rf.x[t];
            }
            wmma::store_matrix_sync(C + (size_t)m*ldc + n, acc[i][j], ldc, wmma::mem_row_major);
        }
    }
}

#define WMMA_SMEM_W (NSTAGE*(ASZ + 256*WPITCH)*2)   // NFRAG=4: 122880 B
#define WMMA_SMEM_N (NSTAGE*(ASZ + 128*WPITCH)*2)   // NFRAG=2: 81920 B

// ---------------- LayerNorm -> bf16 directly ---------------------------------
__global__ void ln_kernel(const float* __restrict__ x, const float* __restrict__ g,
                          const float* __restrict__ b, __nv_bfloat16* __restrict__ xn2)
{
    int row = blockIdx.x;
    int tid = threadIdx.x;
    const float* xr = x + (size_t)row*DMODEL;
    float v[4];
    float s1 = 0.f, s2 = 0.f;
    #pragma unroll
    for (int i = 0; i < 4; i++) {
        v[i] = xr[tid + 256*i];
        s1 += v[i];
        s2 += v[i]*v[i];
    }
    __shared__ float sh1[8], sh2[8];
    #pragma unroll
    for (int o = 16; o; o >>= 1) {
        s1 += __shfl_xor_sync(0xffffffffu, s1, o);
        s2 += __shfl_xor_sync(0xffffffffu, s2, o);
    }
    if ((tid & 31) == 0) { sh1[tid>>5] = s1; sh2[tid>>5] = s2; }
    __syncthreads();
    if (tid < 32) {
        float a = (tid < 8) ? sh1[tid] : 0.f;
        float c = (tid < 8) ? sh2[tid] : 0.f;
        #pragma unroll
        for (int o = 4; o; o >>= 1) {
            a += __shfl_xor_sync(0xffffffffu, a, o);
            c += __shfl_xor_sync(0xffffffffu, c, o);
        }
        if (tid == 0) { sh1[0] = a; sh2[0] = c; }
    }
    __syncthreads();
    float mu  = sh1[0] * (1.f/DMODEL);
    float var = sh2[0] * (1.f/DMODEL) - mu*mu;
    float r   = rsqrtf(var + 1e-5f);
    __nv_bfloat16* o = xn2 + (size_t)row*DMODEL;
    #pragma unroll
    for (int i = 0; i < 4; i++) {
        int c = tid + 256*i;
        o[c] = __float2bfloat16((v[i]-mu)*r*g[c] + b[c]);
    }
}

// ---------------- SGEMM NT (scalar FFMA) — dt_proj --------------------------
#define BM 128
#define BN 128
#define BKT 8

__global__ __launch_bounds__(256) void sgemm_nt(
    const float* __restrict__ A, int lda,
    const float* __restrict__ B, int ldb,
    float* __restrict__ C, int ldc,
    const float* __restrict__ R, int ldr,
    const float* __restrict__ bias,
    int M, int N, int K, int mode)
{
    __shared__ float As[BKT][BM+4];
    __shared__ float Bs[BKT][BN+4];

    int tid = threadIdx.x;
    int tx  = tid & 15;
    int ty  = tid >> 4;
    int m0  = blockIdx.y * BM;
    int n0  = blockIdx.x * BN;

    int lrow = tid >> 1;
    int lk4  = (tid & 1) * 4;

    float acc[8][8];
    #pragma unroll
    for (int i = 0; i < 8; i++)
        #pragma unroll
        for (int j = 0; j < 8; j++) acc[i][j] = 0.f;

    for (int k0 = 0; k0 < K; k0 += BKT) {
        float4 a = make_float4(0.f,0.f,0.f,0.f);
        int am = m0 + lrow;
        if (am < M) a = *reinterpret_cast<const float4*>(A + (size_t)am*lda + k0 + lk4);
        As[lk4+0][lrow] = a.x; As[lk4+1][lrow] = a.y;
        As[lk4+2][lrow] = a.z; As[lk4+3][lrow] = a.w;

        float4 bv = make_float4(0.f,0.f,0.f,0.f);
        int bn = n0 + lrow;
        if (bn < N) bv = *reinterpret_cast<const float4*>(B + (size_t)bn*ldb + k0 + lk4);
        Bs[lk4+0][lrow] = bv.x; Bs[lk4+1][lrow] = bv.y;
        Bs[lk4+2][lrow] = bv.z; Bs[lk4+3][lrow] = bv.w;

        __syncthreads();

        #pragma unroll
        for (int kk = 0; kk < BKT; kk++) {
            float ra[8], rb[8];
            #pragma unroll
            for (int i = 0; i < 4; i++) {
                ra[i]   = As[kk][ty*4 + i];
                ra[i+4] = As[kk][64 + ty*4 + i];
                rb[i]   = Bs[kk][tx*4 + i];
                rb[i+4] = Bs[kk][64 + tx*4 + i];
            }
            #pragma unroll
            for (int i = 0; i < 8; i++)
                #pragma unroll
                for (int j = 0; j < 8; j++)
                    acc[i][j] = fmaf(ra[i], rb[j], acc[i][j]);
        }
        __syncthreads();
    }

    #pragma unroll
    for (int i = 0; i < 8; i++) {
        int m = m0 + ((i < 4) ? (ty*4 + i) : (64 + ty*4 + i - 4));
        if (m >= M) continue;
        float bm = (mode == 3) ? bias[m] : 0.f;
        #pragma unroll
        for (int j = 0; j < 8; j++) {
            int n = n0 + ((j < 4) ? (tx*4 + j) : (64 + tx*4 + j - 4));
            if (n < N) {
                float val = acc[i][j];
                if (mode == 1) {
                    val += R[(size_t)m*ldr + n];
                } else if (mode == 3) {
                    float v = val + bm;
                    val = (v > 20.f) ? v : __logf(1.f + __expf(v));
                }
                C[(size_t)m*ldc + n] = val;
            }
        }
    }
}

// ---------------- x_proj tall-skinny GEMM, split-K --------------------------
#define XP_BM 16
#define XP_BK 32
#define XP_BSROW 98

__global__ __launch_bounds__(256) void xproj_kernel(
    const float* __restrict__ u, const float* __restrict__ w, float* __restrict__ part)
{
    __shared__ float As[XP_BK][XP_BM+1];
    __shared__ float Bs[XP_BK][XP_BSROW];

    int tid  = threadIdx.x;
    int m0   = blockIdx.x * XP_BM;
    int kc   = blockIdx.y;
    int kbeg = kc * (DINNER/XP_KSPLIT);
    int kend = kbeg + (DINNER/XP_KSPLIT);
    int r    = tid >> 4;
    int cg   = tid & 15;

    ull acc[2][3];
    #pragma unroll
    for (int p = 0; p < 2; p++)
        #pragma unroll
        for (int j = 0; j < 3; j++) acc[p][j] = 0ull;

    for (int k0 = kbeg; k0 < kend; k0 += XP_BK) {
        #pragma unroll
        for (int e = tid; e < XP_BM*XP_BK; e += 256) {
            int k = e & 31, m = e >> 5;
            As[k][m] = u[(size_t)(m0+m)*DINNER + k0 + k];
        }
        #pragma unroll
        for (int e = tid; e < XPROJ_OUT*XP_BK; e += 256) {
            int k = e & 31, n = e >> 5;
            Bs[k][n] = w[(size_t)n*DINNER + k0 + k];
        }
        __syncthreads();
        #pragma unroll
        for (int kk = 0; kk < XP_BK; kk += 2) {
            ull a0 = pack_dup(As[kk  ][r]);
            ull a1 = pack_dup(As[kk+1][r]);
            const ull* b0 = reinterpret_cast<const ull*>(&Bs[kk  ][cg*6]);
            const ull* b1 = reinterpret_cast<const ull*>(&Bs[kk+1][cg*6]);
            ffma2(acc[0][0], a0, b0[0]);
            ffma2(acc[0][1], a0, b0[1]);
            ffma2(acc[0][2], a0, b0[2]);
            ffma2(acc[1][0], a1, b1[0]);
            ffma2(acc[1][1], a1, b1[1]);
            ffma2(acc[1][2], a1, b1[2]);
        }
        __syncthreads();
    }

    float* o = part + (size_t)kc*ROWS*XPROJ_OUT + (size_t)(m0 + r)*XPROJ_OUT + cg*6;
    #pragma unroll
    for (int j = 0; j < 3; j++) {
        float2 v0 = unpack2(acc[0][j]);
        float2 v1 = unpack2(acc[1][j]);
        v0.x += v1.x; v0.y += v1.y;
        *reinterpret_cast<float2*>(o + 2*j) = v0;
    }
}

__global__ void xpart_reduce(const float* __restrict__ part, float* __restrict__ xdbl)
{
    int i = blockIdx.x*blockDim.x + threadIdx.x;
    if (i >= ROWS*XPROJ_OUT) return;
    const int S = ROWS*XPROJ_OUT;
    xdbl[i] = (part[i] + part[i+S]) + (part[i+2*S] + part[i+3*S]);
}

// ---------------- causal conv1d + SiLU, coalesced u and u^T -----------------
__global__ __launch_bounds__(256) void conv_silu_kernel(
    const float* __restrict__ xz, const float* __restrict__ w,
    const float* __restrict__ bias, float* __restrict__ u, float* __restrict__ uT)
{
    __shared__ float s[32][33];
    int tid  = threadIdx.x;
    int ld   = tid & 31;
    int lr   = tid >> 5;
    int d0   = blockIdx.x * 32;
    int row0 = blockIdx.y * 32;
    int d    = d0 + ld;

    float w0 = w[d*DCONV+0], w1 = w[d*DCONV+1], w2 = w[d*DCONV+2], w3 = w[d*DCONV+3];
    float bs = bias[d];

    #pragma unroll
    for (int i = 0; i < 4; i++) {
        int row = row0 + lr + 8*i;
        int l   = row % SEQ;
        const float* base = xz + (size_t)row*(2*DINNER) + d;
        float acc = bs + base[0] * w3;
        if (l >= 1) acc += base[-(ptrdiff_t)(2*DINNER)]   * w2;
        if (l >= 2) acc += base[-(ptrdiff_t)(4*DINNER)]   * w1;
        if (l >= 3) acc += base[-(ptrdiff_t)(6*DINNER)]   * w0;
        float sig = 1.f / (1.f + __expf(-acc));
        float val = acc * sig;
        u[(size_t)row*DINNER + d] = val;
        s[ld][lr + 8*i] = val;
    }
    __syncthreads();
    #pragma unroll
    for (int i = 0; i < 4; i++) {
        int wd = lr + 8*i;
        uT[(size_t)(d0 + wd)*ROWS + row0 + ld] = s[wd][ld];
    }
}

// ---------------- selective scan v2: smem-staged, double-buffered -----------
#define SCT 32

__global__ __launch_bounds__(256) void scan_kernel(
    const float* __restrict__ deltaT, const float* __restrict__ uT,
    const float* __restrict__ xdbl, const float* __restrict__ xz,
    const float* __restrict__ A_log, const float* __restrict__ Dskip,
    __nv_bfloat16* __restrict__ yg2)
{
    __shared__ __align__(16) float sBC[2][SCT][32];
    __shared__ __align__(16) float sdt[2][16][SCT];
    __shared__ __align__(16) float sut[2][16][SCT];
    __shared__ __align__(16) float szT[2][SCT][16];
    __shared__ float sy[16][SCT+1];

    int tid  = threadIdx.x;
    int warp = tid >> 5;
    int lane = tid & 31;
    int half = lane >> 4;
    int n    = lane & 15;
    int ch   = warp*2 + half;
    int c0   = blockIdx.x * 16;
    int b    = c0 / DINNER;
    int dbas = c0 % DINNER;
    int d    = dbas + ch;

    float A  = -__expf(A_log[d*DSTATE + n]);
    float Dd = Dskip[d];
    float h  = 0.f;

    const float* xsrc = xdbl + (size_t)b*SEQ*XPROJ_OUT;
    const float* zsrc = xz   + (size_t)b*SEQ*(2*DINNER) + DINNER + dbas;

    auto stage = [&](int buf, int t0) {
        for (int e = tid; e < SCT*8; e += 256) {
            int t = e >> 3, q = e & 7;
            cp_async16(&sBC[buf][t][q*4], xsrc + (size_t)(t0+t)*XPROJ_OUT + DTRANK + q*4);
        }
        for (int e = tid; e < 16*8; e += 256) {
            int cc = e >> 3, q = e & 7;
            cp_async16(&sdt[buf][cc][q*4],
                       deltaT + (size_t)(dbas+cc)*ROWS + b*SEQ + t0 + q*4);
            cp_async16(&sut[buf][cc][q*4],
                       uT + (size_t)(dbas+cc)*ROWS + b*SEQ + t0 + q*4);
        }
        for (int e = tid; e < SCT*4; e += 256) {
            int t = e >> 2, q = e & 3;
            cp_async16(&szT[buf][t][q*4], zsrc + (size_t)(t0+t)*(2*DINNER) + q*4);
        }
        CP_COMMIT();
    };

    const int NCH = SEQ / SCT;
    stage(0, 0);

    for (int j = 0; j < NCH; j++) {
        int buf = j & 1;
        if (j + 1 < NCH) { stage(buf ^ 1, (j+1)*SCT); CP_WAITG(1); }
        else             { CP_WAITG(0); }
        __syncthreads();

        #pragma unroll 4
        for (int i = 0; i < SCT; i++) {
            float dt = sdt[buf][ch][i];
            float ut = sut[buf][ch][i];
            float Bn = sBC[buf][i][n];
            float Cn = sBC[buf][i][16+n];
            float dA = __expf(dt * A);
            h = fmaf(dA, h, dt*ut*Bn);
            float p = h * Cn;
            p += __shfl_xor_sync(0xffffffffu, p, 8);
            p += __shfl_xor_sync(0xffffffffu, p, 4);
            p += __shfl_xor_sync(0xffffffffu, p, 2);
            p += __shfl_xor_sync(0xffffffffu, p, 1);
            if (n == 0) sy[ch][i] = fmaf(ut, Dd, p);
        }
        __syncthreads();

        int t0 = j*SCT;
        #pragma unroll
        for (int e = tid; e < 16*SCT; e += 256) {
            int t = e >> 4, cc = e & 15;
            float val = sy[cc][t];
            float z   = szT[buf][t][cc];
            float sg  = z / (1.f + __expf(-z));
            yg2[(size_t)(b*SEQ + t0 + t)*DINNER + dbas + cc] = __float2bfloat16(val * sg);
        }
        __syncthreads();
    }
}

// ---------------- launch ----------------------------------------------------
extern "C" void kernel_launch(void* const* d_in, const int* in_sizes, int n_in,
                              void* d_out, int out_size)
{
    const float* x      = (const float*)d_in[0];
    const float* ln_g   = (const float*)d_in[1];
    const float* ln_b   = (const float*)d_in[2];
    const float* w_in   = (const float*)d_in[3];
    const float* conv_w = (const float*)d_in[4];
    const float* conv_b = (const float*)d_in[5];
    const float* w_x    = (const float*)d_in[6];
    const float* w_dt   = (const float*)d_in[7];
    const float* b_dt   = (const float*)d_in[8];
    const float* A_log  = (const float*)d_in[9];
    const float* Dsk    = (const float*)d_in[10];
    const float* w_out  = (const float*)d_in[11];
    float* out = (float*)d_out;

    float *xz, *u, *uT, *xdbl, *xpart, *deltaT;
    __nv_bfloat16 *xn2, *win2, *yg2, *wout2;
    cudaGetSymbolAddress((void**)&xz,     g_xz);
    cudaGetSymbolAddress((void**)&u,      g_u);
    cudaGetSymbolAddress((void**)&uT,     g_uT);
    cudaGetSymbolAddress((void**)&xdbl,   g_xdbl);
    cudaGetSymbolAddress((void**)&xpart,  g_xpart);
    cudaGetSymbolAddress((void**)&deltaT, g_deltaT);
    cudaGetSymbolAddress((void**)&xn2,    g_xn2);
    cudaGetSymbolAddress((void**)&win2,   g_win2);
    cudaGetSymbolAddress((void**)&yg2,    g_yg2);
    cudaGetSymbolAddress((void**)&wout2,  g_wout2);

    static int smem_set = 0;
    if (!smem_set) {
        cudaFuncSetAttribute(wmma_nt<4>, cudaFuncAttributeMaxDynamicSharedMemorySize, WMMA_SMEM_W);
        cudaFuncSetAttribute(wmma_nt<2>, cudaFuncAttributeMaxDynamicSharedMemorySize, WMMA_SMEM_N);
        smem_set = 1;
    }

    // 1. layernorm -> xn2 (bf16)
    ln_kernel<<<ROWS, 256>>>(x, ln_g, ln_b, xn2);

    // 2. in_proj (bf16 tensor cores): K = 1024
    cast_kernel<<<(2*DINNER*DMODEL+255)/256, 256>>>(w_in, win2, 2*DINNER*DMODEL);
    {
        dim3 g(2*DINNER/256, ROWS/WBM);
        wmma_nt<4><<<g, 256, WMMA_SMEM_W>>>(xn2, win2, xz, 2*DINNER, nullptr, 0,
                                            ROWS, 2*DINNER, DMODEL, 0);
    }

    // 3. causal depthwise conv + SiLU -> u, u^T
    {
        dim3 g(DINNER/32, ROWS/32);
        conv_silu_kernel<<<g, 256>>>(xz, conv_w, conv_b, u, uT);
    }

    // 4. x_proj (split-K)
    {
        dim3 g(ROWS/XP_BM, XP_KSPLIT);
        xproj_kernel<<<g, 256>>>(u, w_x, xpart);
        xpart_reduce<<<(ROWS*XPROJ_OUT+255)/256, 256>>>(xpart, xdbl);
    }

    // 5. dt_proj TRANSPOSED + fused softplus
    {
        dim3 g(ROWS/BN, DINNER/BM);
        sgemm_nt<<<g, 256>>>(w_dt, DTRANK, xdbl, XPROJ_OUT, deltaT, ROWS,
                             nullptr, 0, b_dt, DINNER, ROWS, DTRANK, 3);
    }

    // 6. selective scan v2 (smem-staged) -> yg2 (bf16, gate fused)
    scan_kernel<<<(BATCH*DINNER)/16, 256>>>(deltaT, uT, xdbl, xz, A_log, Dsk, yg2);

    // 7. out_proj (bf16 tensor cores) + residual: K = 2048
    cast_kernel<<<(DMODEL*DINNER+255)/256, 256>>>(w_out, wout2, DMODEL*DINNER);
    {
        dim3 g(DMODEL/128, ROWS/WBM);
        wmma_nt<2><<<g, 256, WMMA_SMEM_N>>>(yg2, wout2, out, DMODEL, x, DMODEL,
                                            ROWS, DMODEL, DINNER, 1);
    }
}

// round 15
// speedup vs baseline: 6.8049x; 1.1590x over previous
#include <cuda_runtime.h>
#include <cuda_bf16.h>
#include <stdint.h>
#include <math.h>

#define BATCH   2
#define SEQ     1024
#define DMODEL  1024
#define DINNER  2048
#define DTRANK  64
#define DSTATE  16
#define DCONV   4
#define ROWS    (BATCH*SEQ)            // 2048
#define XPROJ_OUT (DTRANK + 2*DSTATE)  // 96

typedef unsigned long long ull;

__device__ __forceinline__ void cp_async16(void* smem, const void* gmem) {
    unsigned s = (unsigned)__cvta_generic_to_shared(smem);
    asm volatile("cp.async.cg.shared.global [%0], [%1], 16;" :: "r"(s), "l"(gmem));
}
#define CP_COMMIT()  asm volatile("cp.async.commit_group;")
#define CP_WAITG(n)  asm volatile("cp.async.wait_group %0;" :: "n"(n))

#include <mma.h>
using namespace nvcuda;

// ---------------- scratch (static device globals; no allocation) ------------
#define XP_KSPLIT 4
__device__ float g_xz    [ROWS*2*DINNER];
__device__ float g_uT    [DINNER*ROWS];
__device__ float g_xdbl  [ROWS*XPROJ_OUT];
__device__ float g_xpart [XP_KSPLIT*ROWS*XPROJ_OUT];
__device__ float g_deltaT[DINNER*ROWS];
// bf16 operands
__device__ __nv_bfloat16 g_xn2  [ROWS*DMODEL];
__device__ __nv_bfloat16 g_win2 [2*DINNER*DMODEL];
__device__ __nv_bfloat16 g_u2   [ROWS*DINNER];
__device__ __nv_bfloat16 g_wx2  [128*DINNER];     // padded 96->128, pad rows stay 0
__device__ __nv_bfloat16 g_yg2  [ROWS*DINNER];
__device__ __nv_bfloat16 g_wout2[DMODEL*DINNER];

// ---------------- cast fp32 -> bf16 ------------------------------------------
__global__ void cast_kernel(const float* __restrict__ X, __nv_bfloat16* __restrict__ Y,
                            int total)
{
    int i = blockIdx.x*blockDim.x + threadIdx.x;
    if (i < total) Y[i] = __float2bfloat16(X[i]);
}

// ---------------- wmma bf16 GEMM NT, 4-stage cp.async pipeline --------------
// C[M,N] = A2[M,K3] @ B2[N,K3]^T; mode: 0 plain, 1 += R
#define WBM 128
#define WBK 32
#define WPITCH 40       // bf16 pitch: 80 bytes
#define NSTAGE 4
#define ASZ (WBM*WPITCH)

template<int NFRAG>
__global__ __launch_bounds__(256) void wmma_nt(
    const __nv_bfloat16* __restrict__ A2, const __nv_bfloat16* __restrict__ B2,
    float* __restrict__ C, int ldc, const float* __restrict__ R, int ldr,
    int M, int N, int K3, int mode)
{
    constexpr int WBN = 64*NFRAG;
    constexpr int BSZ = WBN*WPITCH;

    extern __shared__ __align__(16) __nv_bfloat16 sm[];
    __nv_bfloat16* Asm = sm;
    __nv_bfloat16* Bsm = sm + NSTAGE*ASZ;

    int tid = threadIdx.x;
    int w   = tid >> 5;
    int wm  = w >> 2;
    int wn  = w & 3;
    int m0  = blockIdx.y * WBM;
    int n0  = blockIdx.x * WBN;

    wmma::fragment<wmma::accumulator, 16,16,16, float> acc[4][NFRAG];
    #pragma unroll
    for (int i = 0; i < 4; i++)
        #pragma unroll
        for (int j = 0; j < NFRAG; j++) wmma::fill_fragment(acc[i][j], 0.f);

    auto stage = [&](int s, int k0) {
        __nv_bfloat16* As = Asm + s*ASZ;
        __nv_bfloat16* Bs = Bsm + s*BSZ;
        #pragma unroll
        for (int e = tid; e < WBM*4; e += 256) {
            int row = e >> 2, q = e & 3;
            cp_async16(&As[row*WPITCH + q*8], A2 + (size_t)(m0+row)*K3 + k0 + q*8);
        }
        #pragma unroll
        for (int e = tid; e < WBN*4; e += 256) {
            int row = e >> 2, q = e & 3;
            cp_async16(&Bs[row*WPITCH + q*8], B2 + (size_t)(n0+row)*K3 + k0 + q*8);
        }
        CP_COMMIT();
    };

    int NT = K3 / WBK;
    stage(0, 0);
    if (NT > 1) stage(1, WBK);
    if (NT > 2) stage(2, 2*WBK);

    for (int kt = 0; kt < NT; kt++) {
        __syncthreads();
        if (kt + 3 < NT)      { stage((kt+3)%NSTAGE, (kt+3)*WBK); CP_WAITG(3); }
        else if (kt + 3 == NT) { CP_WAITG(2); }
        else if (kt + 2 == NT) { CP_WAITG(1); }
        else                   { CP_WAITG(0); }
        __syncthreads();

        const __nv_bfloat16* As = Asm + (kt%NSTAGE)*ASZ;
        const __nv_bfloat16* Bs = Bsm + (kt%NSTAGE)*BSZ;
        #pragma unroll
        for (int ks = 0; ks < WBK; ks += 16) {
            wmma::fragment<wmma::matrix_a, 16,16,16, __nv_bfloat16, wmma::row_major> af[4];
            wmma::fragment<wmma::matrix_b, 16,16,16, __nv_bfloat16, wmma::col_major> bf[NFRAG];
            #pragma unroll
            for (int i = 0; i < 4; i++)
                wmma::load_matrix_sync(af[i], &As[(wm*64 + i*16)*WPITCH + ks], WPITCH);
            #pragma unroll
            for (int j = 0; j < NFRAG; j++)
                wmma::load_matrix_sync(bf[j], &Bs[(wn*16*NFRAG + j*16)*WPITCH + ks], WPITCH);
            #pragma unroll
            for (int i = 0; i < 4; i++)
                #pragma unroll
                for (int j = 0; j < NFRAG; j++)
                    wmma::mma_sync(acc[i][j], af[i], bf[j], acc[i][j]);
        }
    }

    #pragma unroll
    for (int i = 0; i < 4; i++) {
        int m = m0 + wm*64 + i*16;
        #pragma unroll
        for (int j = 0; j < NFRAG; j++) {
            int n = n0 + wn*16*NFRAG + j*16;
            if (mode == 1) {
                wmma::fragment<wmma::accumulator, 16,16,16, float> rf;
                wmma::load_matrix_sync(rf, R + (size_t)m*ldr + n, ldr, wmma::mem_row_major);
                #pragma unroll
                for (int t = 0; t < acc[i][j].num_elements; t++)
                    acc[i][j].x[t] += rf.x[t];
            }
            wmma::store_matrix_sync(C + (size_t)m*ldc + n, acc[i][j], ldc, wmma::mem_row_major);
        }
    }
}

#define WMMA_SMEM_W (NSTAGE*(ASZ + 256*WPITCH)*2)   // NFRAG=4: 122880 B
#define WMMA_SMEM_N (NSTAGE*(ASZ + 128*WPITCH)*2)   // NFRAG=2: 81920 B

// ---------------- x_proj wmma split-K: part[kc] = u2 @ wx2^T (N padded 128) --
__global__ __launch_bounds__(256) void wmma_xk(
    const __nv_bfloat16* __restrict__ A2,   // u2 [ROWS][DINNER]
    const __nv_bfloat16* __restrict__ B2,   // wx2 [128][DINNER]
    float* __restrict__ part)
{
    constexpr int WBN = 128;
    constexpr int BSZ = WBN*WPITCH;

    extern __shared__ __align__(16) __nv_bfloat16 sm[];
    __nv_bfloat16* Asm = sm;
    __nv_bfloat16* Bsm = sm + NSTAGE*ASZ;

    int tid  = threadIdx.x;
    int w    = tid >> 5;
    int wm   = w >> 2;
    int wn   = w & 3;
    int m0   = blockIdx.x * WBM;
    int kc   = blockIdx.y;
    int kbeg = kc * (DINNER/XP_KSPLIT);

    wmma::fragment<wmma::accumulator, 16,16,16, float> acc[4][2];
    #pragma unroll
    for (int i = 0; i < 4; i++)
        #pragma unroll
        for (int j = 0; j < 2; j++) wmma::fill_fragment(acc[i][j], 0.f);

    auto stage = [&](int s, int k0) {
        __nv_bfloat16* As = Asm + s*ASZ;
        __nv_bfloat16* Bs = Bsm + s*BSZ;
        #pragma unroll
        for (int e = tid; e < WBM*4; e += 256) {
            int row = e >> 2, q = e & 3;
            cp_async16(&As[row*WPITCH + q*8], A2 + (size_t)(m0+row)*DINNER + k0 + q*8);
        }
        #pragma unroll
        for (int e = tid; e < WBN*4; e += 256) {
            int row = e >> 2, q = e & 3;
            cp_async16(&Bs[row*WPITCH + q*8], B2 + (size_t)row*DINNER + k0 + q*8);
        }
        CP_COMMIT();
    };

    const int NT = (DINNER/XP_KSPLIT)/WBK;   // 16
    stage(0, kbeg); stage(1, kbeg+WBK); stage(2, kbeg+2*WBK);

    for (int kt = 0; kt < NT; kt++) {
        __syncthreads();
        if (kt + 3 < NT)      { stage((kt+3)%NSTAGE, kbeg+(kt+3)*WBK); CP_WAITG(3); }
        else if (kt + 3 == NT) { CP_WAITG(2); }
        else if (kt + 2 == NT) { CP_WAITG(1); }
        else                   { CP_WAITG(0); }
        __syncthreads();

        const __nv_bfloat16* As = Asm + (kt%NSTAGE)*ASZ;
        const __nv_bfloat16* Bs = Bsm + (kt%NSTAGE)*BSZ;
        #pragma unroll
        for (int ks = 0; ks < WBK; ks += 16) {
            wmma::fragment<wmma::matrix_a, 16,16,16, __nv_bfloat16, wmma::row_major> af[4];
            wmma::fragment<wmma::matrix_b, 16,16,16, __nv_bfloat16, wmma::col_major> bf[2];
            #pragma unroll
            for (int i = 0; i < 4; i++)
                wmma::load_matrix_sync(af[i], &As[(wm*64 + i*16)*WPITCH + ks], WPITCH);
            #pragma unroll
            for (int j = 0; j < 2; j++)
                wmma::load_matrix_sync(bf[j], &Bs[(wn*32 + j*16)*WPITCH + ks], WPITCH);
            #pragma unroll
            for (int i = 0; i < 4; i++)
                #pragma unroll
                for (int j = 0; j < 2; j++)
                    wmma::mma_sync(acc[i][j], af[i], bf[j], acc[i][j]);
        }
    }

    float* base = part + (size_t)kc*ROWS*XPROJ_OUT;
    #pragma unroll
    for (int i = 0; i < 4; i++) {
        int m = m0 + wm*64 + i*16;
        #pragma unroll
        for (int j = 0; j < 2; j++) {
            int n = wn*32 + j*16;
            if (n < XPROJ_OUT)
                wmma::store_matrix_sync(base + (size_t)m*XPROJ_OUT + n, acc[i][j],
                                        XPROJ_OUT, wmma::mem_row_major);
        }
    }
}

__global__ void xpart_reduce(const float* __restrict__ part, float* __restrict__ xdbl)
{
    int i = blockIdx.x*blockDim.x + threadIdx.x;
    if (i >= ROWS*XPROJ_OUT) return;
    const int S = ROWS*XPROJ_OUT;
    xdbl[i] = (part[i] + part[i+S]) + (part[i+2*S] + part[i+3*S]);
}

// ---------------- LayerNorm -> bf16 directly ---------------------------------
__global__ void ln_kernel(const float* __restrict__ x, const float* __restrict__ g,
                          const float* __restrict__ b, __nv_bfloat16* __restrict__ xn2)
{
    int row = blockIdx.x;
    int tid = threadIdx.x;
    const float* xr = x + (size_t)row*DMODEL;
    float v[4];
    float s1 = 0.f, s2 = 0.f;
    #pragma unroll
    for (int i = 0; i < 4; i++) {
        v[i] = xr[tid + 256*i];
        s1 += v[i];
        s2 += v[i]*v[i];
    }
    __shared__ float sh1[8], sh2[8];
    #pragma unroll
    for (int o = 16; o; o >>= 1) {
        s1 += __shfl_xor_sync(0xffffffffu, s1, o);
        s2 += __shfl_xor_sync(0xffffffffu, s2, o);
    }
    if ((tid & 31) == 0) { sh1[tid>>5] = s1; sh2[tid>>5] = s2; }
    __syncthreads();
    if (tid < 32) {
        float a = (tid < 8) ? sh1[tid] : 0.f;
        float c = (tid < 8) ? sh2[tid] : 0.f;
        #pragma unroll
        for (int o = 4; o; o >>= 1) {
            a += __shfl_xor_sync(0xffffffffu, a, o);
            c += __shfl_xor_sync(0xffffffffu, c, o);
        }
        if (tid == 0) { sh1[0] = a; sh2[0] = c; }
    }
    __syncthreads();
    float mu  = sh1[0] * (1.f/DMODEL);
    float var = sh2[0] * (1.f/DMODEL) - mu*mu;
    float r   = rsqrtf(var + 1e-5f);
    __nv_bfloat16* o = xn2 + (size_t)row*DMODEL;
    #pragma unroll
    for (int i = 0; i < 4; i++) {
        int c = tid + 256*i;
        o[c] = __float2bfloat16((v[i]-mu)*r*g[c] + b[c]);
    }
}

// ---------------- SGEMM NT (scalar FFMA) — dt_proj --------------------------
#define BM 128
#define BN 128
#define BKT 8

__global__ __launch_bounds__(256) void sgemm_nt(
    const float* __restrict__ A, int lda,
    const float* __restrict__ B, int ldb,
    float* __restrict__ C, int ldc,
    const float* __restrict__ R, int ldr,
    const float* __restrict__ bias,
    int M, int N, int K, int mode)
{
    __shared__ float As[BKT][BM+4];
    __shared__ float Bs[BKT][BN+4];

    int tid = threadIdx.x;
    int tx  = tid & 15;
    int ty  = tid >> 4;
    int m0  = blockIdx.y * BM;
    int n0  = blockIdx.x * BN;

    int lrow = tid >> 1;
    int lk4  = (tid & 1) * 4;

    float acc[8][8];
    #pragma unroll
    for (int i = 0; i < 8; i++)
        #pragma unroll
        for (int j = 0; j < 8; j++) acc[i][j] = 0.f;

    for (int k0 = 0; k0 < K; k0 += BKT) {
        float4 a = make_float4(0.f,0.f,0.f,0.f);
        int am = m0 + lrow;
        if (am < M) a = *reinterpret_cast<const float4*>(A + (size_t)am*lda + k0 + lk4);
        As[lk4+0][lrow] = a.x; As[lk4+1][lrow] = a.y;
        As[lk4+2][lrow] = a.z; As[lk4+3][lrow] = a.w;

        float4 bv = make_float4(0.f,0.f,0.f,0.f);
        int bn = n0 + lrow;
        if (bn < N) bv = *reinterpret_cast<const float4*>(B + (size_t)bn*ldb + k0 + lk4);
        Bs[lk4+0][lrow] = bv.x; Bs[lk4+1][lrow] = bv.y;
        Bs[lk4+2][lrow] = bv.z; Bs[lk4+3][lrow] = bv.w;

        __syncthreads();

        #pragma unroll
        for (int kk = 0; kk < BKT; kk++) {
            float ra[8], rb[8];
            #pragma unroll
            for (int i = 0; i < 4; i++) {
                ra[i]   = As[kk][ty*4 + i];
                ra[i+4] = As[kk][64 + ty*4 + i];
                rb[i]   = Bs[kk][tx*4 + i];
                rb[i+4] = Bs[kk][64 + tx*4 + i];
            }
            #pragma unroll
            for (int i = 0; i < 8; i++)
                #pragma unroll
                for (int j = 0; j < 8; j++)
                    acc[i][j] = fmaf(ra[i], rb[j], acc[i][j]);
        }
        __syncthreads();
    }

    #pragma unroll
    for (int i = 0; i < 8; i++) {
        int m = m0 + ((i < 4) ? (ty*4 + i) : (64 + ty*4 + i - 4));
        if (m >= M) continue;
        float bm = (mode == 3) ? bias[m] : 0.f;
        #pragma unroll
        for (int j = 0; j < 8; j++) {
            int n = n0 + ((j < 4) ? (tx*4 + j) : (64 + tx*4 + j - 4));
            if (n < N) {
                float val = acc[i][j];
                if (mode == 1) {
                    val += R[(size_t)m*ldr + n];
                } else if (mode == 3) {
                    float v = val + bm;
                    val = (v > 20.f) ? v : __logf(1.f + __expf(v));
                }
                C[(size_t)m*ldc + n] = val;
            }
        }
    }
}

// ---------------- causal conv1d + SiLU: u (bf16) + u^T (fp32) ---------------
__global__ __launch_bounds__(256) void conv_silu_kernel(
    const float* __restrict__ xz, const float* __restrict__ w,
    const float* __restrict__ bias, __nv_bfloat16* __restrict__ u2,
    float* __restrict__ uT)
{
    __shared__ float s[32][33];
    int tid  = threadIdx.x;
    int ld   = tid & 31;
    int lr   = tid >> 5;
    int d0   = blockIdx.x * 32;
    int row0 = blockIdx.y * 32;
    int d    = d0 + ld;

    float w0 = w[d*DCONV+0], w1 = w[d*DCONV+1], w2 = w[d*DCONV+2], w3 = w[d*DCONV+3];
    float bs = bias[d];

    #pragma unroll
    for (int i = 0; i < 4; i++) {
        int row = row0 + lr + 8*i;
        int l   = row % SEQ;
        const float* base = xz + (size_t)row*(2*DINNER) + d;
        float acc = bs + base[0] * w3;
        if (l >= 1) acc += base[-(ptrdiff_t)(2*DINNER)]   * w2;
        if (l >= 2) acc += base[-(ptrdiff_t)(4*DINNER)]   * w1;
        if (l >= 3) acc += base[-(ptrdiff_t)(6*DINNER)]   * w0;
        float sig = 1.f / (1.f + __expf(-acc));
        float val = acc * sig;
        u2[(size_t)row*DINNER + d] = __float2bfloat16(val);
        s[ld][lr + 8*i] = val;
    }
    __syncthreads();
    #pragma unroll
    for (int i = 0; i < 4; i++) {
        int wd = lr + 8*i;
        uT[(size_t)(d0 + wd)*ROWS + row0 + ld] = s[wd][ld];
    }
}

// ---------------- selective scan v2: smem-staged, double-buffered -----------
#define SCT 32

__global__ __launch_bounds__(256) void scan_kernel(
    const float* __restrict__ deltaT, const float* __restrict__ uT,
    const float* __restrict__ xdbl, const float* __restrict__ xz,
    const float* __restrict__ A_log, const float* __restrict__ Dskip,
    __nv_bfloat16* __restrict__ yg2)
{
    __shared__ __align__(16) float sBC[2][SCT][32];
    __shared__ __align__(16) float sdt[2][16][SCT];
    __shared__ __align__(16) float sut[2][16][SCT];
    __shared__ __align__(16) float szT[2][SCT][16];
    __shared__ float sy[16][SCT+1];

    int tid  = threadIdx.x;
    int warp = tid >> 5;
    int lane = tid & 31;
    int half = lane >> 4;
    int n    = lane & 15;
    int ch   = warp*2 + half;
    int c0   = blockIdx.x * 16;
    int b    = c0 / DINNER;
    int dbas = c0 % DINNER;
    int d    = dbas + ch;

    float A  = -__expf(A_log[d*DSTATE + n]);
    float Dd = Dskip[d];
    float h  = 0.f;

    const float* xsrc = xdbl + (size_t)b*SEQ*XPROJ_OUT;
    const float* zsrc = xz   + (size_t)b*SEQ*(2*DINNER) + DINNER + dbas;

    auto stage = [&](int buf, int t0) {
        for (int e = tid; e < SCT*8; e += 256) {
            int t = e >> 3, q = e & 7;
            cp_async16(&sBC[buf][t][q*4], xsrc + (size_t)(t0+t)*XPROJ_OUT + DTRANK + q*4);
        }
        for (int e = tid; e < 16*8; e += 256) {
            int cc = e >> 3, q = e & 7;
            cp_async16(&sdt[buf][cc][q*4],
                       deltaT + (size_t)(dbas+cc)*ROWS + b*SEQ + t0 + q*4);
            cp_async16(&sut[buf][cc][q*4],
                       uT + (size_t)(dbas+cc)*ROWS + b*SEQ + t0 + q*4);
        }
        for (int e = tid; e < SCT*4; e += 256) {
            int t = e >> 2, q = e & 3;
            cp_async16(&szT[buf][t][q*4], zsrc + (size_t)(t0+t)*(2*DINNER) + q*4);
        }
        CP_COMMIT();
    };

    const int NCH = SEQ / SCT;
    stage(0, 0);

    for (int j = 0; j < NCH; j++) {
        int buf = j & 1;
        if (j + 1 < NCH) { stage(buf ^ 1, (j+1)*SCT); CP_WAITG(1); }
        else             { CP_WAITG(0); }
        __syncthreads();

        #pragma unroll 4
        for (int i = 0; i < SCT; i++) {
            float dt = sdt[buf][ch][i];
            float ut = sut[buf][ch][i];
            float Bn = sBC[buf][i][n];
            float Cn = sBC[buf][i][16+n];
            float dA = __expf(dt * A);
            h = fmaf(dA, h, dt*ut*Bn);
            float p = h * Cn;
            p += __shfl_xor_sync(0xffffffffu, p, 8);
            p += __shfl_xor_sync(0xffffffffu, p, 4);
            p += __shfl_xor_sync(0xffffffffu, p, 2);
            p += __shfl_xor_sync(0xffffffffu, p, 1);
            if (n == 0) sy[ch][i] = fmaf(ut, Dd, p);
        }
        __syncthreads();

        int t0 = j*SCT;
        #pragma unroll
        for (int e = tid; e < 16*SCT; e += 256) {
            int t = e >> 4, cc = e & 15;
            float val = sy[cc][t];
            float z   = szT[buf][t][cc];
            float sg  = z / (1.f + __expf(-z));
            yg2[(size_t)(b*SEQ + t0 + t)*DINNER + dbas + cc] = __float2bfloat16(val * sg);
        }
        __syncthreads();
    }
}

// ---------------- launch ----------------------------------------------------
extern "C" void kernel_launch(void* const* d_in, const int* in_sizes, int n_in,
                              void* d_out, int out_size)
{
    const float* x      = (const float*)d_in[0];
    const float* ln_g   = (const float*)d_in[1];
    const float* ln_b   = (const float*)d_in[2];
    const float* w_in   = (const float*)d_in[3];
    const float* conv_w = (const float*)d_in[4];
    const float* conv_b = (const float*)d_in[5];
    const float* w_x    = (const float*)d_in[6];
    const float* w_dt   = (const float*)d_in[7];
    const float* b_dt   = (const float*)d_in[8];
    const float* A_log  = (const float*)d_in[9];
    const float* Dsk    = (const float*)d_in[10];
    const float* w_out  = (const float*)d_in[11];
    float* out = (float*)d_out;

    float *xz, *uT, *xdbl, *xpart, *deltaT;
    __nv_bfloat16 *xn2, *win2, *u2, *wx2, *yg2, *wout2;
    cudaGetSymbolAddress((void**)&xz,     g_xz);
    cudaGetSymbolAddress((void**)&uT,     g_uT);
    cudaGetSymbolAddress((void**)&xdbl,   g_xdbl);
    cudaGetSymbolAddress((void**)&xpart,  g_xpart);
    cudaGetSymbolAddress((void**)&deltaT, g_deltaT);
    cudaGetSymbolAddress((void**)&xn2,    g_xn2);
    cudaGetSymbolAddress((void**)&win2,   g_win2);
    cudaGetSymbolAddress((void**)&u2,     g_u2);
    cudaGetSymbolAddress((void**)&wx2,    g_wx2);
    cudaGetSymbolAddress((void**)&yg2,    g_yg2);
    cudaGetSymbolAddress((void**)&wout2,  g_wout2);

    static int smem_set = 0;
    if (!smem_set) {
        cudaFuncSetAttribute(wmma_nt<4>, cudaFuncAttributeMaxDynamicSharedMemorySize, WMMA_SMEM_W);
        cudaFuncSetAttribute(wmma_nt<2>, cudaFuncAttributeMaxDynamicSharedMemorySize, WMMA_SMEM_N);
        cudaFuncSetAttribute(wmma_xk,    cudaFuncAttributeMaxDynamicSharedMemorySize, WMMA_SMEM_N);
        smem_set = 1;
    }

    // 1. layernorm -> xn2 (bf16)
    ln_kernel<<<ROWS, 256>>>(x, ln_g, ln_b, xn2);

    // 2. in_proj (bf16 tensor cores): K = 1024
    cast_kernel<<<(2*DINNER*DMODEL+255)/256, 256>>>(w_in, win2, 2*DINNER*DMODEL);
    {
        dim3 g(2*DINNER/256, ROWS/WBM);
        wmma_nt<4><<<g, 256, WMMA_SMEM_W>>>(xn2, win2, xz, 2*DINNER, nullptr, 0,
                                            ROWS, 2*DINNER, DMODEL, 0);
    }

    // 3. causal depthwise conv + SiLU -> u2 (bf16), u^T (fp32)
    {
        dim3 g(DINNER/32, ROWS/32);
        conv_silu_kernel<<<g, 256>>>(xz, conv_w, conv_b, u2, uT);
    }

    // 4. x_proj on tensor cores (split-K, N padded to 128)
    cast_kernel<<<(XPROJ_OUT*DINNER+255)/256, 256>>>(w_x, wx2, XPROJ_OUT*DINNER);
    {
        dim3 g(ROWS/WBM, XP_KSPLIT);
        wmma_xk<<<g, 256, WMMA_SMEM_N>>>(u2, wx2, xpart);
        xpart_reduce<<<(ROWS*XPROJ_OUT+255)/256, 256>>>(xpart, xdbl);
    }

    // 5. dt_proj TRANSPOSED + fused softplus
    {
        dim3 g(ROWS/BN, DINNER/BM);
        sgemm_nt<<<g, 256>>>(w_dt, DTRANK, xdbl, XPROJ_OUT, deltaT, ROWS,
                             nullptr, 0, b_dt, DINNER, ROWS, DTRANK, 3);
    }

    // 6. selective scan v2 (smem-staged) -> yg2 (bf16, gate fused)
    scan_kernel<<<(BATCH*DINNER)/16, 256>>>(deltaT, uT, xdbl, xz, A_log, Dsk, yg2);

    // 7. out_proj (bf16 tensor cores) + residual: K = 2048
    cast_kernel<<<(DMODEL*DINNER+255)/256, 256>>>(w_out, wout2, DMODEL*DINNER);
    {
        dim3 g(DMODEL/128, ROWS/WBM);
        wmma_nt<2><<<g, 256, WMMA_SMEM_N>>>(yg2, wout2, out, DMODEL, x, DMODEL,
                                            ROWS, DMODEL, DINNER, 1);
    }
}

// round 16
// speedup vs baseline: 6.9664x; 1.0237x over previous
#include <cuda_runtime.h>
#include <cuda_bf16.h>
#include <stdint.h>
#include <math.h>

#define BATCH   2
#define SEQ     1024
#define DMODEL  1024
#define DINNER  2048
#define DTRANK  64
#define DSTATE  16
#define DCONV   4
#define ROWS    (BATCH*SEQ)            // 2048
#define XPROJ_OUT (DTRANK + 2*DSTATE)  // 96

typedef unsigned long long ull;

__device__ __forceinline__ void cp_async16(void* smem, const void* gmem) {
    unsigned s = (unsigned)__cvta_generic_to_shared(smem);
    asm volatile("cp.async.cg.shared.global [%0], [%1], 16;" :: "r"(s), "l"(gmem));
}
#define CP_COMMIT()  asm volatile("cp.async.commit_group;")
#define CP_WAITG(n)  asm volatile("cp.async.wait_group %0;" :: "n"(n))

#include <mma.h>
using namespace nvcuda;

// ---------------- scratch (static device globals; no allocation) ------------
#define XP_KSPLIT 4
__device__ float g_xz    [ROWS*2*DINNER];
__device__ float g_uT    [DINNER*ROWS];
__device__ float g_xdbl  [ROWS*XPROJ_OUT];
__device__ float g_xpart [XP_KSPLIT*ROWS*XPROJ_OUT];
__device__ float g_deltaT[DINNER*ROWS];
// bf16 operands
__device__ __nv_bfloat16 g_xn2   [ROWS*DMODEL];
__device__ __nv_bfloat16 g_win2  [2*DINNER*DMODEL];
__device__ __nv_bfloat16 g_u2    [ROWS*DINNER];
__device__ __nv_bfloat16 g_wx2   [128*DINNER];     // padded 96->128, pad rows stay 0
__device__ __nv_bfloat16 g_wdt2  [DINNER*DTRANK];
__device__ __nv_bfloat16 g_xdbl64[ROWS*DTRANK];
__device__ __nv_bfloat16 g_yg2   [ROWS*DINNER];
__device__ __nv_bfloat16 g_wout2 [DMODEL*DINNER];

// ---------------- cast fp32 -> bf16 ------------------------------------------
__global__ void cast_kernel(const float* __restrict__ X, __nv_bfloat16* __restrict__ Y,
                            int total)
{
    int i = blockIdx.x*blockDim.x + threadIdx.x;
    if (i < total) Y[i] = __float2bfloat16(X[i]);
}

// ---------------- wmma bf16 GEMM NT, 4-stage cp.async pipeline --------------
// C[M,N] = A2[M,K3] @ B2[N,K3]^T
// mode: 0 plain, 1 += R (residual), 3 softplus(v + bias[m]) via smem epilogue
#define WBM 128
#define WBK 32
#define WPITCH 40       // bf16 pitch: 80 bytes
#define NSTAGE 4
#define ASZ (WBM*WPITCH)

template<int NFRAG>
__global__ __launch_bounds__(256) void wmma_nt(
    const __nv_bfloat16* __restrict__ A2, const __nv_bfloat16* __restrict__ B2,
    float* __restrict__ C, int ldc, const float* __restrict__ R, int ldr,
    const float* __restrict__ bias,
    int M, int N, int K3, int mode)
{
    constexpr int WBN = 64*NFRAG;
    constexpr int BSZ = WBN*WPITCH;

    extern __shared__ __align__(16) __nv_bfloat16 sm[];
    __nv_bfloat16* Asm = sm;
    __nv_bfloat16* Bsm = sm + NSTAGE*ASZ;

    int tid = threadIdx.x;
    int w   = tid >> 5;
    int wm  = w >> 2;
    int wn  = w & 3;
    int m0  = blockIdx.y * WBM;
    int n0  = blockIdx.x * WBN;

    wmma::fragment<wmma::accumulator, 16,16,16, float> acc[4][NFRAG];
    #pragma unroll
    for (int i = 0; i < 4; i++)
        #pragma unroll
        for (int j = 0; j < NFRAG; j++) wmma::fill_fragment(acc[i][j], 0.f);

    auto stage = [&](int s, int k0) {
        __nv_bfloat16* As = Asm + s*ASZ;
        __nv_bfloat16* Bs = Bsm + s*BSZ;
        #pragma unroll
        for (int e = tid; e < WBM*4; e += 256) {
            int row = e >> 2, q = e & 3;
            cp_async16(&As[row*WPITCH + q*8], A2 + (size_t)(m0+row)*K3 + k0 + q*8);
        }
        #pragma unroll
        for (int e = tid; e < WBN*4; e += 256) {
            int row = e >> 2, q = e & 3;
            cp_async16(&Bs[row*WPITCH + q*8], B2 + (size_t)(n0+row)*K3 + k0 + q*8);
        }
        CP_COMMIT();
    };

    int NT = K3 / WBK;
    stage(0, 0);
    if (NT > 1) stage(1, WBK);
    if (NT > 2) stage(2, 2*WBK);

    for (int kt = 0; kt < NT; kt++) {
        __syncthreads();
        if (kt + 3 < NT)      { stage((kt+3)%NSTAGE, (kt+3)*WBK); CP_WAITG(3); }
        else if (kt + 3 == NT) { CP_WAITG(2); }
        else if (kt + 2 == NT) { CP_WAITG(1); }
        else                   { CP_WAITG(0); }
        __syncthreads();

        const __nv_bfloat16* As = Asm + (kt%NSTAGE)*ASZ;
        const __nv_bfloat16* Bs = Bsm + (kt%NSTAGE)*BSZ;
        #pragma unroll
        for (int ks = 0; ks < WBK; ks += 16) {
            wmma::fragment<wmma::matrix_a, 16,16,16, __nv_bfloat16, wmma::row_major> af[4];
            wmma::fragment<wmma::matrix_b, 16,16,16, __nv_bfloat16, wmma::col_major> bf[NFRAG];
            #pragma unroll
            for (int i = 0; i < 4; i++)
                wmma::load_matrix_sync(af[i], &As[(wm*64 + i*16)*WPITCH + ks], WPITCH);
            #pragma unroll
            for (int j = 0; j < NFRAG; j++)
                wmma::load_matrix_sync(bf[j], &Bs[(wn*16*NFRAG + j*16)*WPITCH + ks], WPITCH);
            #pragma unroll
            for (int i = 0; i < 4; i++)
                #pragma unroll
                for (int j = 0; j < NFRAG; j++)
                    wmma::mma_sync(acc[i][j], af[i], bf[j], acc[i][j]);
        }
    }

    if (mode == 3) {
        // smem-bounce epilogue: bias[m] + softplus, coalesced store (NFRAG==2 only)
        float* sf = reinterpret_cast<float*>(sm);
        __syncthreads();
        #pragma unroll
        for (int i = 0; i < 4; i++)
            #pragma unroll
            for (int j = 0; j < NFRAG; j++)
                wmma::store_matrix_sync(sf + (size_t)(wm*64 + i*16)*132 + wn*16*NFRAG + j*16,
                                        acc[i][j], 132, wmma::mem_row_major);
        __syncthreads();
        for (int e = tid; e < WBM*(WBN/4); e += 256) {
            int r  = e / (WBN/4);
            int c4 = e % (WBN/4);
            int m  = m0 + r;
            float bm = bias[m];
            float vv[4];
            #pragma unroll
            for (int q = 0; q < 4; q++) {
                float v = sf[(size_t)r*132 + c4*4 + q] + bm;
                vv[q] = (v > 20.f) ? v : __logf(1.f + __expf(v));
            }
            float4 v4 = {vv[0], vv[1], vv[2], vv[3]};
            *reinterpret_cast<float4*>(C + (size_t)m*ldc + n0 + c4*4) = v4;
        }
        return;
    }

    #pragma unroll
    for (int i = 0; i < 4; i++) {
        int m = m0 + wm*64 + i*16;
        #pragma unroll
        for (int j = 0; j < NFRAG; j++) {
            int n = n0 + wn*16*NFRAG + j*16;
            if (mode == 1) {
                wmma::fragment<wmma::accumulator, 16,16,16, float> rf;
                wmma::load_matrix_sync(rf, R + (size_t)m*ldr + n, ldr, wmma::mem_row_major);
                #pragma unroll
                for (int t = 0; t < acc[i][j].num_elements; t++)
                    acc[i][j].x[t] += rf.x[t];
            }
            wmma::store_matrix_sync(C + (size_t)m*ldc + n, acc[i][j], ldc, wmma::mem_row_major);
        }
    }
}

#define WMMA_SMEM_W (NSTAGE*(ASZ + 256*WPITCH)*2)   // NFRAG=4: 122880 B
#define WMMA_SMEM_N (NSTAGE*(ASZ + 128*WPITCH)*2)   // NFRAG=2: 81920 B

// ---------------- x_proj wmma split-K: part[kc] = u2 @ wx2^T (N padded 128) --
__global__ __launch_bounds__(256) void wmma_xk(
    const __nv_bfloat16* __restrict__ A2,   // u2 [ROWS][DINNER]
    const __nv_bfloat16* __restrict__ B2,   // wx2 [128][DINNER]
    float* __restrict__ part)
{
    constexpr int WBN = 128;
    constexpr int BSZ = WBN*WPITCH;

    extern __shared__ __align__(16) __nv_bfloat16 sm[];
    __nv_bfloat16* Asm = sm;
    __nv_bfloat16* Bsm = sm + NSTAGE*ASZ;

    int tid  = threadIdx.x;
    int w    = tid >> 5;
    int wm   = w >> 2;
    int wn   = w & 3;
    int m0   = blockIdx.x * WBM;
    int kc   = blockIdx.y;
    int kbeg = kc * (DINNER/XP_KSPLIT);

    wmma::fragment<wmma::accumulator, 16,16,16, float> acc[4][2];
    #pragma unroll
    for (int i = 0; i < 4; i++)
        #pragma unroll
        for (int j = 0; j < 2; j++) wmma::fill_fragment(acc[i][j], 0.f);

    auto stage = [&](int s, int k0) {
        __nv_bfloat16* As = Asm + s*ASZ;
        __nv_bfloat16* Bs = Bsm + s*BSZ;
        #pragma unroll
        for (int e = tid; e < WBM*4; e += 256) {
            int row = e >> 2, q = e & 3;
            cp_async16(&As[row*WPITCH + q*8], A2 + (size_t)(m0+row)*DINNER + k0 + q*8);
        }
        #pragma unroll
        for (int e = tid; e < WBN*4; e += 256) {
            int row = e >> 2, q = e & 3;
            cp_async16(&Bs[row*WPITCH + q*8], B2 + (size_t)row*DINNER + k0 + q*8);
        }
        CP_COMMIT();
    };

    const int NT = (DINNER/XP_KSPLIT)/WBK;   // 16
    stage(0, kbeg); stage(1, kbeg+WBK); stage(2, kbeg+2*WBK);

    for (int kt = 0; kt < NT; kt++) {
        __syncthreads();
        if (kt + 3 < NT)      { stage((kt+3)%NSTAGE, kbeg+(kt+3)*WBK); CP_WAITG(3); }
        else if (kt + 3 == NT) { CP_WAITG(2); }
        else if (kt + 2 == NT) { CP_WAITG(1); }
        else                   { CP_WAITG(0); }
        __syncthreads();

        const __nv_bfloat16* As = Asm + (kt%NSTAGE)*ASZ;
        const __nv_bfloat16* Bs = Bsm + (kt%NSTAGE)*BSZ;
        #pragma unroll
        for (int ks = 0; ks < WBK; ks += 16) {
            wmma::fragment<wmma::matrix_a, 16,16,16, __nv_bfloat16, wmma::row_major> af[4];
            wmma::fragment<wmma::matrix_b, 16,16,16, __nv_bfloat16, wmma::col_major> bf[2];
            #pragma unroll
            for (int i = 0; i < 4; i++)
                wmma::load_matrix_sync(af[i], &As[(wm*64 + i*16)*WPITCH + ks], WPITCH);
            #pragma unroll
            for (int j = 0; j < 2; j++)
                wmma::load_matrix_sync(bf[j], &Bs[(wn*32 + j*16)*WPITCH + ks], WPITCH);
            #pragma unroll
            for (int i = 0; i < 4; i++)
                #pragma unroll
                for (int j = 0; j < 2; j++)
                    wmma::mma_sync(acc[i][j], af[i], bf[j], acc[i][j]);
        }
    }

    float* base = part + (size_t)kc*ROWS*XPROJ_OUT;
    #pragma unroll
    for (int i = 0; i < 4; i++) {
        int m = m0 + wm*64 + i*16;
        #pragma unroll
        for (int j = 0; j < 2; j++) {
            int n = wn*32 + j*16;
            if (n < XPROJ_OUT)
                wmma::store_matrix_sync(base + (size_t)m*XPROJ_OUT + n, acc[i][j],
                                        XPROJ_OUT, wmma::mem_row_major);
        }
    }
}

// reduce 4 partials -> xdbl (fp32) + xdbl64 (bf16, first 64 cols) ------------
__global__ void xpart_reduce(const float* __restrict__ part, float* __restrict__ xdbl,
                             __nv_bfloat16* __restrict__ xdbl64)
{
    int i = blockIdx.x*blockDim.x + threadIdx.x;
    if (i >= ROWS*XPROJ_OUT) return;
    const int S = ROWS*XPROJ_OUT;
    float v = (part[i] + part[i+S]) + (part[i+2*S] + part[i+3*S]);
    xdbl[i] = v;
    int r = i / XPROJ_OUT, c = i % XPROJ_OUT;
    if (c < DTRANK) xdbl64[(size_t)r*DTRANK + c] = __float2bfloat16(v);
}

// ---------------- LayerNorm -> bf16 directly ---------------------------------
__global__ void ln_kernel(const float* __restrict__ x, const float* __restrict__ g,
                          const float* __restrict__ b, __nv_bfloat16* __restrict__ xn2)
{
    int row = blockIdx.x;
    int tid = threadIdx.x;
    const float* xr = x + (size_t)row*DMODEL;
    float v[4];
    float s1 = 0.f, s2 = 0.f;
    #pragma unroll
    for (int i = 0; i < 4; i++) {
        v[i] = xr[tid + 256*i];
        s1 += v[i];
        s2 += v[i]*v[i];
    }
    __shared__ float sh1[8], sh2[8];
    #pragma unroll
    for (int o = 16; o; o >>= 1) {
        s1 += __shfl_xor_sync(0xffffffffu, s1, o);
        s2 += __shfl_xor_sync(0xffffffffu, s2, o);
    }
    if ((tid & 31) == 0) { sh1[tid>>5] = s1; sh2[tid>>5] = s2; }
    __syncthreads();
    if (tid < 32) {
        float a = (tid < 8) ? sh1[tid] : 0.f;
        float c = (tid < 8) ? sh2[tid] : 0.f;
        #pragma unroll
        for (int o = 4; o; o >>= 1) {
            a += __shfl_xor_sync(0xffffffffu, a, o);
            c += __shfl_xor_sync(0xffffffffu, c, o);
        }
        if (tid == 0) { sh1[0] = a; sh2[0] = c; }
    }
    __syncthreads();
    float mu  = sh1[0] * (1.f/DMODEL);
    float var = sh2[0] * (1.f/DMODEL) - mu*mu;
    float r   = rsqrtf(var + 1e-5f);
    __nv_bfloat16* o = xn2 + (size_t)row*DMODEL;
    #pragma unroll
    for (int i = 0; i < 4; i++) {
        int c = tid + 256*i;
        o[c] = __float2bfloat16((v[i]-mu)*r*g[c] + b[c]);
    }
}

// ---------------- causal conv1d + SiLU: u (bf16) + u^T (fp32) ---------------
__global__ __launch_bounds__(256) void conv_silu_kernel(
    const float* __restrict__ xz, const float* __restrict__ w,
    const float* __restrict__ bias, __nv_bfloat16* __restrict__ u2,
    float* __restrict__ uT)
{
    __shared__ float s[32][33];
    int tid  = threadIdx.x;
    int ld   = tid & 31;
    int lr   = tid >> 5;
    int d0   = blockIdx.x * 32;
    int row0 = blockIdx.y * 32;
    int d    = d0 + ld;

    float w0 = w[d*DCONV+0], w1 = w[d*DCONV+1], w2 = w[d*DCONV+2], w3 = w[d*DCONV+3];
    float bs = bias[d];

    #pragma unroll
    for (int i = 0; i < 4; i++) {
        int row = row0 + lr + 8*i;
        int l   = row % SEQ;
        const float* base = xz + (size_t)row*(2*DINNER) + d;
        float acc = bs + base[0] * w3;
        if (l >= 1) acc += base[-(ptrdiff_t)(2*DINNER)]   * w2;
        if (l >= 2) acc += base[-(ptrdiff_t)(4*DINNER)]   * w1;
        if (l >= 3) acc += base[-(ptrdiff_t)(6*DINNER)]   * w0;
        float sig = 1.f / (1.f + __expf(-acc));
        float val = acc * sig;
        u2[(size_t)row*DINNER + d] = __float2bfloat16(val);
        s[ld][lr + 8*i] = val;
    }
    __syncthreads();
    #pragma unroll
    for (int i = 0; i < 4; i++) {
        int wd = lr + 8*i;
        uT[(size_t)(d0 + wd)*ROWS + row0 + ld] = s[wd][ld];
    }
}

// ---------------- selective scan v2: smem-staged, double-buffered -----------
#define SCT 32

__global__ __launch_bounds__(256) void scan_kernel(
    const float* __restrict__ deltaT, const float* __restrict__ uT,
    const float* __restrict__ xdbl, const float* __restrict__ xz,
    const float* __restrict__ A_log, const float* __restrict__ Dskip,
    __nv_bfloat16* __restrict__ yg2)
{
    __shared__ __align__(16) float sBC[2][SCT][32];
    __shared__ __align__(16) float sdt[2][16][SCT];
    __shared__ __align__(16) float sut[2][16][SCT];
    __shared__ __align__(16) float szT[2][SCT][16];
    __shared__ float sy[16][SCT+1];

    int tid  = threadIdx.x;
    int warp = tid >> 5;
    int lane = tid & 31;
    int half = lane >> 4;
    int n    = lane & 15;
    int ch   = warp*2 + half;
    int c0   = blockIdx.x * 16;
    int b    = c0 / DINNER;
    int dbas = c0 % DINNER;
    int d    = dbas + ch;

    float A  = -__expf(A_log[d*DSTATE + n]);
    float Dd = Dskip[d];
    float h  = 0.f;

    const float* xsrc = xdbl + (size_t)b*SEQ*XPROJ_OUT;
    const float* zsrc = xz   + (size_t)b*SEQ*(2*DINNER) + DINNER + dbas;

    auto stage = [&](int buf, int t0) {
        for (int e = tid; e < SCT*8; e += 256) {
            int t = e >> 3, q = e & 7;
            cp_async16(&sBC[buf][t][q*4], xsrc + (size_t)(t0+t)*XPROJ_OUT + DTRANK + q*4);
        }
        for (int e = tid; e < 16*8; e += 256) {
            int cc = e >> 3, q = e & 7;
            cp_async16(&sdt[buf][cc][q*4],
                       deltaT + (size_t)(dbas+cc)*ROWS + b*SEQ + t0 + q*4);
            cp_async16(&sut[buf][cc][q*4],
                       uT + (size_t)(dbas+cc)*ROWS + b*SEQ + t0 + q*4);
        }
        for (int e = tid; e < SCT*4; e += 256) {
            int t = e >> 2, q = e & 3;
            cp_async16(&szT[buf][t][q*4], zsrc + (size_t)(t0+t)*(2*DINNER) + q*4);
        }
        CP_COMMIT();
    };

    const int NCH = SEQ / SCT;
    stage(0, 0);

    for (int j = 0; j < NCH; j++) {
        int buf = j & 1;
        if (j + 1 < NCH) { stage(buf ^ 1, (j+1)*SCT); CP_WAITG(1); }
        else             { CP_WAITG(0); }
        __syncthreads();

        #pragma unroll 4
        for (int i = 0; i < SCT; i++) {
            float dt = sdt[buf][ch][i];
            float ut = sut[buf][ch][i];
            float Bn = sBC[buf][i][n];
            float Cn = sBC[buf][i][16+n];
            float dA = __expf(dt * A);
            h = fmaf(dA, h, dt*ut*Bn);
            float p = h * Cn;
            p += __shfl_xor_sync(0xffffffffu, p, 8);
            p += __shfl_xor_sync(0xffffffffu, p, 4);
            p += __shfl_xor_sync(0xffffffffu, p, 2);
            p += __shfl_xor_sync(0xffffffffu, p, 1);
            if (n == 0) sy[ch][i] = fmaf(ut, Dd, p);
        }
        __syncthreads();

        int t0 = j*SCT;
        #pragma unroll
        for (int e = tid; e < 16*SCT; e += 256) {
            int t = e >> 4, cc = e & 15;
            float val = sy[cc][t];
            float z   = szT[buf][t][cc];
            float sg  = z / (1.f + __expf(-z));
            yg2[(size_t)(b*SEQ + t0 + t)*DINNER + dbas + cc] = __float2bfloat16(val * sg);
        }
        __syncthreads();
    }
}

// ---------------- launch ----------------------------------------------------
extern "C" void kernel_launch(void* const* d_in, const int* in_sizes, int n_in,
                              void* d_out, int out_size)
{
    const float* x      = (const float*)d_in[0];
    const float* ln_g   = (const float*)d_in[1];
    const float* ln_b   = (const float*)d_in[2];
    const float* w_in   = (const float*)d_in[3];
    const float* conv_w = (const float*)d_in[4];
    const float* conv_b = (const float*)d_in[5];
    const float* w_x    = (const float*)d_in[6];
    const float* w_dt   = (const float*)d_in[7];
    const float* b_dt   = (const float*)d_in[8];
    const float* A_log  = (const float*)d_in[9];
    const float* Dsk    = (const float*)d_in[10];
    const float* w_out  = (const float*)d_in[11];
    float* out = (float*)d_out;

    float *xz, *uT, *xdbl, *xpart, *deltaT;
    __nv_bfloat16 *xn2, *win2, *u2, *wx2, *wdt2, *xdbl64, *yg2, *wout2;
    cudaGetSymbolAddress((void**)&xz,     g_xz);
    cudaGetSymbolAddress((void**)&uT,     g_uT);
    cudaGetSymbolAddress((void**)&xdbl,   g_xdbl);
    cudaGetSymbolAddress((void**)&xpart,  g_xpart);
    cudaGetSymbolAddress((void**)&deltaT, g_deltaT);
    cudaGetSymbolAddress((void**)&xn2,    g_xn2);
    cudaGetSymbolAddress((void**)&win2,   g_win2);
    cudaGetSymbolAddress((void**)&u2,     g_u2);
    cudaGetSymbolAddress((void**)&wx2,    g_wx2);
    cudaGetSymbolAddress((void**)&wdt2,   g_wdt2);
    cudaGetSymbolAddress((void**)&xdbl64, g_xdbl64);
    cudaGetSymbolAddress((void**)&yg2,    g_yg2);
    cudaGetSymbolAddress((void**)&wout2,  g_wout2);

    static int smem_set = 0;
    if (!smem_set) {
        cudaFuncSetAttribute(wmma_nt<4>, cudaFuncAttributeMaxDynamicSharedMemorySize, WMMA_SMEM_W);
        cudaFuncSetAttribute(wmma_nt<2>, cudaFuncAttributeMaxDynamicSharedMemorySize, WMMA_SMEM_N);
        cudaFuncSetAttribute(wmma_xk,    cudaFuncAttributeMaxDynamicSharedMemorySize, WMMA_SMEM_N);
        smem_set = 1;
    }

    // 1. layernorm -> xn2 (bf16)
    ln_kernel<<<ROWS, 256>>>(x, ln_g, ln_b, xn2);

    // 2. in_proj (bf16 tensor cores): K = 1024
    cast_kernel<<<(2*DINNER*DMODEL+255)/256, 256>>>(w_in, win2, 2*DINNER*DMODEL);
    {
        dim3 g(2*DINNER/256, ROWS/WBM);
        wmma_nt<4><<<g, 256, WMMA_SMEM_W>>>(xn2, win2, xz, 2*DINNER, nullptr, 0,
                                            nullptr, ROWS, 2*DINNER, DMODEL, 0);
    }

    // 3. causal depthwise conv + SiLU -> u2 (bf16), u^T (fp32)
    {
        dim3 g(DINNER/32, ROWS/32);
        conv_silu_kernel<<<g, 256>>>(xz, conv_w, conv_b, u2, uT);
    }

    // 4. x_proj on tensor cores (split-K, N padded to 128)
    cast_kernel<<<(XPROJ_OUT*DINNER+255)/256, 256>>>(w_x, wx2, XPROJ_OUT*DINNER);
    {
        dim3 g(ROWS/WBM, XP_KSPLIT);
        wmma_xk<<<g, 256, WMMA_SMEM_N>>>(u2, wx2, xpart);
        xpart_reduce<<<(ROWS*XPROJ_OUT+255)/256, 256>>>(xpart, xdbl, xdbl64);
    }

    // 5. dt_proj on tensor cores + fused softplus:
    //    deltaT[DINNER][ROWS] = softplus(w_dt @ xdbl64^T + b_dt), K=64
    cast_kernel<<<(DINNER*DTRANK+255)/256, 256>>>(w_dt, wdt2, DINNER*DTRANK);
    {
        dim3 g(ROWS/128, DINNER/WBM);
        wmma_nt<2><<<g, 256, WMMA_SMEM_N>>>(wdt2, xdbl64, deltaT, ROWS, nullptr, 0,
                                            b_dt, DINNER, ROWS, DTRANK, 3);
    }

    // 6. selective scan v2 (smem-staged) -> yg2 (bf16, gate fused)
    scan_kernel<<<(BATCH*DINNER)/16, 256>>>(deltaT, uT, xdbl, xz, A_log, Dsk, yg2);

    // 7. out_proj (bf16 tensor cores) + residual: K = 2048
    cast_kernel<<<(DMODEL*DINNER+255)/256, 256>>>(w_out, wout2, DMODEL*DINNER);
    {
        dim3 g(DMODEL/128, ROWS/WBM);
        wmma_nt<2><<<g, 256, WMMA_SMEM_N>>>(yg2, wout2, out, DMODEL, x, DMODEL,
                                            nullptr, ROWS, DMODEL, DINNER, 1);
    }
}